// round 5
// baseline (speedup 1.0000x reference)
#include <cuda_runtime.h>
#include <cuda_bf16.h>
#include <cstdint>
#include <cstddef>

// ---------------- problem constants ----------------
static constexpr int B  = 4;
static constexpr int C  = 512;
static constexpr int T  = 2048;
static constexpr int H  = 8;
static constexpr int FC = 2048;
static constexpr int L  = 6;
static constexpr int S  = 256;
static constexpr int DK = 64;

// ---------------- device scratch ----------------
__device__ float g_x  [B * C  * T];
__device__ float g_y  [B * C  * T];
__device__ float g_q  [B * C  * T];
__device__ float g_k  [B * C  * T];
__device__ float g_v  [B * C  * T];
__device__ float g_att[B * C  * T];
__device__ float g_h  [B * FC * T];

// packed split weights (hi/lo bf16x2 words), pretiled [omBlk][chunk][k2(16)][m(128)]
static constexpr size_t OFF_COND = 0;                    // 512x256   ->   65536
static constexpr size_t OFF_PRE  = 65536;                // 512x1536  ->  393216
static constexpr size_t OFF_QKV  = 458752;               // L x 3 x 131072
static constexpr size_t QKV_LSTR = 393216;
static constexpr size_t OFF_OUT  = 2818048;              // L x 131072
static constexpr size_t OUT_LSTR = 131072;
static constexpr size_t OFF_F1   = 3604480;              // L x 1572864
static constexpr size_t F1_LSTR  = 1572864;
static constexpr size_t OFF_F2   = 13041664;             // L x 1572864
static constexpr size_t F2_LSTR  = 1572864;
static constexpr size_t W_TOTAL  = 22478848;

__device__ uint32_t g_wh[W_TOTAL];
__device__ uint32_t g_wl[W_TOTAL];
// packed split activations [b][c2][t] (sized for FC: 4*1024*2048)
__device__ uint32_t g_ah[(size_t)B * (FC / 2) * T];
__device__ uint32_t g_al[(size_t)B * (FC / 2) * T];

// ---------------- helpers ----------------
__device__ __forceinline__ uint32_t pack_bf2(float a, float b) {
    uint32_t r;
    asm("cvt.rn.bf16x2.f32 %0, %1, %2;" : "=r"(r) : "f"(b), "f"(a));
    return r;
}
__device__ __forceinline__ float bf_hi_val(float v) {
    __nv_bfloat16 h = __float2bfloat16_rn(v);
    return __bfloat162float(h);
}
__device__ __forceinline__ void mma_bf16(float* d, const uint32_t* a, const uint32_t* b) {
    asm volatile("mma.sync.aligned.m16n8k16.row.col.f32.bf16.bf16.f32 "
        "{%0,%1,%2,%3}, {%4,%5,%6,%7}, {%8,%9}, {%0,%1,%2,%3};"
        : "+f"(d[0]), "+f"(d[1]), "+f"(d[2]), "+f"(d[3])
        : "r"(a[0]), "r"(a[1]), "r"(a[2]), "r"(a[3]), "r"(b[0]), "r"(b[1]));
}

// ---------------- weight packing ----------------
// src W [layers][Cout][Cin*KW] (orig k = c*KW + kk) -> pretiled packed hi/lo.
// k2 ordering: KW==1: pair (2k2, 2k2+1). KW==3 (kk-major): kk = k2/(Cin/2),
// c2 = k2%(Cin/2), pair = channels (2c2, 2c2+1) at shift kk.
__global__ void pack_w(const float* __restrict__ src, size_t src_lstride,
                       size_t dst_base, size_t dst_lstride,
                       int Cin, int KW, int chunks)
{
    const int l = blockIdx.y;
    const int w = blockIdx.x * 256 + threadIdx.x;     // word index within matrix
    const int per_blk = chunks * 2048;
    const int omBlk = w / per_blk;
    const int r  = w % per_blk;
    const int ch = r / 2048, r2 = r % 2048;
    const int k2 = ch * 16 + (r2 >> 7);
    const int m  = r2 & 127;
    int ka, kb;
    if (KW == 1) { ka = 2 * k2; kb = ka + 1; }
    else { int half = Cin >> 1; int c2 = k2 % half, kk = k2 / half;
           ka = (2 * c2) * KW + kk; kb = ka + KW; }
    const float* s = src + (size_t)l * src_lstride + (size_t)(omBlk * 128 + m) * Cin * KW;
    float va = s[ka], vb = s[kb];
    float ha = bf_hi_val(va), hb = bf_hi_val(vb);
    size_t d = dst_base + (size_t)l * dst_lstride + w;
    g_wh[d] = pack_bf2(ha, hb);
    g_wl[d] = pack_bf2(va - ha, vb - hb);
}

// ---------------- activation split/pack ----------------
// X [b][2*Chalf][T] -> packed [b][Chalf][T]
__global__ void split_act(const float* __restrict__ X, uint32_t* __restrict__ Xh,
                          uint32_t* __restrict__ Xl, int Chalf)
{
    const int t  = blockIdx.x * 256 + threadIdx.x;
    const int c2 = blockIdx.y;
    const int b  = blockIdx.z;
    const float* x0 = X + ((size_t)b * 2 * Chalf + 2 * c2) * T;
    float va = x0[t], vb = x0[T + t];
    float ha = bf_hi_val(va), hb = bf_hi_val(vb);
    size_t d = ((size_t)b * Chalf + c2) * T + t;
    Xh[d] = pack_bf2(ha, hb);
    Xl[d] = pack_bf2(va - ha, vb - hb);
}

// ================= packed bf16x2-split mma.sync conv-GEMM =================
static constexpr int KSTR = 136;

template <int KW, int PL, bool RELU, bool DOMASK, bool ADDSRC, int NOUT>
__global__ __launch_bounds__(256, 2) void mma_gemm_p(
    const uint32_t* __restrict__ Xh, const uint32_t* __restrict__ Xl,
    const uint32_t* __restrict__ Wh, const uint32_t* __restrict__ Wl,
    const float* __restrict__ b0, const float* __restrict__ b1, const float* __restrict__ b2,
    const float* __restrict__ mask, const float* __restrict__ src,
    float* __restrict__ Y0, float* __restrict__ Y1, float* __restrict__ Y2,
    int Cin, int Cout)
{
    __shared__ uint32_t Ah[16 * KSTR], Al[16 * KSTR];
    __shared__ uint32_t Bh[16 * KSTR], Bl[16 * KSTR];

    const int tid  = threadIdx.x;
    const int lane = tid & 31;
    const int wid  = tid >> 5;
    const int mw   = wid & 1;
    const int nw   = wid >> 1;
    const int gid  = lane >> 2;
    const int tig  = lane & 3;

    const int b   = blockIdx.z;
    const int tn0 = blockIdx.x * 128;
    int sel, om;
    if (NOUT == 3) { sel = blockIdx.y >> 2; om = (blockIdx.y & 3) * 128; }
    else           { sel = 0;               om = blockIdx.y * 128; }
    const float* bias = (NOUT == 3) ? (sel == 0 ? b0 : sel == 1 ? b1 : b2) : b0;
    float* Y          = (NOUT == 3) ? (sel == 0 ? Y0 : sel == 1 ? Y1 : Y2) : Y0;

    const int Chalf  = Cin >> 1;
    const int chunks = (Cin * KW) >> 5;
    const uint32_t* wtH = Wh + (size_t)blockIdx.y * chunks * 2048;
    const uint32_t* wtL = Wl + (size_t)blockIdx.y * chunks * 2048;
    const uint32_t* XhB = Xh + (size_t)b * Chalf * T;
    const uint32_t* XlB = Xl + (size_t)b * Chalf * T;

    const int lk2 = tid >> 4;   // k2 row handled by this thread (loaders)
    const int lq  = tid & 15;   // 8-word group

    float acc[4][4][4];
#pragma unroll
    for (int i = 0; i < 4; i++)
#pragma unroll
        for (int j = 0; j < 4; j++)
#pragma unroll
            for (int r = 0; r < 4; r++) acc[i][j][r] = 0.f;

    for (int ch = 0; ch < chunks; ch++) {
        // ---- A: pretiled packed weights, pure copy ----
        {
            const uint32_t* aH = wtH + ch * 2048 + lk2 * 128 + lq * 8;
            const uint32_t* aL = wtL + ch * 2048 + lk2 * 128 + lq * 8;
            uint4 h0 = *(const uint4*)aH;
            uint4 h1 = *(const uint4*)(aH + 4);
            uint4 l0 = *(const uint4*)aL;
            uint4 l1 = *(const uint4*)(aL + 4);
            *(uint4*)&Ah[lk2 * KSTR + lq * 8]     = h0;
            *(uint4*)&Ah[lk2 * KSTR + lq * 8 + 4] = h1;
            *(uint4*)&Al[lk2 * KSTR + lq * 8]     = l0;
            *(uint4*)&Al[lk2 * KSTR + lq * 8 + 4] = l1;
        }
        // ---- B: packed activations ----
        {
            const int k2g = ch * 16 + lk2;
            if (KW == 1) {
                const uint32_t* rH = XhB + (size_t)k2g * T + tn0 + lq * 8;
                const uint32_t* rL = XlB + (size_t)k2g * T + tn0 + lq * 8;
                uint4 h0 = *(const uint4*)rH;
                uint4 h1 = *(const uint4*)(rH + 4);
                uint4 l0 = *(const uint4*)rL;
                uint4 l1 = *(const uint4*)(rL + 4);
                *(uint4*)&Bh[lk2 * KSTR + lq * 8]     = h0;
                *(uint4*)&Bh[lk2 * KSTR + lq * 8 + 4] = h1;
                *(uint4*)&Bl[lk2 * KSTR + lq * 8]     = l0;
                *(uint4*)&Bl[lk2 * KSTR + lq * 8 + 4] = l1;
            } else {
                const int c2 = k2g % Chalf;
                const int kk = k2g / Chalf;
                const int dt = kk - PL;
                const uint32_t* rH = XhB + (size_t)c2 * T;
                const uint32_t* rL = XlB + (size_t)c2 * T;
                const int tb = tn0 + lq * 8 + dt;
#pragma unroll
                for (int j = 0; j < 8; j++) {
                    int t = tb + j;
                    bool ok = (unsigned)t < (unsigned)T;
                    Bh[lk2 * KSTR + lq * 8 + j] = ok ? rH[t] : 0u;
                    Bl[lk2 * KSTR + lq * 8 + j] = ok ? rL[t] : 0u;
                }
            }
        }
        __syncthreads();

        // ---- 2 k-steps of 16 ----
#pragma unroll
        for (int ks = 0; ks < 2; ks++) {
            const int k2a = ks * 8 + tig;
            const int k2b = ks * 8 + 4 + tig;
            uint32_t bfh[4][2], bfl[4][2];
#pragma unroll
            for (int nt = 0; nt < 4; nt++) {
                int n = nw * 32 + nt * 8 + gid;
                bfh[nt][0] = Bh[k2a * KSTR + n];
                bfh[nt][1] = Bh[k2b * KSTR + n];
                bfl[nt][0] = Bl[k2a * KSTR + n];
                bfl[nt][1] = Bl[k2b * KSTR + n];
            }
#pragma unroll
            for (int mt = 0; mt < 4; mt++) {
                int m = mw * 64 + mt * 16 + gid;
                uint32_t afh[4], afl[4];
                afh[0] = Ah[k2a * KSTR + m];
                afh[1] = Ah[k2a * KSTR + m + 8];
                afh[2] = Ah[k2b * KSTR + m];
                afh[3] = Ah[k2b * KSTR + m + 8];
                afl[0] = Al[k2a * KSTR + m];
                afl[1] = Al[k2a * KSTR + m + 8];
                afl[2] = Al[k2b * KSTR + m];
                afl[3] = Al[k2b * KSTR + m + 8];
#pragma unroll
                for (int nt = 0; nt < 4; nt++) {
                    mma_bf16(acc[mt][nt], afh, bfh[nt]);
                    mma_bf16(acc[mt][nt], afh, bfl[nt]);
                    mma_bf16(acc[mt][nt], afl, bfh[nt]);
                }
            }
        }
        __syncthreads();
    }

    // ---- epilogue ----
#pragma unroll
    for (int mt = 0; mt < 4; mt++) {
        int o0 = om + mw * 64 + mt * 16 + gid;
        float bb0 = bias[o0];
        float bb1 = bias[o0 + 8];
#pragma unroll
        for (int nt = 0; nt < 4; nt++) {
            int t0 = tn0 + nw * 32 + nt * 8 + 2 * tig;
            float m0 = 1.f, m1 = 1.f;
            if (DOMASK) {
                m0 = mask[(size_t)b * T + t0];
                m1 = mask[(size_t)b * T + t0 + 1];
            }
            float v0 = acc[mt][nt][0] + bb0;
            float v1 = acc[mt][nt][1] + bb0;
            float v2 = acc[mt][nt][2] + bb1;
            float v3 = acc[mt][nt][3] + bb1;
            if (RELU) {
                v0 = fmaxf(v0, 0.f); v1 = fmaxf(v1, 0.f);
                v2 = fmaxf(v2, 0.f); v3 = fmaxf(v3, 0.f);
            }
            size_t oi0 = ((size_t)b * Cout + o0)     * T + t0;
            size_t oi1 = ((size_t)b * Cout + o0 + 8) * T + t0;
            if (ADDSRC) {
                float2 s0 = *(const float2*)(src + oi0);
                float2 s1 = *(const float2*)(src + oi1);
                v0 += s0.x; v1 += s0.y; v2 += s1.x; v3 += s1.y;
            }
            if (DOMASK) { v0 *= m0; v1 *= m1; v2 *= m0; v3 *= m1; }
            *(float2*)(Y + oi0) = make_float2(v0, v1);
            *(float2*)(Y + oi1) = make_float2(v2, v3);
        }
    }
}

// ---------------- f0 prenet added in-place ----------------
__global__ void add_f0(const float* __restrict__ f0, const float* __restrict__ w,
                       const float* __restrict__ fb, float* __restrict__ y)
{
    int t = blockIdx.x * 256 + threadIdx.x;
    int c = blockIdx.y;
    int b = blockIdx.z;
    float fm1 = (t - 1 >= 0) ? f0[(size_t)b * T + t - 1] : 0.f;
    float fc0 = f0[(size_t)b * T + t];
    float fp1 = (t + 1 < T) ? f0[(size_t)b * T + t + 1] : 0.f;
    float v = w[c * 3 + 0] * fm1 + w[c * 3 + 1] * fc0 + w[c * 3 + 2] * fp1 + fb[c];
    y[((size_t)b * C + c) * T + t] += v;
}

// ---------------- fused residual-add + LayerNorm + packed split output ----------------
__global__ void add_ln_p(const float* __restrict__ x, const float* __restrict__ y,
                         const float* __restrict__ g, const float* __restrict__ be,
                         float* __restrict__ out,
                         uint32_t* __restrict__ ph, uint32_t* __restrict__ pl)
{
    __shared__ float red0[8][32];
    __shared__ float red1[8][32];
    __shared__ float smv[2][32];
    const int tx = threadIdx.x, ty = threadIdx.y;
    const int t = blockIdx.x * 32 + tx;
    const int b = blockIdx.y;
    const size_t base = (size_t)b * C * T + t;

    float s = 0.f, sq = 0.f;
    for (int c2 = ty; c2 < C / 2; c2 += 8) {
        size_t i0 = base + (size_t)(2 * c2) * T;
        float v0 = x[i0] + y[i0];
        float v1 = x[i0 + T] + y[i0 + T];
        s += v0 + v1; sq += v0 * v0 + v1 * v1;
    }
    red0[ty][tx] = s; red1[ty][tx] = sq;
    __syncthreads();
    if (ty == 0) {
#pragma unroll
        for (int i = 1; i < 8; i++) { s += red0[i][tx]; sq += red1[i][tx]; }
        float mean = s * (1.f / C);
        float var  = sq * (1.f / C) - mean * mean;
        smv[0][tx] = mean;
        smv[1][tx] = rsqrtf(var + 1e-5f);
    }
    __syncthreads();
    float mean = smv[0][tx], rstd = smv[1][tx];
    for (int c2 = ty; c2 < C / 2; c2 += 8) {
        size_t i0 = base + (size_t)(2 * c2) * T;
        float v0 = (x[i0]     + y[i0]     - mean) * rstd * g[2 * c2]     + be[2 * c2];
        float v1 = (x[i0 + T] + y[i0 + T] - mean) * rstd * g[2 * c2 + 1] + be[2 * c2 + 1];
        out[i0]     = v0;
        out[i0 + T] = v1;
        float h0 = bf_hi_val(v0), h1 = bf_hi_val(v1);
        size_t d = ((size_t)b * (C / 2) + c2) * T + t;
        ph[d] = pack_bf2(h0, h1);
        pl[d] = pack_bf2(v0 - h0, v1 - h1);
    }
}

// ---------------- fused causal flash attention (fp32) ----------------
static constexpr int FLASH_SMEM = (64 * 64 + 64 * 68 + 64 * 68) * 4;

__global__ __launch_bounds__(256) void flash_attn(
    const float* __restrict__ q, const float* __restrict__ k,
    const float* __restrict__ v, float* __restrict__ o)
{
    extern __shared__ float sm[];
    float* Qs = sm;
    float* Ks = sm + 64 * 64;
    float* Vt = Ks + 64 * 68;
    float* Ss = Ks;

    const int tid  = threadIdx.x;
    const int lane = tid & 31;
    const int warp = tid >> 5;
    const int mb   = blockIdx.x;
    const int m0   = mb * 64;
    const int bh   = blockIdx.y;
    const int b    = bh >> 3;
    const int h    = bh & 7;
    const size_t base = ((size_t)b * C + (size_t)h * DK) * T;
    const float* __restrict__ qp = q + base;
    const float* __restrict__ kp = k + base;
    const float* __restrict__ vp = v + base;

    for (int idx = tid; idx < 64 * 64; idx += 256) {
        int d = idx >> 6, tt = idx & 63;
        Qs[tt * 64 + d] = qp[(size_t)d * T + m0 + tt] * 0.125f;
    }

    float mI[8], lI[8], a0[8], a1[8];
#pragma unroll
    for (int r = 0; r < 8; r++) { mI[r] = -1e30f; lI[r] = 0.f; a0[r] = 0.f; a1[r] = 0.f; }
    const int r0 = warp * 8;

    for (int kbk = 0; kbk <= mb; kbk++) {
        const int kn0 = kbk * 64;
        __syncthreads();
        for (int idx = tid; idx < 64 * 64; idx += 256) {
            int d = idx >> 6, j = idx & 63;
            Ks[j * 68 + d] = kp[(size_t)d * T + kn0 + j];
            Vt[d * 68 + j] = vp[(size_t)d * T + kn0 + j];
        }
        __syncthreads();

        float sc0[8], sc1[8];
#pragma unroll
        for (int r = 0; r < 8; r++) {
            int rr = r0 + r;
            float s0 = 0.f, s1 = 0.f;
#pragma unroll
            for (int d = 0; d < 64; d += 4) {
                float4 q4 = *(const float4*)&Qs[rr * 64 + d];
                float4 ka = *(const float4*)&Ks[lane * 68 + d];
                float4 kb = *(const float4*)&Ks[(lane + 32) * 68 + d];
                s0 += q4.x * ka.x + q4.y * ka.y + q4.z * ka.z + q4.w * ka.w;
                s1 += q4.x * kb.x + q4.y * kb.y + q4.z * kb.z + q4.w * kb.w;
            }
            int tg = m0 + rr;
            if (kn0 + lane      > tg) s0 = -1e4f;
            if (kn0 + lane + 32 > tg) s1 = -1e4f;
            sc0[r] = s0; sc1[r] = s1;
        }
        __syncthreads();

#pragma unroll
        for (int r = 0; r < 8; r++) {
            int rr = r0 + r;
            float mx = fmaxf(sc0[r], sc1[r]);
#pragma unroll
            for (int off = 16; off; off >>= 1)
                mx = fmaxf(mx, __shfl_xor_sync(0xffffffffu, mx, off));
            float mnew = fmaxf(mI[r], mx);
            float p0 = __expf(sc0[r] - mnew);
            float p1 = __expf(sc1[r] - mnew);
            float ps = p0 + p1;
#pragma unroll
            for (int off = 16; off; off >>= 1)
                ps += __shfl_xor_sync(0xffffffffu, ps, off);
            float corr = __expf(mI[r] - mnew);
            lI[r] = lI[r] * corr + ps;
            mI[r] = mnew;
            a0[r] *= corr; a1[r] *= corr;
            Ss[rr * 68 + lane]      = p0;
            Ss[rr * 68 + lane + 32] = p1;
        }
        __syncwarp();

#pragma unroll
        for (int r = 0; r < 8; r++) {
            int rr = r0 + r;
            float acc0 = 0.f, acc1 = 0.f;
#pragma unroll
            for (int j = 0; j < 64; j += 4) {
                float4 p4 = *(const float4*)&Ss[rr * 68 + j];
                float4 va = *(const float4*)&Vt[lane * 68 + j];
                float4 vb = *(const float4*)&Vt[(lane + 32) * 68 + j];
                acc0 += p4.x * va.x + p4.y * va.y + p4.z * va.z + p4.w * va.w;
                acc1 += p4.x * vb.x + p4.y * vb.y + p4.z * vb.z + p4.w * vb.w;
            }
            a0[r] += acc0; a1[r] += acc1;
        }
    }

#pragma unroll
    for (int r = 0; r < 8; r++) {
        int rr = r0 + r;
        float inv = 1.f / lI[r];
        o[base + (size_t)lane        * T + m0 + rr] = a0[r] * inv;
        o[base + (size_t)(lane + 32) * T + m0 + rr] = a1[r] * inv;
    }
}

// ---------------- final 1-channel projection ----------------
__global__ void proj_out(const float* __restrict__ x, const float* __restrict__ w,
                         const float* __restrict__ pb, const float* __restrict__ mask,
                         float* __restrict__ out)
{
    int t = blockIdx.x * 256 + threadIdx.x;
    int b = blockIdx.y;
    float s = pb[0];
    const float* xb = x + (size_t)b * C * T;
    for (int c = 0; c < C; c++)
        s += w[c] * xb[(size_t)c * T + t];
    out[(size_t)b * T + t] = s * mask[(size_t)b * T + t];
}

// ---------------- launch ----------------
extern "C" void kernel_launch(void* const* d_in, const int* in_sizes, int n_in,
                              void* d_out, int out_size)
{
    const float* x    = (const float*)d_in[0];
    const float* f0   = (const float*)d_in[1];
    const float* mask = (const float*)d_in[2];
    const float* spk  = (const float*)d_in[3];
    const float* prw  = (const float*)d_in[4];
    const float* prb  = (const float*)d_in[5];
    const float* f0w  = (const float*)d_in[6];
    const float* f0b  = (const float*)d_in[7];
    const float* cw   = (const float*)d_in[8];
    const float* cb   = (const float*)d_in[9];
    const float* pw   = (const float*)d_in[10];
    const float* pb   = (const float*)d_in[11];
    const float* qw   = (const float*)d_in[12];
    const float* qb   = (const float*)d_in[13];
    const float* kw   = (const float*)d_in[14];
    const float* kb   = (const float*)d_in[15];
    const float* vw   = (const float*)d_in[16];
    const float* vb   = (const float*)d_in[17];
    const float* ow   = (const float*)d_in[18];
    const float* ob   = (const float*)d_in[19];
    const float* ln0g = (const float*)d_in[20];
    const float* ln0b = (const float*)d_in[21];
    const float* ln1g = (const float*)d_in[22];
    const float* ln1b = (const float*)d_in[23];
    const float* f1w  = (const float*)d_in[24];
    const float* f1b  = (const float*)d_in[25];
    const float* f2w  = (const float*)d_in[26];
    const float* f2b  = (const float*)d_in[27];
    float* out = (float*)d_out;

    float *gx, *gy, *gq, *gk, *gv, *gatt, *gh;
    uint32_t *wh, *wl, *ah, *al;
    cudaGetSymbolAddress((void**)&gx,   g_x);
    cudaGetSymbolAddress((void**)&gy,   g_y);
    cudaGetSymbolAddress((void**)&gq,   g_q);
    cudaGetSymbolAddress((void**)&gk,   g_k);
    cudaGetSymbolAddress((void**)&gv,   g_v);
    cudaGetSymbolAddress((void**)&gatt, g_att);
    cudaGetSymbolAddress((void**)&gh,   g_h);
    cudaGetSymbolAddress((void**)&wh,   g_wh);
    cudaGetSymbolAddress((void**)&wl,   g_wl);
    cudaGetSymbolAddress((void**)&ah,   g_ah);
    cudaGetSymbolAddress((void**)&al,   g_al);

    cudaFuncSetAttribute(flash_attn, cudaFuncAttributeMaxDynamicSharedMemorySize, FLASH_SMEM);

    // ---- pack all weights (graph-captured, ~60us) ----
    pack_w<<<dim3(65536 / 256, 1), 256>>>(cw, 0, OFF_COND, 0, S, 1, 8);
    pack_w<<<dim3(393216 / 256, 1), 256>>>(prw, 0, OFF_PRE, 0, C, 3, 48);
    pack_w<<<dim3(131072 / 256, L), 256>>>(qw, (size_t)C * C, OFF_QKV + 0,      QKV_LSTR, C, 1, 16);
    pack_w<<<dim3(131072 / 256, L), 256>>>(kw, (size_t)C * C, OFF_QKV + 131072, QKV_LSTR, C, 1, 16);
    pack_w<<<dim3(131072 / 256, L), 256>>>(vw, (size_t)C * C, OFF_QKV + 262144, QKV_LSTR, C, 1, 16);
    pack_w<<<dim3(131072 / 256, L), 256>>>(ow, (size_t)C * C, OFF_OUT, OUT_LSTR, C, 1, 16);
    pack_w<<<dim3(1572864 / 256, L), 256>>>(f1w, (size_t)FC * C * 3, OFF_F1, F1_LSTR, C,  3, 48);
    pack_w<<<dim3(1572864 / 256, L), 256>>>(f2w, (size_t)C * FC * 3, OFF_F2, F2_LSTR, FC, 3, 192);

    // ---- prep: gy = x + cond(spk); gy += f0conv; gx = prenet(gy) * mask ----
    split_act<<<dim3(T / 256, S / 2, B), 256>>>(spk, ah, al, S / 2);
    mma_gemm_p<1, 0, false, false, true, 1><<<dim3(T / 128, 4, B), 256>>>(
        ah, al, wh + OFF_COND, wl + OFF_COND, cb, cb, cb, nullptr, x, gy, gy, gy, S, C);
    add_f0<<<dim3(T / 256, C, B), 256>>>(f0, f0w, f0b, gy);
    split_act<<<dim3(T / 256, C / 2, B), 256>>>(gy, ah, al, C / 2);
    mma_gemm_p<3, 1, false, true, false, 1><<<dim3(T / 128, 4, B), 256>>>(
        ah, al, wh + OFF_PRE, wl + OFF_PRE, prb, prb, prb, mask, nullptr, gx, gx, gx, C, C);
    split_act<<<dim3(T / 256, C / 2, B), 256>>>(gx, ah, al, C / 2);

    for (int l = 0; l < L; l++) {
        // fused QKV (grid.y: 0-3 Q, 4-7 K, 8-11 V)
        mma_gemm_p<1, 0, false, false, false, 3><<<dim3(T / 128, 12, B), 256>>>(
            ah, al, wh + OFF_QKV + (size_t)l * QKV_LSTR, wl + OFF_QKV + (size_t)l * QKV_LSTR,
            qb + l * C, kb + l * C, vb + l * C, nullptr, nullptr, gq, gk, gv, C, C);

        flash_attn<<<dim3(T / 64, B * H), 256, FLASH_SMEM>>>(gq, gk, gv, gatt);

        split_act<<<dim3(T / 256, C / 2, B), 256>>>(gatt, ah, al, C / 2);
        mma_gemm_p<1, 0, false, false, false, 1><<<dim3(T / 128, 4, B), 256>>>(
            ah, al, wh + OFF_OUT + (size_t)l * OUT_LSTR, wl + OFF_OUT + (size_t)l * OUT_LSTR,
            ob + l * C, nullptr, nullptr, nullptr, nullptr, gy, nullptr, nullptr, C, C);

        add_ln_p<<<dim3(T / 32, B), dim3(32, 8)>>>(gx, gy, ln0g + l * C, ln0b + l * C, gx, ah, al);

        mma_gemm_p<3, 2, true, false, false, 1><<<dim3(T / 128, FC / 128, B), 256>>>(
            ah, al, wh + OFF_F1 + (size_t)l * F1_LSTR, wl + OFF_F1 + (size_t)l * F1_LSTR,
            f1b + l * FC, nullptr, nullptr, nullptr, nullptr, gh, nullptr, nullptr, C, FC);

        split_act<<<dim3(T / 256, FC / 2, B), 256>>>(gh, ah, al, FC / 2);
        mma_gemm_p<3, 2, false, true, false, 1><<<dim3(T / 128, 4, B), 256>>>(
            ah, al, wh + OFF_F2 + (size_t)l * F2_LSTR, wl + OFF_F2 + (size_t)l * F2_LSTR,
            f2b + l * C, nullptr, nullptr, mask, nullptr, gy, nullptr, nullptr, FC, C);

        add_ln_p<<<dim3(T / 32, B), dim3(32, 8)>>>(gx, gy, ln1g + l * C, ln1b + l * C, gx, ah, al);
    }

    proj_out<<<dim3(T / 256, B), 256>>>(gx, pw, pb, mask, out);
}

// round 6
// speedup vs baseline: 1.0496x; 1.0496x over previous
#include <cuda_runtime.h>
#include <cuda_bf16.h>
#include <cstdint>
#include <cstddef>

// ---------------- problem constants ----------------
static constexpr int B  = 4;
static constexpr int C  = 512;
static constexpr int T  = 2048;
static constexpr int H  = 8;
static constexpr int FC = 2048;
static constexpr int L  = 6;
static constexpr int S  = 256;
static constexpr int DK = 64;

// ---------------- device scratch ----------------
__device__ float g_x[B * C * T];
__device__ float g_y[B * C * T];
__device__ float g_q[B * C * T];
__device__ float g_k[B * C * T];
__device__ float g_v[B * C * T];

// packed split weights (hi/lo bf16x2), pretiled [omBlk][chunk][m(128)][k2(16)]
static constexpr size_t OFF_COND = 0;
static constexpr size_t OFF_PRE  = 65536;
static constexpr size_t OFF_QKV  = 458752;
static constexpr size_t QKV_LSTR = 393216;
static constexpr size_t OFF_OUT  = 2818048;
static constexpr size_t OUT_LSTR = 131072;
static constexpr size_t OFF_F1   = 3604480;
static constexpr size_t F1_LSTR  = 1572864;
static constexpr size_t OFF_F2   = 13041664;
static constexpr size_t F2_LSTR  = 1572864;
static constexpr size_t W_TOTAL  = 22478848;

__device__ uint32_t g_wh[W_TOTAL];
__device__ uint32_t g_wl[W_TOTAL];
// packed split activations, ping-pong buffers [b][c2][t]
__device__ uint32_t g_ah[(size_t)B * (FC / 2) * T];
__device__ uint32_t g_al[(size_t)B * (FC / 2) * T];
__device__ uint32_t g_bh[(size_t)B * (FC / 2) * T];
__device__ uint32_t g_bl[(size_t)B * (FC / 2) * T];

// ---------------- helpers ----------------
__device__ __forceinline__ uint32_t pack_bf2(float a, float b) {
    uint32_t r;
    asm("cvt.rn.bf16x2.f32 %0, %1, %2;" : "=r"(r) : "f"(b), "f"(a));
    return r;
}
__device__ __forceinline__ float bf_hi_val(float v) {
    __nv_bfloat16 h = __float2bfloat16_rn(v);
    return __bfloat162float(h);
}
__device__ __forceinline__ void mma_bf16(float* d, const uint32_t* a, const uint32_t* b) {
    asm volatile("mma.sync.aligned.m16n8k16.row.col.f32.bf16.bf16.f32 "
        "{%0,%1,%2,%3}, {%4,%5,%6,%7}, {%8,%9}, {%0,%1,%2,%3};"
        : "+f"(d[0]), "+f"(d[1]), "+f"(d[2]), "+f"(d[3])
        : "r"(a[0]), "r"(a[1]), "r"(a[2]), "r"(a[3]), "r"(b[0]), "r"(b[1]));
}
__device__ __forceinline__ uint32_t smem_u32(const void* p) {
    uint32_t a;
    asm("{ .reg .u64 t; cvta.to.shared.u64 t, %1; cvt.u32.u64 %0, t; }" : "=r"(a) : "l"(p));
    return a;
}
__device__ __forceinline__ void ldm4(uint32_t* r, uint32_t addr) {
    asm volatile("ldmatrix.sync.aligned.m8n8.x4.shared.b16 {%0,%1,%2,%3}, [%4];"
        : "=r"(r[0]), "=r"(r[1]), "=r"(r[2]), "=r"(r[3]) : "r"(addr));
}

// ---------------- weight packing ----------------
// dst word within chunk-block (2048): m = r2>>4 (0..127), k2 = r2&15.
// k2 pairing: KW==1 -> channels (2k2, 2k2+1); KW==3 (kk-major) -> kk = k2/(Cin/2),
// c2 = k2%(Cin/2), pair channels (2c2, 2c2+1) at temporal tap kk.
__global__ void pack_w(const float* __restrict__ src, size_t src_lstride,
                       size_t dst_base, size_t dst_lstride,
                       int Cin, int KW, int chunks)
{
    const int l = blockIdx.y;
    const int w = blockIdx.x * 256 + threadIdx.x;
    const int per_blk = chunks * 2048;
    const int omBlk = w / per_blk;
    const int r  = w % per_blk;
    const int ch = r / 2048, r2 = r % 2048;
    const int m  = r2 >> 4;
    const int k2 = ch * 16 + (r2 & 15);
    int ka, kb;
    if (KW == 1) { ka = 2 * k2; kb = ka + 1; }
    else { int half = Cin >> 1; int c2 = k2 % half, kk = k2 / half;
           ka = (2 * c2) * KW + kk; kb = ka + KW; }
    const float* s = src + (size_t)l * src_lstride + (size_t)(omBlk * 128 + m) * Cin * KW;
    float va = s[ka], vb = s[kb];
    float ha = bf_hi_val(va), hb = bf_hi_val(vb);
    size_t d = dst_base + (size_t)l * dst_lstride + w;
    g_wh[d] = pack_bf2(ha, hb);
    g_wl[d] = pack_bf2(va - ha, vb - hb);
}

// ---------------- activation split/pack (prep only) ----------------
__global__ void split_act(const float* __restrict__ X, uint32_t* __restrict__ Xh,
                          uint32_t* __restrict__ Xl, int Chalf)
{
    const int t  = blockIdx.x * 256 + threadIdx.x;
    const int c2 = blockIdx.y;
    const int b  = blockIdx.z;
    const float* x0 = X + ((size_t)b * 2 * Chalf + 2 * c2) * T;
    float va = x0[t], vb = x0[T + t];
    float ha = bf_hi_val(va), hb = bf_hi_val(vb);
    size_t d = ((size_t)b * Chalf + c2) * T + t;
    Xh[d] = pack_bf2(ha, hb);
    Xl[d] = pack_bf2(va - ha, vb - hb);
}

// ================= packed bf16x2-split mma.sync conv-GEMM =================
static constexpr int KSTR = 136;   // B smem row stride (words)
static constexpr int ASTR = 20;    // A smem row stride (words), 16B-aligned, conflict-free

template <int KW, int PL, bool RELU, bool DOMASK, bool ADDSRC, int NOUT, bool PACKOUT>
__global__ __launch_bounds__(256, 2) void mma_gemm_p(
    const uint32_t* __restrict__ Xh, const uint32_t* __restrict__ Xl,
    const uint32_t* __restrict__ Wh, const uint32_t* __restrict__ Wl,
    const float* __restrict__ b0, const float* __restrict__ b1, const float* __restrict__ b2,
    const float* __restrict__ mask, const float* __restrict__ src,
    float* __restrict__ Y0, float* __restrict__ Y1, float* __restrict__ Y2,
    uint32_t* __restrict__ poh, uint32_t* __restrict__ pol,
    int Cin, int Cout)
{
    __shared__ uint32_t Ah[128 * ASTR], Al[128 * ASTR];
    __shared__ uint32_t Bh[16 * KSTR],  Bl[16 * KSTR];

    const int tid  = threadIdx.x;
    const int lane = tid & 31;
    const int wid  = tid >> 5;
    const int mw   = wid & 1;
    const int nw   = wid >> 1;
    const int gid  = lane >> 2;
    const int tig  = lane & 3;

    const int b   = blockIdx.z;
    const int tn0 = blockIdx.x * 128;
    int sel, om;
    if (NOUT == 3) { sel = blockIdx.y >> 2; om = (blockIdx.y & 3) * 128; }
    else           { sel = 0;               om = blockIdx.y * 128; }
    const float* bias = (NOUT == 3) ? (sel == 0 ? b0 : sel == 1 ? b1 : b2) : b0;
    float* Y          = (NOUT == 3) ? (sel == 0 ? Y0 : sel == 1 ? Y1 : Y2) : Y0;

    const int Chalf  = Cin >> 1;
    const int chunks = (Cin * KW) >> 5;
    const uint32_t* wtH = Wh + (size_t)blockIdx.y * chunks * 2048;
    const uint32_t* wtL = Wl + (size_t)blockIdx.y * chunks * 2048;
    const uint32_t* XhB = Xh + (size_t)b * Chalf * T;
    const uint32_t* XlB = Xl + (size_t)b * Chalf * T;

    // loader indices
    const int lm  = tid >> 1;           // A: m row
    const int lh  = tid & 1;            // A: which 8-word half
    const int lk2 = tid >> 4;           // B: k2 row
    const int lq  = tid & 15;           // B: 8-word group

    // ldmatrix lane base: matrix q = lane>>3 -> rows (q&1)*8.., cols (q>>1)*4
    const int qq   = lane >> 3;
    const int rrow = lane & 7;
    const uint32_t aAh = smem_u32(Ah);
    const uint32_t aAl = smem_u32(Al);
    const uint32_t laneOff = ((uint32_t)((mw * 64 + (qq & 1) * 8 + rrow) * ASTR
                             + (qq >> 1) * 4)) * 4u;

    float acc[4][4][4];
#pragma unroll
    for (int i = 0; i < 4; i++)
#pragma unroll
        for (int j = 0; j < 4; j++)
#pragma unroll
            for (int r = 0; r < 4; r++) acc[i][j][r] = 0.f;

    for (int ch = 0; ch < chunks; ch++) {
        // ---- A: pretiled [m][k2] -> smem [m][ASTR] ----
        {
            const uint32_t* aH = wtH + ch * 2048 + lm * 16 + lh * 8;
            const uint32_t* aL = wtL + ch * 2048 + lm * 16 + lh * 8;
            uint4 h0 = *(const uint4*)aH;
            uint4 h1 = *(const uint4*)(aH + 4);
            uint4 l0 = *(const uint4*)aL;
            uint4 l1 = *(const uint4*)(aL + 4);
            *(uint4*)&Ah[lm * ASTR + lh * 8]     = h0;
            *(uint4*)&Ah[lm * ASTR + lh * 8 + 4] = h1;
            *(uint4*)&Al[lm * ASTR + lh * 8]     = l0;
            *(uint4*)&Al[lm * ASTR + lh * 8 + 4] = l1;
        }
        // ---- B: packed activations [k2][n] ----
        {
            const int k2g = ch * 16 + lk2;
            if (KW == 1) {
                const uint32_t* rH = XhB + (size_t)k2g * T + tn0 + lq * 8;
                const uint32_t* rL = XlB + (size_t)k2g * T + tn0 + lq * 8;
                uint4 h0 = *(const uint4*)rH;
                uint4 h1 = *(const uint4*)(rH + 4);
                uint4 l0 = *(const uint4*)rL;
                uint4 l1 = *(const uint4*)(rL + 4);
                *(uint4*)&Bh[lk2 * KSTR + lq * 8]     = h0;
                *(uint4*)&Bh[lk2 * KSTR + lq * 8 + 4] = h1;
                *(uint4*)&Bl[lk2 * KSTR + lq * 8]     = l0;
                *(uint4*)&Bl[lk2 * KSTR + lq * 8 + 4] = l1;
            } else {
                const int c2 = k2g % Chalf;
                const int kk = k2g / Chalf;
                const int dt = kk - PL;
                const uint32_t* rH = XhB + (size_t)c2 * T;
                const uint32_t* rL = XlB + (size_t)c2 * T;
                const int tb = tn0 + lq * 8 + dt;
#pragma unroll
                for (int j = 0; j < 8; j++) {
                    int t = tb + j;
                    bool ok = (unsigned)t < (unsigned)T;
                    Bh[lk2 * KSTR + lq * 8 + j] = ok ? rH[t] : 0u;
                    Bl[lk2 * KSTR + lq * 8 + j] = ok ? rL[t] : 0u;
                }
            }
        }
        __syncthreads();

#pragma unroll
        for (int ks = 0; ks < 2; ks++) {
            const int k2a = ks * 8 + tig;
            const int k2b = ks * 8 + 4 + tig;
            uint32_t bfh[4][2], bfl[4][2];
#pragma unroll
            for (int nt = 0; nt < 4; nt++) {
                int n = nw * 32 + nt * 8 + gid;
                bfh[nt][0] = Bh[k2a * KSTR + n];
                bfh[nt][1] = Bh[k2b * KSTR + n];
                bfl[nt][0] = Bl[k2a * KSTR + n];
                bfl[nt][1] = Bl[k2b * KSTR + n];
            }
#pragma unroll
            for (int mt = 0; mt < 4; mt++) {
                uint32_t afh[4], afl[4];
                const uint32_t off = laneOff + (uint32_t)(mt * 16 * ASTR + ks * 8) * 4u;
                ldm4(afh, aAh + off);
                ldm4(afl, aAl + off);
#pragma unroll
                for (int nt = 0; nt < 4; nt++) {
                    mma_bf16(acc[mt][nt], afh, bfh[nt]);
                    mma_bf16(acc[mt][nt], afh, bfl[nt]);
                    mma_bf16(acc[mt][nt], afl, bfh[nt]);
                }
            }
        }
        __syncthreads();
    }

    // ---- epilogue ----
    const int ChalfO = Cout >> 1;
#pragma unroll
    for (int mt = 0; mt < 4; mt++) {
        int o0 = om + mw * 64 + mt * 16 + gid;
        float bb0 = bias[o0];
        float bb1 = bias[o0 + 8];
#pragma unroll
        for (int nt = 0; nt < 4; nt++) {
            int t0 = tn0 + nw * 32 + nt * 8 + 2 * tig;
            float v0 = acc[mt][nt][0] + bb0;
            float v1 = acc[mt][nt][1] + bb0;
            float v2 = acc[mt][nt][2] + bb1;
            float v3 = acc[mt][nt][3] + bb1;
            if (RELU) {
                v0 = fmaxf(v0, 0.f); v1 = fmaxf(v1, 0.f);
                v2 = fmaxf(v2, 0.f); v3 = fmaxf(v3, 0.f);
            }
            if (PACKOUT) {
                // channel pairing via gid^1 partner (lane^4)
                float q0 = __shfl_xor_sync(0xffffffffu, v0, 4);
                float q1 = __shfl_xor_sync(0xffffffffu, v1, 4);
                float q2 = __shfl_xor_sync(0xffffffffu, v2, 4);
                float q3 = __shfl_xor_sync(0xffffffffu, v3, 4);
                if ((gid & 1) == 0) {
                    size_t da = ((size_t)b * ChalfO + (o0 >> 1)) * T + t0;
                    size_t db = ((size_t)b * ChalfO + ((o0 + 8) >> 1)) * T + t0;
                    float h;
                    h = bf_hi_val(v0); float hq = bf_hi_val(q0);
                    poh[da]     = pack_bf2(h, hq);
                    pol[da]     = pack_bf2(v0 - h, q0 - hq);
                    h = bf_hi_val(v1); hq = bf_hi_val(q1);
                    poh[da + 1] = pack_bf2(h, hq);
                    pol[da + 1] = pack_bf2(v1 - h, q1 - hq);
                    h = bf_hi_val(v2); hq = bf_hi_val(q2);
                    poh[db]     = pack_bf2(h, hq);
                    pol[db]     = pack_bf2(v2 - h, q2 - hq);
                    h = bf_hi_val(v3); hq = bf_hi_val(q3);
                    poh[db + 1] = pack_bf2(h, hq);
                    pol[db + 1] = pack_bf2(v3 - h, q3 - hq);
                }
            } else {
                float m0 = 1.f, m1 = 1.f;
                if (DOMASK) {
                    m0 = mask[(size_t)b * T + t0];
                    m1 = mask[(size_t)b * T + t0 + 1];
                }
                size_t oi0 = ((size_t)b * Cout + o0)     * T + t0;
                size_t oi1 = ((size_t)b * Cout + o0 + 8) * T + t0;
                if (ADDSRC) {
                    float2 s0 = *(const float2*)(src + oi0);
                    float2 s1 = *(const float2*)(src + oi1);
                    v0 += s0.x; v1 += s0.y; v2 += s1.x; v3 += s1.y;
                }
                if (DOMASK) { v0 *= m0; v1 *= m1; v2 *= m0; v3 *= m1; }
                *(float2*)(Y + oi0) = make_float2(v0, v1);
                *(float2*)(Y + oi1) = make_float2(v2, v3);
            }
        }
    }
}

// ---------------- f0 prenet added in-place ----------------
__global__ void add_f0(const float* __restrict__ f0, const float* __restrict__ w,
                       const float* __restrict__ fb, float* __restrict__ y)
{
    int t = blockIdx.x * 256 + threadIdx.x;
    int c = blockIdx.y;
    int b = blockIdx.z;
    float fm1 = (t - 1 >= 0) ? f0[(size_t)b * T + t - 1] : 0.f;
    float fc0 = f0[(size_t)b * T + t];
    float fp1 = (t + 1 < T) ? f0[(size_t)b * T + t + 1] : 0.f;
    float v = w[c * 3 + 0] * fm1 + w[c * 3 + 1] * fc0 + w[c * 3 + 2] * fp1 + fb[c];
    y[((size_t)b * C + c) * T + t] += v;
}

// ---------------- fused residual-add + LayerNorm + packed split output ----------------
__global__ void add_ln_p(const float* __restrict__ x, const float* __restrict__ y,
                         const float* __restrict__ g, const float* __restrict__ be,
                         float* __restrict__ out,
                         uint32_t* __restrict__ ph, uint32_t* __restrict__ pl)
{
    __shared__ float red0[8][32];
    __shared__ float red1[8][32];
    __shared__ float smv[2][32];
    const int tx = threadIdx.x, ty = threadIdx.y;
    const int t = blockIdx.x * 32 + tx;
    const int b = blockIdx.y;
    const size_t base = (size_t)b * C * T + t;

    float s = 0.f, sq = 0.f;
    for (int c2 = ty; c2 < C / 2; c2 += 8) {
        size_t i0 = base + (size_t)(2 * c2) * T;
        float v0 = x[i0] + y[i0];
        float v1 = x[i0 + T] + y[i0 + T];
        s += v0 + v1; sq += v0 * v0 + v1 * v1;
    }
    red0[ty][tx] = s; red1[ty][tx] = sq;
    __syncthreads();
    if (ty == 0) {
#pragma unroll
        for (int i = 1; i < 8; i++) { s += red0[i][tx]; sq += red1[i][tx]; }
        float mean = s * (1.f / C);
        float var  = sq * (1.f / C) - mean * mean;
        smv[0][tx] = mean;
        smv[1][tx] = rsqrtf(var + 1e-5f);
    }
    __syncthreads();
    float mean = smv[0][tx], rstd = smv[1][tx];
    for (int c2 = ty; c2 < C / 2; c2 += 8) {
        size_t i0 = base + (size_t)(2 * c2) * T;
        float v0 = (x[i0]     + y[i0]     - mean) * rstd * g[2 * c2]     + be[2 * c2];
        float v1 = (x[i0 + T] + y[i0 + T] - mean) * rstd * g[2 * c2 + 1] + be[2 * c2 + 1];
        out[i0]     = v0;
        out[i0 + T] = v1;
        float h0 = bf_hi_val(v0), h1 = bf_hi_val(v1);
        size_t d = ((size_t)b * (C / 2) + c2) * T + t;
        ph[d] = pack_bf2(h0, h1);
        pl[d] = pack_bf2(v0 - h0, v1 - h1);
    }
}

// ---------------- fused causal flash attention, packed split output ----------------
static constexpr int FLASH_SMEM = (64 * 64 + 64 * 68 + 64 * 68) * 4;

__global__ __launch_bounds__(256) void flash_attn(
    const float* __restrict__ q, const float* __restrict__ k,
    const float* __restrict__ v,
    uint32_t* __restrict__ ph, uint32_t* __restrict__ pl)
{
    extern __shared__ float sm[];
    float* Qs = sm;
    float* Ks = sm + 64 * 64;
    float* Vt = Ks + 64 * 68;
    float* Ss = Ks;

    const int tid  = threadIdx.x;
    const int lane = tid & 31;
    const int warp = tid >> 5;
    const int mb   = blockIdx.x;
    const int m0   = mb * 64;
    const int bh   = blockIdx.y;
    const int b    = bh >> 3;
    const int h    = bh & 7;
    const size_t base = ((size_t)b * C + (size_t)h * DK) * T;
    const float* __restrict__ qp = q + base;
    const float* __restrict__ kp = k + base;
    const float* __restrict__ vp = v + base;

    for (int idx = tid; idx < 64 * 64; idx += 256) {
        int d = idx >> 6, tt = idx & 63;
        Qs[tt * 64 + d] = qp[(size_t)d * T + m0 + tt] * 0.125f;
    }

    float mI[8], lI[8], a0[8], a1[8];
#pragma unroll
    for (int r = 0; r < 8; r++) { mI[r] = -1e30f; lI[r] = 0.f; a0[r] = 0.f; a1[r] = 0.f; }
    const int r0 = warp * 8;

    for (int kbk = 0; kbk <= mb; kbk++) {
        const int kn0 = kbk * 64;
        __syncthreads();
        for (int idx = tid; idx < 64 * 64; idx += 256) {
            int d = idx >> 6, j = idx & 63;
            Ks[j * 68 + d] = kp[(size_t)d * T + kn0 + j];
            Vt[d * 68 + j] = vp[(size_t)d * T + kn0 + j];
        }
        __syncthreads();

        float sc0[8], sc1[8];
#pragma unroll
        for (int r = 0; r < 8; r++) {
            int rr = r0 + r;
            float s0 = 0.f, s1 = 0.f;
#pragma unroll
            for (int d = 0; d < 64; d += 4) {
                float4 q4 = *(const float4*)&Qs[rr * 64 + d];
                float4 ka = *(const float4*)&Ks[lane * 68 + d];
                float4 kb = *(const float4*)&Ks[(lane + 32) * 68 + d];
                s0 += q4.x * ka.x + q4.y * ka.y + q4.z * ka.z + q4.w * ka.w;
                s1 += q4.x * kb.x + q4.y * kb.y + q4.z * kb.z + q4.w * kb.w;
            }
            int tg = m0 + rr;
            if (kn0 + lane      > tg) s0 = -1e4f;
            if (kn0 + lane + 32 > tg) s1 = -1e4f;
            sc0[r] = s0; sc1[r] = s1;
        }
        __syncthreads();

#pragma unroll
        for (int r = 0; r < 8; r++) {
            int rr = r0 + r;
            float mx = fmaxf(sc0[r], sc1[r]);
#pragma unroll
            for (int off = 16; off; off >>= 1)
                mx = fmaxf(mx, __shfl_xor_sync(0xffffffffu, mx, off));
            float mnew = fmaxf(mI[r], mx);
            float p0 = __expf(sc0[r] - mnew);
            float p1 = __expf(sc1[r] - mnew);
            float ps = p0 + p1;
#pragma unroll
            for (int off = 16; off; off >>= 1)
                ps += __shfl_xor_sync(0xffffffffu, ps, off);
            float corr = __expf(mI[r] - mnew);
            lI[r] = lI[r] * corr + ps;
            mI[r] = mnew;
            a0[r] *= corr; a1[r] *= corr;
            Ss[rr * 68 + lane]      = p0;
            Ss[rr * 68 + lane + 32] = p1;
        }
        __syncwarp();

#pragma unroll
        for (int r = 0; r < 8; r++) {
            int rr = r0 + r;
            float acc0 = 0.f, acc1 = 0.f;
#pragma unroll
            for (int j = 0; j < 64; j += 4) {
                float4 p4 = *(const float4*)&Ss[rr * 68 + j];
                float4 va = *(const float4*)&Vt[lane * 68 + j];
                float4 vb = *(const float4*)&Vt[(lane + 32) * 68 + j];
                acc0 += p4.x * va.x + p4.y * va.y + p4.z * va.z + p4.w * va.w;
                acc1 += p4.x * vb.x + p4.y * vb.y + p4.z * vb.z + p4.w * vb.w;
            }
            a0[r] += acc0; a1[r] += acc1;
        }
    }

    // packed split epilogue: channel pairs (d, d+1) via lane^1 partner
#pragma unroll
    for (int r = 0; r < 8; r++) {
        int rr = r0 + r;
        float inv = 1.f / lI[r];
        float ov0 = a0[r] * inv;
        float ov1 = a1[r] * inv;
        float p0 = __shfl_xor_sync(0xffffffffu, ov0, 1);
        float p1 = __shfl_xor_sync(0xffffffffu, ov1, 1);
        if ((lane & 1) == 0) {
            int c2a = (h * DK + lane) >> 1;
            int c2b = (h * DK + 32 + lane) >> 1;
            size_t da = ((size_t)b * (C / 2) + c2a) * T + m0 + rr;
            size_t db = ((size_t)b * (C / 2) + c2b) * T + m0 + rr;
            float h0 = bf_hi_val(ov0), h1 = bf_hi_val(p0);
            ph[da] = pack_bf2(h0, h1);
            pl[da] = pack_bf2(ov0 - h0, p0 - h1);
            float h2 = bf_hi_val(ov1), h3 = bf_hi_val(p1);
            ph[db] = pack_bf2(h2, h3);
            pl[db] = pack_bf2(ov1 - h2, p1 - h3);
        }
    }
}

// ---------------- final 1-channel projection ----------------
__global__ void proj_out(const float* __restrict__ x, const float* __restrict__ w,
                         const float* __restrict__ pb, const float* __restrict__ mask,
                         float* __restrict__ out)
{
    int t = blockIdx.x * 256 + threadIdx.x;
    int b = blockIdx.y;
    float s = pb[0];
    const float* xb = x + (size_t)b * C * T;
    for (int c = 0; c < C; c++)
        s += w[c] * xb[(size_t)c * T + t];
    out[(size_t)b * T + t] = s * mask[(size_t)b * T + t];
}

// ---------------- launch ----------------
extern "C" void kernel_launch(void* const* d_in, const int* in_sizes, int n_in,
                              void* d_out, int out_size)
{
    const float* x    = (const float*)d_in[0];
    const float* f0   = (const float*)d_in[1];
    const float* mask = (const float*)d_in[2];
    const float* spk  = (const float*)d_in[3];
    const float* prw  = (const float*)d_in[4];
    const float* prb  = (const float*)d_in[5];
    const float* f0w  = (const float*)d_in[6];
    const float* f0b  = (const float*)d_in[7];
    const float* cw   = (const float*)d_in[8];
    const float* cb   = (const float*)d_in[9];
    const float* pw   = (const float*)d_in[10];
    const float* pb   = (const float*)d_in[11];
    const float* qw   = (const float*)d_in[12];
    const float* qb   = (const float*)d_in[13];
    const float* kw   = (const float*)d_in[14];
    const float* kb   = (const float*)d_in[15];
    const float* vw   = (const float*)d_in[16];
    const float* vb   = (const float*)d_in[17];
    const float* ow   = (const float*)d_in[18];
    const float* ob   = (const float*)d_in[19];
    const float* ln0g = (const float*)d_in[20];
    const float* ln0b = (const float*)d_in[21];
    const float* ln1g = (const float*)d_in[22];
    const float* ln1b = (const float*)d_in[23];
    const float* f1w  = (const float*)d_in[24];
    const float* f1b  = (const float*)d_in[25];
    const float* f2w  = (const float*)d_in[26];
    const float* f2b  = (const float*)d_in[27];
    float* out = (float*)d_out;

    float *gx, *gy, *gq, *gk, *gv;
    uint32_t *wh, *wl, *ah, *al, *bh2, *bl2;
    cudaGetSymbolAddress((void**)&gx,  g_x);
    cudaGetSymbolAddress((void**)&gy,  g_y);
    cudaGetSymbolAddress((void**)&gq,  g_q);
    cudaGetSymbolAddress((void**)&gk,  g_k);
    cudaGetSymbolAddress((void**)&gv,  g_v);
    cudaGetSymbolAddress((void**)&wh,  g_wh);
    cudaGetSymbolAddress((void**)&wl,  g_wl);
    cudaGetSymbolAddress((void**)&ah,  g_ah);
    cudaGetSymbolAddress((void**)&al,  g_al);
    cudaGetSymbolAddress((void**)&bh2, g_bh);
    cudaGetSymbolAddress((void**)&bl2, g_bl);

    cudaFuncSetAttribute(flash_attn, cudaFuncAttributeMaxDynamicSharedMemorySize, FLASH_SMEM);

    // ---- pack all weights ----
    pack_w<<<dim3(65536 / 256, 1), 256>>>(cw, 0, OFF_COND, 0, S, 1, 8);
    pack_w<<<dim3(393216 / 256, 1), 256>>>(prw, 0, OFF_PRE, 0, C, 3, 48);
    pack_w<<<dim3(131072 / 256, L), 256>>>(qw, (size_t)C * C, OFF_QKV + 0,      QKV_LSTR, C, 1, 16);
    pack_w<<<dim3(131072 / 256, L), 256>>>(kw, (size_t)C * C, OFF_QKV + 131072, QKV_LSTR, C, 1, 16);
    pack_w<<<dim3(131072 / 256, L), 256>>>(vw, (size_t)C * C, OFF_QKV + 262144, QKV_LSTR, C, 1, 16);
    pack_w<<<dim3(131072 / 256, L), 256>>>(ow, (size_t)C * C, OFF_OUT, OUT_LSTR, C, 1, 16);
    pack_w<<<dim3(1572864 / 256, L), 256>>>(f1w, (size_t)FC * C * 3, OFF_F1, F1_LSTR, C,  3, 48);
    pack_w<<<dim3(1572864 / 256, L), 256>>>(f2w, (size_t)C * FC * 3, OFF_F2, F2_LSTR, FC, 3, 192);

    // ---- prep ----
    split_act<<<dim3(T / 256, S / 2, B), 256>>>(spk, ah, al, S / 2);
    mma_gemm_p<1, 0, false, false, true, 1, false><<<dim3(T / 128, 4, B), 256>>>(
        ah, al, wh + OFF_COND, wl + OFF_COND, cb, cb, cb, nullptr, x,
        gy, gy, gy, nullptr, nullptr, S, C);
    add_f0<<<dim3(T / 256, C, B), 256>>>(f0, f0w, f0b, gy);
    split_act<<<dim3(T / 256, C / 2, B), 256>>>(gy, ah, al, C / 2);
    mma_gemm_p<3, 1, false, true, false, 1, false><<<dim3(T / 128, 4, B), 256>>>(
        ah, al, wh + OFF_PRE, wl + OFF_PRE, prb, prb, prb, mask, nullptr,
        gx, gx, gx, nullptr, nullptr, C, C);
    split_act<<<dim3(T / 256, C / 2, B), 256>>>(gx, ah, al, C / 2);

    for (int l = 0; l < L; l++) {
        // fused QKV from packed A-buf
        mma_gemm_p<1, 0, false, false, false, 3, false><<<dim3(T / 128, 12, B), 256>>>(
            ah, al, wh + OFF_QKV + (size_t)l * QKV_LSTR, wl + OFF_QKV + (size_t)l * QKV_LSTR,
            qb + l * C, kb + l * C, vb + l * C, nullptr, nullptr,
            gq, gk, gv, nullptr, nullptr, C, C);

        // attention -> packed B-buf
        flash_attn<<<dim3(T / 64, B * H), 256, FLASH_SMEM>>>(gq, gk, gv, bh2, bl2);

        // out-proj from packed B-buf -> gy float
        mma_gemm_p<1, 0, false, false, false, 1, false><<<dim3(T / 128, 4, B), 256>>>(
            bh2, bl2, wh + OFF_OUT + (size_t)l * OUT_LSTR, wl + OFF_OUT + (size_t)l * OUT_LSTR,
            ob + l * C, nullptr, nullptr, nullptr, nullptr,
            gy, nullptr, nullptr, nullptr, nullptr, C, C);

        add_ln_p<<<dim3(T / 32, B), dim3(32, 8)>>>(gx, gy, ln0g + l * C, ln0b + l * C, gx, ah, al);

        // FFN1 from A-buf -> packed B-buf (relu)
        mma_gemm_p<3, 2, true, false, false, 1, true><<<dim3(T / 128, FC / 128, B), 256>>>(
            ah, al, wh + OFF_F1 + (size_t)l * F1_LSTR, wl + OFF_F1 + (size_t)l * F1_LSTR,
            f1b + l * FC, nullptr, nullptr, nullptr, nullptr,
            nullptr, nullptr, nullptr, bh2, bl2, C, FC);

        // FFN2 from packed B-buf -> gy float (mask)
        mma_gemm_p<3, 2, false, true, false, 1, false><<<dim3(T / 128, 4, B), 256>>>(
            bh2, bl2, wh + OFF_F2 + (size_t)l * F2_LSTR, wl + OFF_F2 + (size_t)l * F2_LSTR,
            f2b + l * C, nullptr, nullptr, mask, nullptr,
            gy, nullptr, nullptr, nullptr, nullptr, FC, C);

        add_ln_p<<<dim3(T / 32, B), dim3(32, 8)>>>(gx, gy, ln1g + l * C, ln1b + l * C, gx, ah, al);
    }

    proj_out<<<dim3(T / 256, B), 256>>>(gx, pw, pb, mask, out);
}

// round 7
// speedup vs baseline: 1.1721x; 1.1167x over previous
#include <cuda_runtime.h>
#include <cuda_bf16.h>
#include <cstdint>
#include <cstddef>

// ---------------- problem constants ----------------
static constexpr int B  = 4;
static constexpr int C  = 512;
static constexpr int T  = 2048;
static constexpr int H  = 8;
static constexpr int FC = 2048;
static constexpr int L  = 6;
static constexpr int S  = 256;
static constexpr int DK = 64;

// ---------------- device scratch ----------------
__device__ float g_x[B * C * T];
__device__ float g_y[B * C * T];
__device__ float g_q[B * C * T];
__device__ float g_k[B * C * T];
__device__ float g_v[B * C * T];

// packed split weights (hi/lo bf16x2), pretiled [omBlk][chunk][m(128)][k2(16)]
static constexpr size_t OFF_COND = 0;
static constexpr size_t OFF_PRE  = 65536;
static constexpr size_t OFF_QKV  = 458752;
static constexpr size_t QKV_LSTR = 393216;
static constexpr size_t OFF_OUT  = 2818048;
static constexpr size_t OUT_LSTR = 131072;
static constexpr size_t OFF_F1   = 3604480;
static constexpr size_t F1_LSTR  = 1572864;
static constexpr size_t OFF_F2   = 13041664;
static constexpr size_t F2_LSTR  = 1572864;
static constexpr size_t W_TOTAL  = 22478848;

__device__ uint32_t g_wh[W_TOTAL];
__device__ uint32_t g_wl[W_TOTAL];
// packed split activations, ping-pong buffers [b][c2][t]
__device__ uint32_t g_ah[(size_t)B * (FC / 2) * T];
__device__ uint32_t g_al[(size_t)B * (FC / 2) * T];
__device__ uint32_t g_bh[(size_t)B * (FC / 2) * T];
__device__ uint32_t g_bl[(size_t)B * (FC / 2) * T];

// ---------------- helpers ----------------
__device__ __forceinline__ uint32_t pack_bf2(float a, float b) {
    uint32_t r;
    asm("cvt.rn.bf16x2.f32 %0, %1, %2;" : "=r"(r) : "f"(b), "f"(a));
    return r;
}
__device__ __forceinline__ float bf_hi_val(float v) {
    __nv_bfloat16 h = __float2bfloat16_rn(v);
    return __bfloat162float(h);
}
__device__ __forceinline__ void mma_bf16(float* d, const uint32_t* a, const uint32_t* b) {
    asm volatile("mma.sync.aligned.m16n8k16.row.col.f32.bf16.bf16.f32 "
        "{%0,%1,%2,%3}, {%4,%5,%6,%7}, {%8,%9}, {%0,%1,%2,%3};"
        : "+f"(d[0]), "+f"(d[1]), "+f"(d[2]), "+f"(d[3])
        : "r"(a[0]), "r"(a[1]), "r"(a[2]), "r"(a[3]), "r"(b[0]), "r"(b[1]));
}
__device__ __forceinline__ uint32_t smem_u32(const void* p) {
    uint32_t a;
    asm("{ .reg .u64 t; cvta.to.shared.u64 t, %1; cvt.u32.u64 %0, t; }" : "=r"(a) : "l"(p));
    return a;
}
__device__ __forceinline__ void ldm4(uint32_t* r, uint32_t addr) {
    asm volatile("ldmatrix.sync.aligned.m8n8.x4.shared.b16 {%0,%1,%2,%3}, [%4];"
        : "=r"(r[0]), "=r"(r[1]), "=r"(r[2]), "=r"(r[3]) : "r"(addr));
}
__device__ __forceinline__ void cp16(uint32_t dst, const void* src) {
    asm volatile("cp.async.cg.shared.global [%0], [%1], 16;" :: "r"(dst), "l"(src));
}
__device__ __forceinline__ void cp4z(uint32_t dst, const void* src, int srcsz) {
    asm volatile("cp.async.ca.shared.global [%0], [%1], 4, %2;"
                 :: "r"(dst), "l"(src), "r"(srcsz));
}
__device__ __forceinline__ void cp_commit() {
    asm volatile("cp.async.commit_group;" ::: "memory");
}
template <int N>
__device__ __forceinline__ void cp_wait() {
    asm volatile("cp.async.wait_group %0;" :: "n"(N) : "memory");
}

// ---------------- weight packing ----------------
__global__ void pack_w(const float* __restrict__ src, size_t src_lstride,
                       size_t dst_base, size_t dst_lstride,
                       int Cin, int KW, int chunks)
{
    const int l = blockIdx.y;
    const int w = blockIdx.x * 256 + threadIdx.x;
    const int per_blk = chunks * 2048;
    const int omBlk = w / per_blk;
    const int r  = w % per_blk;
    const int ch = r / 2048, r2 = r % 2048;
    const int m  = r2 >> 4;
    const int k2 = ch * 16 + (r2 & 15);
    int ka, kb;
    if (KW == 1) { ka = 2 * k2; kb = ka + 1; }
    else { int half = Cin >> 1; int c2 = k2 % half, kk = k2 / half;
           ka = (2 * c2) * KW + kk; kb = ka + KW; }
    const float* s = src + (size_t)l * src_lstride + (size_t)(omBlk * 128 + m) * Cin * KW;
    float va = s[ka], vb = s[kb];
    float ha = bf_hi_val(va), hb = bf_hi_val(vb);
    size_t d = dst_base + (size_t)l * dst_lstride + w;
    g_wh[d] = pack_bf2(ha, hb);
    g_wl[d] = pack_bf2(va - ha, vb - hb);
}

// ---------------- activation split/pack (prep only) ----------------
__global__ void split_act(const float* __restrict__ X, uint32_t* __restrict__ Xh,
                          uint32_t* __restrict__ Xl, int Chalf)
{
    const int t  = blockIdx.x * 256 + threadIdx.x;
    const int c2 = blockIdx.y;
    const int b  = blockIdx.z;
    const float* x0 = X + ((size_t)b * 2 * Chalf + 2 * c2) * T;
    float va = x0[t], vb = x0[T + t];
    float ha = bf_hi_val(va), hb = bf_hi_val(vb);
    size_t d = ((size_t)b * Chalf + c2) * T + t;
    Xh[d] = pack_bf2(ha, hb);
    Xl[d] = pack_bf2(va - ha, vb - hb);
}

// ================= cp.async pipelined bf16x2-split mma.sync conv-GEMM =================
static constexpr int ASTR = 20;                  // A smem row stride (words)
static constexpr int KSTR = 136;                 // B smem row stride (words)
static constexpr int A_WORDS = 128 * ASTR;       // 2560
static constexpr int B_WORDS = 16 * KSTR;        // 2176
static constexpr int STG_WORDS = 2 * A_WORDS + 2 * B_WORDS;   // 9472
static constexpr int GEMM_SMEM = 2 * STG_WORDS * 4;           // 75776 B

template <int KW, int PL, bool RELU, bool DOMASK, bool ADDSRC, int NOUT, bool PACKOUT>
__global__ __launch_bounds__(256, 2) void mma_gemm_p(
    const uint32_t* __restrict__ Xh, const uint32_t* __restrict__ Xl,
    const uint32_t* __restrict__ Wh, const uint32_t* __restrict__ Wl,
    const float* __restrict__ b0, const float* __restrict__ b1, const float* __restrict__ b2,
    const float* __restrict__ mask, const float* __restrict__ src,
    float* __restrict__ Y0, float* __restrict__ Y1, float* __restrict__ Y2,
    uint32_t* __restrict__ poh, uint32_t* __restrict__ pol,
    int Cin, int Cout)
{
    extern __shared__ uint32_t dsm[];
    const uint32_t sbase = smem_u32(dsm);

    const int tid  = threadIdx.x;
    const int lane = tid & 31;
    const int wid  = tid >> 5;
    const int mw   = wid & 1;
    const int nw   = wid >> 1;
    const int gid  = lane >> 2;
    const int tig  = lane & 3;

    const int b   = blockIdx.z;
    const int tn0 = blockIdx.x * 128;
    int sel, om;
    if (NOUT == 3) { sel = blockIdx.y >> 2; om = (blockIdx.y & 3) * 128; }
    else           { sel = 0;               om = blockIdx.y * 128; }
    const float* bias = (NOUT == 3) ? (sel == 0 ? b0 : sel == 1 ? b1 : b2) : b0;
    float* Y          = (NOUT == 3) ? (sel == 0 ? Y0 : sel == 1 ? Y1 : Y2) : Y0;

    const int Chalf  = Cin >> 1;
    const int chunks = (Cin * KW) >> 5;
    const uint32_t* wtH = Wh + (size_t)blockIdx.y * chunks * 2048;
    const uint32_t* wtL = Wl + (size_t)blockIdx.y * chunks * 2048;
    const uint32_t* XhB = Xh + (size_t)b * Chalf * T;
    const uint32_t* XlB = Xl + (size_t)b * Chalf * T;

    // loader indices
    const int lm  = tid >> 1;           // A: m row
    const int lh  = tid & 1;            // A: 8-word half
    const int lk2 = tid >> 4;           // B: k2 row
    const int lq  = tid & 15;           // B: 8-word group

    // ldmatrix lane base (within an A tile)
    const int qq   = lane >> 3;
    const int rrow = lane & 7;
    const uint32_t laneOff = ((uint32_t)((mw * 64 + (qq & 1) * 8 + rrow) * ASTR
                             + (qq >> 1) * 4)) * 4u;

    auto issueA = [&](int ch, int s) {
        const uint32_t* aH = wtH + ch * 2048 + lm * 16 + lh * 8;
        const uint32_t* aL = wtL + ch * 2048 + lm * 16 + lh * 8;
        uint32_t d = sbase + (uint32_t)(s * STG_WORDS + lm * ASTR + lh * 8) * 4u;
        cp16(d, aH);
        cp16(d + 16, aH + 4);
        cp16(d + A_WORDS * 4, aL);
        cp16(d + A_WORDS * 4 + 16, aL + 4);
    };
    auto issueB = [&](int ch, int s) {
        const int k2g = ch * 16 + lk2;
        uint32_t dh = sbase + (uint32_t)(s * STG_WORDS + 2 * A_WORDS + lk2 * KSTR + lq * 8) * 4u;
        uint32_t dl = dh + B_WORDS * 4;
        if (KW == 1) {
            const uint32_t* rH = XhB + (size_t)k2g * T + tn0 + lq * 8;
            const uint32_t* rL = XlB + (size_t)k2g * T + tn0 + lq * 8;
            cp16(dh, rH); cp16(dh + 16, rH + 4);
            cp16(dl, rL); cp16(dl + 16, rL + 4);
        } else {
            const int c2 = k2g % Chalf;
            const int kk = k2g / Chalf;
            const int dt = kk - PL;
            const uint32_t* rH = XhB + (size_t)c2 * T;
            const uint32_t* rL = XlB + (size_t)c2 * T;
            const int tb = tn0 + lq * 8 + dt;
#pragma unroll
            for (int j = 0; j < 8; j++) {
                int t = tb + j;
                bool ok = (unsigned)t < (unsigned)T;
                int tc = ok ? t : 0;
                int sz = ok ? 4 : 0;
                cp4z(dh + j * 4, rH + tc, sz);
                cp4z(dl + j * 4, rL + tc, sz);
            }
        }
    };

    float acc[4][4][4];
#pragma unroll
    for (int i = 0; i < 4; i++)
#pragma unroll
        for (int j = 0; j < 4; j++)
#pragma unroll
            for (int r = 0; r < 4; r++) acc[i][j][r] = 0.f;

    issueA(0, 0); issueB(0, 0); cp_commit();

    for (int ch = 0; ch < chunks; ch++) {
        const int s = ch & 1;
        if (ch + 1 < chunks) {
            issueA(ch + 1, s ^ 1); issueB(ch + 1, s ^ 1); cp_commit();
            cp_wait<1>();
        } else {
            cp_wait<0>();
        }
        __syncthreads();

        const uint32_t aAh = sbase + (uint32_t)(s * STG_WORDS) * 4u;
        const uint32_t aAl = aAh + A_WORDS * 4u;
        const uint32_t* BhS = dsm + s * STG_WORDS + 2 * A_WORDS;
        const uint32_t* BlS = BhS + B_WORDS;

#pragma unroll
        for (int ks = 0; ks < 2; ks++) {
            const int k2a = ks * 8 + tig;
            const int k2b = ks * 8 + 4 + tig;
            uint32_t bfh[4][2], bfl[4][2];
#pragma unroll
            for (int nt = 0; nt < 4; nt++) {
                int n = nw * 32 + nt * 8 + gid;
                bfh[nt][0] = BhS[k2a * KSTR + n];
                bfh[nt][1] = BhS[k2b * KSTR + n];
                bfl[nt][0] = BlS[k2a * KSTR + n];
                bfl[nt][1] = BlS[k2b * KSTR + n];
            }
#pragma unroll
            for (int mt = 0; mt < 4; mt++) {
                uint32_t afh[4], afl[4];
                const uint32_t off = laneOff + (uint32_t)(mt * 16 * ASTR + ks * 8) * 4u;
                ldm4(afh, aAh + off);
                ldm4(afl, aAl + off);
#pragma unroll
                for (int nt = 0; nt < 4; nt++) {
                    mma_bf16(acc[mt][nt], afh, bfh[nt]);
                    mma_bf16(acc[mt][nt], afh, bfl[nt]);
                    mma_bf16(acc[mt][nt], afl, bfh[nt]);
                }
            }
        }
        __syncthreads();
    }

    // ---- epilogue ----
    const int ChalfO = Cout >> 1;
#pragma unroll
    for (int mt = 0; mt < 4; mt++) {
        int o0 = om + mw * 64 + mt * 16 + gid;
        float bb0 = bias[o0];
        float bb1 = bias[o0 + 8];
#pragma unroll
        for (int nt = 0; nt < 4; nt++) {
            int t0 = tn0 + nw * 32 + nt * 8 + 2 * tig;
            float v0 = acc[mt][nt][0] + bb0;
            float v1 = acc[mt][nt][1] + bb0;
            float v2 = acc[mt][nt][2] + bb1;
            float v3 = acc[mt][nt][3] + bb1;
            if (RELU) {
                v0 = fmaxf(v0, 0.f); v1 = fmaxf(v1, 0.f);
                v2 = fmaxf(v2, 0.f); v3 = fmaxf(v3, 0.f);
            }
            if (PACKOUT) {
                float q0 = __shfl_xor_sync(0xffffffffu, v0, 4);
                float q1 = __shfl_xor_sync(0xffffffffu, v1, 4);
                float q2 = __shfl_xor_sync(0xffffffffu, v2, 4);
                float q3 = __shfl_xor_sync(0xffffffffu, v3, 4);
                if ((gid & 1) == 0) {
                    size_t da = ((size_t)b * ChalfO + (o0 >> 1)) * T + t0;
                    size_t db = ((size_t)b * ChalfO + ((o0 + 8) >> 1)) * T + t0;
                    float h;
                    h = bf_hi_val(v0); float hq = bf_hi_val(q0);
                    poh[da]     = pack_bf2(h, hq);
                    pol[da]     = pack_bf2(v0 - h, q0 - hq);
                    h = bf_hi_val(v1); hq = bf_hi_val(q1);
                    poh[da + 1] = pack_bf2(h, hq);
                    pol[da + 1] = pack_bf2(v1 - h, q1 - hq);
                    h = bf_hi_val(v2); hq = bf_hi_val(q2);
                    poh[db]     = pack_bf2(h, hq);
                    pol[db]     = pack_bf2(v2 - h, q2 - hq);
                    h = bf_hi_val(v3); hq = bf_hi_val(q3);
                    poh[db + 1] = pack_bf2(h, hq);
                    pol[db + 1] = pack_bf2(v3 - h, q3 - hq);
                }
            } else {
                float m0 = 1.f, m1 = 1.f;
                if (DOMASK) {
                    m0 = mask[(size_t)b * T + t0];
                    m1 = mask[(size_t)b * T + t0 + 1];
                }
                size_t oi0 = ((size_t)b * Cout + o0)     * T + t0;
                size_t oi1 = ((size_t)b * Cout + o0 + 8) * T + t0;
                if (ADDSRC) {
                    float2 s0 = *(const float2*)(src + oi0);
                    float2 s1 = *(const float2*)(src + oi1);
                    v0 += s0.x; v1 += s0.y; v2 += s1.x; v3 += s1.y;
                }
                if (DOMASK) { v0 *= m0; v1 *= m1; v2 *= m0; v3 *= m1; }
                *(float2*)(Y + oi0) = make_float2(v0, v1);
                *(float2*)(Y + oi1) = make_float2(v2, v3);
            }
        }
    }
}

// ---------------- f0 prenet added in-place ----------------
__global__ void add_f0(const float* __restrict__ f0, const float* __restrict__ w,
                       const float* __restrict__ fb, float* __restrict__ y)
{
    int t = blockIdx.x * 256 + threadIdx.x;
    int c = blockIdx.y;
    int b = blockIdx.z;
    float fm1 = (t - 1 >= 0) ? f0[(size_t)b * T + t - 1] : 0.f;
    float fc0 = f0[(size_t)b * T + t];
    float fp1 = (t + 1 < T) ? f0[(size_t)b * T + t + 1] : 0.f;
    float v = w[c * 3 + 0] * fm1 + w[c * 3 + 1] * fc0 + w[c * 3 + 2] * fp1 + fb[c];
    y[((size_t)b * C + c) * T + t] += v;
}

// ---------------- fused residual-add + LayerNorm + packed split output ----------------
__global__ void add_ln_p(const float* __restrict__ x, const float* __restrict__ y,
                         const float* __restrict__ g, const float* __restrict__ be,
                         float* __restrict__ out,
                         uint32_t* __restrict__ ph, uint32_t* __restrict__ pl)
{
    __shared__ float red0[8][32];
    __shared__ float red1[8][32];
    __shared__ float smv[2][32];
    const int tx = threadIdx.x, ty = threadIdx.y;
    const int t = blockIdx.x * 32 + tx;
    const int b = blockIdx.y;
    const size_t base = (size_t)b * C * T + t;

    float s = 0.f, sq = 0.f;
    for (int c2 = ty; c2 < C / 2; c2 += 8) {
        size_t i0 = base + (size_t)(2 * c2) * T;
        float v0 = x[i0] + y[i0];
        float v1 = x[i0 + T] + y[i0 + T];
        s += v0 + v1; sq += v0 * v0 + v1 * v1;
    }
    red0[ty][tx] = s; red1[ty][tx] = sq;
    __syncthreads();
    if (ty == 0) {
#pragma unroll
        for (int i = 1; i < 8; i++) { s += red0[i][tx]; sq += red1[i][tx]; }
        float mean = s * (1.f / C);
        float var  = sq * (1.f / C) - mean * mean;
        smv[0][tx] = mean;
        smv[1][tx] = rsqrtf(var + 1e-5f);
    }
    __syncthreads();
    float mean = smv[0][tx], rstd = smv[1][tx];
    for (int c2 = ty; c2 < C / 2; c2 += 8) {
        size_t i0 = base + (size_t)(2 * c2) * T;
        float v0 = (x[i0]     + y[i0]     - mean) * rstd * g[2 * c2]     + be[2 * c2];
        float v1 = (x[i0 + T] + y[i0 + T] - mean) * rstd * g[2 * c2 + 1] + be[2 * c2 + 1];
        out[i0]     = v0;
        out[i0 + T] = v1;
        float h0 = bf_hi_val(v0), h1 = bf_hi_val(v1);
        size_t d = ((size_t)b * (C / 2) + c2) * T + t;
        ph[d] = pack_bf2(h0, h1);
        pl[d] = pack_bf2(v0 - h0, v1 - h1);
    }
}

// ---------------- fused causal flash attention, packed split output ----------------
static constexpr int FLASH_SMEM = (64 * 64 + 64 * 68 + 64 * 68) * 4;

__global__ __launch_bounds__(256) void flash_attn(
    const float* __restrict__ q, const float* __restrict__ k,
    const float* __restrict__ v,
    uint32_t* __restrict__ ph, uint32_t* __restrict__ pl)
{
    extern __shared__ float sm[];
    float* Qs = sm;
    float* Ks = sm + 64 * 64;
    float* Vt = Ks + 64 * 68;
    float* Ss = Ks;

    const int tid  = threadIdx.x;
    const int lane = tid & 31;
    const int warp = tid >> 5;
    const int mb   = blockIdx.x;
    const int m0   = mb * 64;
    const int bh   = blockIdx.y;
    const int b    = bh >> 3;
    const int h    = bh & 7;
    const size_t base = ((size_t)b * C + (size_t)h * DK) * T;
    const float* __restrict__ qp = q + base;
    const float* __restrict__ kp = k + base;
    const float* __restrict__ vp = v + base;

    for (int idx = tid; idx < 64 * 64; idx += 256) {
        int d = idx >> 6, tt = idx & 63;
        Qs[tt * 64 + d] = qp[(size_t)d * T + m0 + tt] * 0.125f;
    }

    float mI[8], lI[8], a0[8], a1[8];
#pragma unroll
    for (int r = 0; r < 8; r++) { mI[r] = -1e30f; lI[r] = 0.f; a0[r] = 0.f; a1[r] = 0.f; }
    const int r0 = warp * 8;

    for (int kbk = 0; kbk <= mb; kbk++) {
        const int kn0 = kbk * 64;
        __syncthreads();
        for (int idx = tid; idx < 64 * 64; idx += 256) {
            int d = idx >> 6, j = idx & 63;
            Ks[j * 68 + d] = kp[(size_t)d * T + kn0 + j];
            Vt[d * 68 + j] = vp[(size_t)d * T + kn0 + j];
        }
        __syncthreads();

        float sc0[8], sc1[8];
#pragma unroll
        for (int r = 0; r < 8; r++) {
            int rr = r0 + r;
            float s0 = 0.f, s1 = 0.f;
#pragma unroll
            for (int d = 0; d < 64; d += 4) {
                float4 q4 = *(const float4*)&Qs[rr * 64 + d];
                float4 ka = *(const float4*)&Ks[lane * 68 + d];
                float4 kb = *(const float4*)&Ks[(lane + 32) * 68 + d];
                s0 += q4.x * ka.x + q4.y * ka.y + q4.z * ka.z + q4.w * ka.w;
                s1 += q4.x * kb.x + q4.y * kb.y + q4.z * kb.z + q4.w * kb.w;
            }
            int tg = m0 + rr;
            if (kn0 + lane      > tg) s0 = -1e4f;
            if (kn0 + lane + 32 > tg) s1 = -1e4f;
            sc0[r] = s0; sc1[r] = s1;
        }
        __syncthreads();

#pragma unroll
        for (int r = 0; r < 8; r++) {
            int rr = r0 + r;
            float mx = fmaxf(sc0[r], sc1[r]);
#pragma unroll
            for (int off = 16; off; off >>= 1)
                mx = fmaxf(mx, __shfl_xor_sync(0xffffffffu, mx, off));
            float mnew = fmaxf(mI[r], mx);
            float p0 = __expf(sc0[r] - mnew);
            float p1 = __expf(sc1[r] - mnew);
            float ps = p0 + p1;
#pragma unroll
            for (int off = 16; off; off >>= 1)
                ps += __shfl_xor_sync(0xffffffffu, ps, off);
            float corr = __expf(mI[r] - mnew);
            lI[r] = lI[r] * corr + ps;
            mI[r] = mnew;
            a0[r] *= corr; a1[r] *= corr;
            Ss[rr * 68 + lane]      = p0;
            Ss[rr * 68 + lane + 32] = p1;
        }
        __syncwarp();

#pragma unroll
        for (int r = 0; r < 8; r++) {
            int rr = r0 + r;
            float acc0 = 0.f, acc1 = 0.f;
#pragma unroll
            for (int j = 0; j < 64; j += 4) {
                float4 p4 = *(const float4*)&Ss[rr * 68 + j];
                float4 va = *(const float4*)&Vt[lane * 68 + j];
                float4 vb = *(const float4*)&Vt[(lane + 32) * 68 + j];
                acc0 += p4.x * va.x + p4.y * va.y + p4.z * va.z + p4.w * va.w;
                acc1 += p4.x * vb.x + p4.y * vb.y + p4.z * vb.z + p4.w * vb.w;
            }
            a0[r] += acc0; a1[r] += acc1;
        }
    }

#pragma unroll
    for (int r = 0; r < 8; r++) {
        int rr = r0 + r;
        float inv = 1.f / lI[r];
        float ov0 = a0[r] * inv;
        float ov1 = a1[r] * inv;
        float p0 = __shfl_xor_sync(0xffffffffu, ov0, 1);
        float p1 = __shfl_xor_sync(0xffffffffu, ov1, 1);
        if ((lane & 1) == 0) {
            int c2a = (h * DK + lane) >> 1;
            int c2b = (h * DK + 32 + lane) >> 1;
            size_t da = ((size_t)b * (C / 2) + c2a) * T + m0 + rr;
            size_t db = ((size_t)b * (C / 2) + c2b) * T + m0 + rr;
            float h0 = bf_hi_val(ov0), h1 = bf_hi_val(p0);
            ph[da] = pack_bf2(h0, h1);
            pl[da] = pack_bf2(ov0 - h0, p0 - h1);
            float h2 = bf_hi_val(ov1), h3 = bf_hi_val(p1);
            ph[db] = pack_bf2(h2, h3);
            pl[db] = pack_bf2(ov1 - h2, p1 - h3);
        }
    }
}

// ---------------- final 1-channel projection ----------------
__global__ void proj_out(const float* __restrict__ x, const float* __restrict__ w,
                         const float* __restrict__ pb, const float* __restrict__ mask,
                         float* __restrict__ out)
{
    int t = blockIdx.x * 256 + threadIdx.x;
    int b = blockIdx.y;
    float s = pb[0];
    const float* xb = x + (size_t)b * C * T;
    for (int c = 0; c < C; c++)
        s += w[c] * xb[(size_t)c * T + t];
    out[(size_t)b * T + t] = s * mask[(size_t)b * T + t];
}

// ---------------- launch ----------------
extern "C" void kernel_launch(void* const* d_in, const int* in_sizes, int n_in,
                              void* d_out, int out_size)
{
    const float* x    = (const float*)d_in[0];
    const float* f0   = (const float*)d_in[1];
    const float* mask = (const float*)d_in[2];
    const float* spk  = (const float*)d_in[3];
    const float* prw  = (const float*)d_in[4];
    const float* prb  = (const float*)d_in[5];
    const float* f0w  = (const float*)d_in[6];
    const float* f0b  = (const float*)d_in[7];
    const float* cw   = (const float*)d_in[8];
    const float* cb   = (const float*)d_in[9];
    const float* pw   = (const float*)d_in[10];
    const float* pb   = (const float*)d_in[11];
    const float* qw   = (const float*)d_in[12];
    const float* qb   = (const float*)d_in[13];
    const float* kw   = (const float*)d_in[14];
    const float* kb   = (const float*)d_in[15];
    const float* vw   = (const float*)d_in[16];
    const float* vb   = (const float*)d_in[17];
    const float* ow   = (const float*)d_in[18];
    const float* ob   = (const float*)d_in[19];
    const float* ln0g = (const float*)d_in[20];
    const float* ln0b = (const float*)d_in[21];
    const float* ln1g = (const float*)d_in[22];
    const float* ln1b = (const float*)d_in[23];
    const float* f1w  = (const float*)d_in[24];
    const float* f1b  = (const float*)d_in[25];
    const float* f2w  = (const float*)d_in[26];
    const float* f2b  = (const float*)d_in[27];
    float* out = (float*)d_out;

    float *gx, *gy, *gq, *gk, *gv;
    uint32_t *wh, *wl, *ah, *al, *bh2, *bl2;
    cudaGetSymbolAddress((void**)&gx,  g_x);
    cudaGetSymbolAddress((void**)&gy,  g_y);
    cudaGetSymbolAddress((void**)&gq,  g_q);
    cudaGetSymbolAddress((void**)&gk,  g_k);
    cudaGetSymbolAddress((void**)&gv,  g_v);
    cudaGetSymbolAddress((void**)&wh,  g_wh);
    cudaGetSymbolAddress((void**)&wl,  g_wl);
    cudaGetSymbolAddress((void**)&ah,  g_ah);
    cudaGetSymbolAddress((void**)&al,  g_al);
    cudaGetSymbolAddress((void**)&bh2, g_bh);
    cudaGetSymbolAddress((void**)&bl2, g_bl);

    cudaFuncSetAttribute(flash_attn, cudaFuncAttributeMaxDynamicSharedMemorySize, FLASH_SMEM);
    cudaFuncSetAttribute(mma_gemm_p<1,0,false,false,true ,1,false>, cudaFuncAttributeMaxDynamicSharedMemorySize, GEMM_SMEM);
    cudaFuncSetAttribute(mma_gemm_p<3,1,false,true ,false,1,false>, cudaFuncAttributeMaxDynamicSharedMemorySize, GEMM_SMEM);
    cudaFuncSetAttribute(mma_gemm_p<1,0,false,false,false,3,false>, cudaFuncAttributeMaxDynamicSharedMemorySize, GEMM_SMEM);
    cudaFuncSetAttribute(mma_gemm_p<1,0,false,false,false,1,false>, cudaFuncAttributeMaxDynamicSharedMemorySize, GEMM_SMEM);
    cudaFuncSetAttribute(mma_gemm_p<3,2,true ,false,false,1,true >, cudaFuncAttributeMaxDynamicSharedMemorySize, GEMM_SMEM);
    cudaFuncSetAttribute(mma_gemm_p<3,2,false,true ,false,1,false>, cudaFuncAttributeMaxDynamicSharedMemorySize, GEMM_SMEM);

    // ---- pack all weights ----
    pack_w<<<dim3(65536 / 256, 1), 256>>>(cw, 0, OFF_COND, 0, S, 1, 8);
    pack_w<<<dim3(393216 / 256, 1), 256>>>(prw, 0, OFF_PRE, 0, C, 3, 48);
    pack_w<<<dim3(131072 / 256, L), 256>>>(qw, (size_t)C * C, OFF_QKV + 0,      QKV_LSTR, C, 1, 16);
    pack_w<<<dim3(131072 / 256, L), 256>>>(kw, (size_t)C * C, OFF_QKV + 131072, QKV_LSTR, C, 1, 16);
    pack_w<<<dim3(131072 / 256, L), 256>>>(vw, (size_t)C * C, OFF_QKV + 262144, QKV_LSTR, C, 1, 16);
    pack_w<<<dim3(131072 / 256, L), 256>>>(ow, (size_t)C * C, OFF_OUT, OUT_LSTR, C, 1, 16);
    pack_w<<<dim3(1572864 / 256, L), 256>>>(f1w, (size_t)FC * C * 3, OFF_F1, F1_LSTR, C,  3, 48);
    pack_w<<<dim3(1572864 / 256, L), 256>>>(f2w, (size_t)C * FC * 3, OFF_F2, F2_LSTR, FC, 3, 192);

    // ---- prep ----
    split_act<<<dim3(T / 256, S / 2, B), 256>>>(spk, ah, al, S / 2);
    mma_gemm_p<1, 0, false, false, true, 1, false><<<dim3(T / 128, 4, B), 256, GEMM_SMEM>>>(
        ah, al, wh + OFF_COND, wl + OFF_COND, cb, cb, cb, nullptr, x,
        gy, gy, gy, nullptr, nullptr, S, C);
    add_f0<<<dim3(T / 256, C, B), 256>>>(f0, f0w, f0b, gy);
    split_act<<<dim3(T / 256, C / 2, B), 256>>>(gy, ah, al, C / 2);
    mma_gemm_p<3, 1, false, true, false, 1, false><<<dim3(T / 128, 4, B), 256, GEMM_SMEM>>>(
        ah, al, wh + OFF_PRE, wl + OFF_PRE, prb, prb, prb, mask, nullptr,
        gx, gx, gx, nullptr, nullptr, C, C);
    split_act<<<dim3(T / 256, C / 2, B), 256>>>(gx, ah, al, C / 2);

    for (int l = 0; l < L; l++) {
        mma_gemm_p<1, 0, false, false, false, 3, false><<<dim3(T / 128, 12, B), 256, GEMM_SMEM>>>(
            ah, al, wh + OFF_QKV + (size_t)l * QKV_LSTR, wl + OFF_QKV + (size_t)l * QKV_LSTR,
            qb + l * C, kb + l * C, vb + l * C, nullptr, nullptr,
            gq, gk, gv, nullptr, nullptr, C, C);

        flash_attn<<<dim3(T / 64, B * H), 256, FLASH_SMEM>>>(gq, gk, gv, bh2, bl2);

        mma_gemm_p<1, 0, false, false, false, 1, false><<<dim3(T / 128, 4, B), 256, GEMM_SMEM>>>(
            bh2, bl2, wh + OFF_OUT + (size_t)l * OUT_LSTR, wl + OFF_OUT + (size_t)l * OUT_LSTR,
            ob + l * C, nullptr, nullptr, nullptr, nullptr,
            gy, nullptr, nullptr, nullptr, nullptr, C, C);

        add_ln_p<<<dim3(T / 32, B), dim3(32, 8)>>>(gx, gy, ln0g + l * C, ln0b + l * C, gx, ah, al);

        mma_gemm_p<3, 2, true, false, false, 1, true><<<dim3(T / 128, FC / 128, B), 256, GEMM_SMEM>>>(
            ah, al, wh + OFF_F1 + (size_t)l * F1_LSTR, wl + OFF_F1 + (size_t)l * F1_LSTR,
            f1b + l * FC, nullptr, nullptr, nullptr, nullptr,
            nullptr, nullptr, nullptr, bh2, bl2, C, FC);

        mma_gemm_p<3, 2, false, true, false, 1, false><<<dim3(T / 128, 4, B), 256, GEMM_SMEM>>>(
            bh2, bl2, wh + OFF_F2 + (size_t)l * F2_LSTR, wl + OFF_F2 + (size_t)l * F2_LSTR,
            f2b + l * C, nullptr, nullptr, mask, nullptr,
            gy, nullptr, nullptr, nullptr, nullptr, FC, C);

        add_ln_p<<<dim3(T / 32, B), dim3(32, 8)>>>(gx, gy, ln1g + l * C, ln1b + l * C, gx, ah, al);
    }

    proj_out<<<dim3(T / 256, B), 256>>>(gx, pw, pb, mask, out);
}

// round 8
// speedup vs baseline: 1.3008x; 1.1097x over previous
#include <cuda_runtime.h>
#include <cuda_bf16.h>
#include <cstdint>
#include <cstddef>

// ---------------- problem constants ----------------
static constexpr int B  = 4;
static constexpr int C  = 512;
static constexpr int T  = 2048;
static constexpr int H  = 8;
static constexpr int FC = 2048;
static constexpr int L  = 6;
static constexpr int S  = 256;
static constexpr int DK = 64;

// ---------------- device scratch ----------------
__device__ float g_x[B * C * T];
__device__ float g_y[B * C * T];

// packed split weights (hi/lo bf16x2), pretiled [omBlk][chunk][m(128)][k2(16)]
static constexpr size_t OFF_COND = 0;
static constexpr size_t OFF_PRE  = 65536;
static constexpr size_t OFF_QKV  = 458752;
static constexpr size_t QKV_LSTR = 393216;
static constexpr size_t OFF_OUT  = 2818048;
static constexpr size_t OUT_LSTR = 131072;
static constexpr size_t OFF_F1   = 3604480;
static constexpr size_t F1_LSTR  = 1572864;
static constexpr size_t OFF_F2   = 13041664;
static constexpr size_t F2_LSTR  = 1572864;
static constexpr size_t W_TOTAL  = 22478848;

__device__ uint32_t g_wh[W_TOTAL];
__device__ uint32_t g_wl[W_TOTAL];
// packed split activations, ping-pong buffers
__device__ uint32_t g_ah[(size_t)B * (FC / 2) * T];
__device__ uint32_t g_al[(size_t)B * (FC / 2) * T];
__device__ uint32_t g_bh[(size_t)B * (FC / 2) * T];
__device__ uint32_t g_bl[(size_t)B * (FC / 2) * T];

// region offsets inside g_bh/g_bl (words): q, k, vT, attn (2M each)
static constexpr size_t RG_Q = 0;
static constexpr size_t RG_K = 2097152;
static constexpr size_t RG_V = 4194304;
static constexpr size_t RG_A = 6291456;

// ---------------- helpers ----------------
__device__ __forceinline__ uint32_t pack_bf2(float a, float b) {
    uint32_t r;
    asm("cvt.rn.bf16x2.f32 %0, %1, %2;" : "=r"(r) : "f"(b), "f"(a));
    return r;
}
__device__ __forceinline__ float bf_hi_val(float v) {
    __nv_bfloat16 h = __float2bfloat16_rn(v);
    return __bfloat162float(h);
}
__device__ __forceinline__ void mma_bf16(float* d, const uint32_t* a, const uint32_t* b) {
    asm volatile("mma.sync.aligned.m16n8k16.row.col.f32.bf16.bf16.f32 "
        "{%0,%1,%2,%3}, {%4,%5,%6,%7}, {%8,%9}, {%0,%1,%2,%3};"
        : "+f"(d[0]), "+f"(d[1]), "+f"(d[2]), "+f"(d[3])
        : "r"(a[0]), "r"(a[1]), "r"(a[2]), "r"(a[3]), "r"(b[0]), "r"(b[1]));
}
__device__ __forceinline__ uint32_t smem_u32(const void* p) {
    uint32_t a;
    asm("{ .reg .u64 t; cvta.to.shared.u64 t, %1; cvt.u32.u64 %0, t; }" : "=r"(a) : "l"(p));
    return a;
}
__device__ __forceinline__ void ldm4(uint32_t* r, uint32_t addr) {
    asm volatile("ldmatrix.sync.aligned.m8n8.x4.shared.b16 {%0,%1,%2,%3}, [%4];"
        : "=r"(r[0]), "=r"(r[1]), "=r"(r[2]), "=r"(r[3]) : "r"(addr));
}
__device__ __forceinline__ void cp16(uint32_t dst, const void* src) {
    asm volatile("cp.async.cg.shared.global [%0], [%1], 16;" :: "r"(dst), "l"(src));
}
__device__ __forceinline__ void cp4z(uint32_t dst, const void* src, int srcsz) {
    asm volatile("cp.async.ca.shared.global [%0], [%1], 4, %2;"
                 :: "r"(dst), "l"(src), "r"(srcsz));
}
__device__ __forceinline__ void cp_commit() {
    asm volatile("cp.async.commit_group;" ::: "memory");
}
template <int N>
__device__ __forceinline__ void cp_wait() {
    asm volatile("cp.async.wait_group %0;" :: "n"(N) : "memory");
}

// ---------------- weight packing ----------------
__global__ void pack_w(const float* __restrict__ src, size_t src_lstride,
                       size_t dst_base, size_t dst_lstride,
                       int Cin, int KW, int chunks)
{
    const int l = blockIdx.y;
    const int w = blockIdx.x * 256 + threadIdx.x;
    const int per_blk = chunks * 2048;
    const int omBlk = w / per_blk;
    const int r  = w % per_blk;
    const int ch = r / 2048, r2 = r % 2048;
    const int m  = r2 >> 4;
    const int k2 = ch * 16 + (r2 & 15);
    int ka, kb;
    if (KW == 1) { ka = 2 * k2; kb = ka + 1; }
    else { int half = Cin >> 1; int c2 = k2 % half, kk = k2 / half;
           ka = (2 * c2) * KW + kk; kb = ka + KW; }
    const float* s = src + (size_t)l * src_lstride + (size_t)(omBlk * 128 + m) * Cin * KW;
    float va = s[ka], vb = s[kb];
    float ha = bf_hi_val(va), hb = bf_hi_val(vb);
    size_t d = dst_base + (size_t)l * dst_lstride + w;
    g_wh[d] = pack_bf2(ha, hb);
    g_wl[d] = pack_bf2(va - ha, vb - hb);
}

// ---------------- activation split/pack (prep only) ----------------
__global__ void split_act(const float* __restrict__ X, uint32_t* __restrict__ Xh,
                          uint32_t* __restrict__ Xl, int Chalf)
{
    const int t  = blockIdx.x * 256 + threadIdx.x;
    const int c2 = blockIdx.y;
    const int b  = blockIdx.z;
    const float* x0 = X + ((size_t)b * 2 * Chalf + 2 * c2) * T;
    float va = x0[t], vb = x0[T + t];
    float ha = bf_hi_val(va), hb = bf_hi_val(vb);
    size_t d = ((size_t)b * Chalf + c2) * T + t;
    Xh[d] = pack_bf2(ha, hb);
    Xl[d] = pack_bf2(va - ha, vb - hb);
}

// ================= cp.async pipelined bf16x2-split mma.sync conv-GEMM =================
static constexpr int ASTR = 20;
static constexpr int KSTR = 136;
static constexpr int A_WORDS = 128 * ASTR;
static constexpr int B_WORDS = 16 * KSTR;
static constexpr int STG_WORDS = 2 * A_WORDS + 2 * B_WORDS;
static constexpr int GEMM_SMEM = 2 * STG_WORDS * 4;

// OMODE: 0 = float out, 1 = channel-pair packed out, 2 = QKV (sel0/1 packout, sel2 vpackt)
template <int KW, int PL, bool RELU, bool DOMASK, bool ADDSRC, int NOUT, int OMODE>
__global__ __launch_bounds__(256, 2) void mma_gemm_p(
    const uint32_t* __restrict__ Xh, const uint32_t* __restrict__ Xl,
    const uint32_t* __restrict__ Wh, const uint32_t* __restrict__ Wl,
    const float* __restrict__ b0, const float* __restrict__ b1, const float* __restrict__ b2,
    const float* __restrict__ mask, const float* __restrict__ src,
    float* __restrict__ Y0,
    uint32_t* __restrict__ poh,  uint32_t* __restrict__ pol,
    uint32_t* __restrict__ poh2, uint32_t* __restrict__ pol2,
    uint32_t* __restrict__ poh3, uint32_t* __restrict__ pol3,
    float* __restrict__ Y1, float* __restrict__ Y2,
    int Cin, int Cout)
{
    extern __shared__ uint32_t dsm[];
    const uint32_t sbase = smem_u32(dsm);

    const int tid  = threadIdx.x;
    const int lane = tid & 31;
    const int wid  = tid >> 5;
    const int mw   = wid & 1;
    const int nw   = wid >> 1;
    const int gid  = lane >> 2;
    const int tig  = lane & 3;

    const int b   = blockIdx.z;
    const int tn0 = blockIdx.x * 128;
    int sel, om;
    if (NOUT == 3) { sel = blockIdx.y >> 2; om = (blockIdx.y & 3) * 128; }
    else           { sel = 0;               om = blockIdx.y * 128; }
    const float* bias = (NOUT == 3) ? (sel == 0 ? b0 : sel == 1 ? b1 : b2) : b0;
    float* Y          = (NOUT == 3) ? (sel == 0 ? Y0 : sel == 1 ? Y1 : Y2) : Y0;

    const int Chalf  = Cin >> 1;
    const int chunks = (Cin * KW) >> 5;
    const uint32_t* wtH = Wh + (size_t)blockIdx.y * chunks * 2048;
    const uint32_t* wtL = Wl + (size_t)blockIdx.y * chunks * 2048;
    const uint32_t* XhB = Xh + (size_t)b * Chalf * T;
    const uint32_t* XlB = Xl + (size_t)b * Chalf * T;

    const int lm  = tid >> 1;
    const int lh  = tid & 1;
    const int lk2 = tid >> 4;
    const int lq  = tid & 15;

    const int qq   = lane >> 3;
    const int rrow = lane & 7;
    const uint32_t laneOff = ((uint32_t)((mw * 64 + (qq & 1) * 8 + rrow) * ASTR
                             + (qq >> 1) * 4)) * 4u;

    auto issueA = [&](int ch, int s) {
        const uint32_t* aH = wtH + ch * 2048 + lm * 16 + lh * 8;
        const uint32_t* aL = wtL + ch * 2048 + lm * 16 + lh * 8;
        uint32_t d = sbase + (uint32_t)(s * STG_WORDS + lm * ASTR + lh * 8) * 4u;
        cp16(d, aH);
        cp16(d + 16, aH + 4);
        cp16(d + A_WORDS * 4, aL);
        cp16(d + A_WORDS * 4 + 16, aL + 4);
    };
    auto issueB = [&](int ch, int s) {
        const int k2g = ch * 16 + lk2;
        uint32_t dh = sbase + (uint32_t)(s * STG_WORDS + 2 * A_WORDS + lk2 * KSTR + lq * 8) * 4u;
        uint32_t dl = dh + B_WORDS * 4;
        if (KW == 1) {
            const uint32_t* rH = XhB + (size_t)k2g * T + tn0 + lq * 8;
            const uint32_t* rL = XlB + (size_t)k2g * T + tn0 + lq * 8;
            cp16(dh, rH); cp16(dh + 16, rH + 4);
            cp16(dl, rL); cp16(dl + 16, rL + 4);
        } else {
            const int c2 = k2g % Chalf;
            const int kk = k2g / Chalf;
            const int dt = kk - PL;
            const uint32_t* rH = XhB + (size_t)c2 * T;
            const uint32_t* rL = XlB + (size_t)c2 * T;
            const int tb = tn0 + lq * 8 + dt;
#pragma unroll
            for (int j = 0; j < 8; j++) {
                int t = tb + j;
                bool ok = (unsigned)t < (unsigned)T;
                int tc = ok ? t : 0;
                int sz = ok ? 4 : 0;
                cp4z(dh + j * 4, rH + tc, sz);
                cp4z(dl + j * 4, rL + tc, sz);
            }
        }
    };

    float acc[4][4][4];
#pragma unroll
    for (int i = 0; i < 4; i++)
#pragma unroll
        for (int j = 0; j < 4; j++)
#pragma unroll
            for (int r = 0; r < 4; r++) acc[i][j][r] = 0.f;

    issueA(0, 0); issueB(0, 0); cp_commit();

    for (int ch = 0; ch < chunks; ch++) {
        const int s = ch & 1;
        if (ch + 1 < chunks) {
            issueA(ch + 1, s ^ 1); issueB(ch + 1, s ^ 1); cp_commit();
            cp_wait<1>();
        } else {
            cp_wait<0>();
        }
        __syncthreads();

        const uint32_t aAh = sbase + (uint32_t)(s * STG_WORDS) * 4u;
        const uint32_t aAl = aAh + A_WORDS * 4u;
        const uint32_t* BhS = dsm + s * STG_WORDS + 2 * A_WORDS;
        const uint32_t* BlS = BhS + B_WORDS;

#pragma unroll
        for (int ks = 0; ks < 2; ks++) {
            const int k2a = ks * 8 + tig;
            const int k2b = ks * 8 + 4 + tig;
            uint32_t bfh[4][2], bfl[4][2];
#pragma unroll
            for (int nt = 0; nt < 4; nt++) {
                int n = nw * 32 + nt * 8 + gid;
                bfh[nt][0] = BhS[k2a * KSTR + n];
                bfh[nt][1] = BhS[k2b * KSTR + n];
                bfl[nt][0] = BlS[k2a * KSTR + n];
                bfl[nt][1] = BlS[k2b * KSTR + n];
            }
#pragma unroll
            for (int mt = 0; mt < 4; mt++) {
                uint32_t afh[4], afl[4];
                const uint32_t off = laneOff + (uint32_t)(mt * 16 * ASTR + ks * 8) * 4u;
                ldm4(afh, aAh + off);
                ldm4(afl, aAl + off);
#pragma unroll
                for (int nt = 0; nt < 4; nt++) {
                    mma_bf16(acc[mt][nt], afh, bfh[nt]);
                    mma_bf16(acc[mt][nt], afh, bfl[nt]);
                    mma_bf16(acc[mt][nt], afl, bfh[nt]);
                }
            }
        }
        __syncthreads();
    }

    // ---- epilogue ----
    const int ChalfO = Cout >> 1;
    uint32_t* th = poh; uint32_t* tl = pol;
    if (OMODE == 2 && sel == 1) { th = poh2; tl = pol2; }
#pragma unroll
    for (int mt = 0; mt < 4; mt++) {
        int o0 = om + mw * 64 + mt * 16 + gid;
        float bb0 = bias[o0];
        float bb1 = bias[o0 + 8];
#pragma unroll
        for (int nt = 0; nt < 4; nt++) {
            int t0 = tn0 + nw * 32 + nt * 8 + 2 * tig;
            float v0 = acc[mt][nt][0] + bb0;
            float v1 = acc[mt][nt][1] + bb0;
            float v2 = acc[mt][nt][2] + bb1;
            float v3 = acc[mt][nt][3] + bb1;
            if (RELU) {
                v0 = fmaxf(v0, 0.f); v1 = fmaxf(v1, 0.f);
                v2 = fmaxf(v2, 0.f); v3 = fmaxf(v3, 0.f);
            }
            if (OMODE == 2 && sel == 2) {
                // V: time-pair packed [c][t2]
                size_t ia = ((size_t)b * Cout + o0)     * (T / 2) + (t0 >> 1);
                size_t ib = ((size_t)b * Cout + o0 + 8) * (T / 2) + (t0 >> 1);
                float h0 = bf_hi_val(v0), h1 = bf_hi_val(v1);
                poh3[ia] = pack_bf2(h0, h1);
                pol3[ia] = pack_bf2(v0 - h0, v1 - h1);
                h0 = bf_hi_val(v2); h1 = bf_hi_val(v3);
                poh3[ib] = pack_bf2(h0, h1);
                pol3[ib] = pack_bf2(v2 - h0, v3 - h1);
            } else if (OMODE == 1 || OMODE == 2) {
                float q0 = __shfl_xor_sync(0xffffffffu, v0, 4);
                float q1 = __shfl_xor_sync(0xffffffffu, v1, 4);
                float q2 = __shfl_xor_sync(0xffffffffu, v2, 4);
                float q3 = __shfl_xor_sync(0xffffffffu, v3, 4);
                if ((gid & 1) == 0) {
                    size_t da = ((size_t)b * ChalfO + (o0 >> 1)) * T + t0;
                    size_t db = ((size_t)b * ChalfO + ((o0 + 8) >> 1)) * T + t0;
                    float h;
                    h = bf_hi_val(v0); float hq = bf_hi_val(q0);
                    th[da]     = pack_bf2(h, hq);
                    tl[da]     = pack_bf2(v0 - h, q0 - hq);
                    h = bf_hi_val(v1); hq = bf_hi_val(q1);
                    th[da + 1] = pack_bf2(h, hq);
                    tl[da + 1] = pack_bf2(v1 - h, q1 - hq);
                    h = bf_hi_val(v2); hq = bf_hi_val(q2);
                    th[db]     = pack_bf2(h, hq);
                    tl[db]     = pack_bf2(v2 - h, q2 - hq);
                    h = bf_hi_val(v3); hq = bf_hi_val(q3);
                    th[db + 1] = pack_bf2(h, hq);
                    tl[db + 1] = pack_bf2(v3 - h, q3 - hq);
                }
            } else {
                float m0v = 1.f, m1v = 1.f;
                if (DOMASK) {
                    m0v = mask[(size_t)b * T + t0];
                    m1v = mask[(size_t)b * T + t0 + 1];
                }
                size_t oi0 = ((size_t)b * Cout + o0)     * T + t0;
                size_t oi1 = ((size_t)b * Cout + o0 + 8) * T + t0;
                if (ADDSRC) {
                    float2 s0 = *(const float2*)(src + oi0);
                    float2 s1 = *(const float2*)(src + oi1);
                    v0 += s0.x; v1 += s0.y; v2 += s1.x; v3 += s1.y;
                }
                if (DOMASK) { v0 *= m0v; v1 *= m1v; v2 *= m0v; v3 *= m1v; }
                *(float2*)(Y + oi0) = make_float2(v0, v1);
                *(float2*)(Y + oi1) = make_float2(v2, v3);
            }
        }
    }
}

// ---------------- f0 prenet added in-place ----------------
__global__ void add_f0(const float* __restrict__ f0, const float* __restrict__ w,
                       const float* __restrict__ fb, float* __restrict__ y)
{
    int t = blockIdx.x * 256 + threadIdx.x;
    int c = blockIdx.y;
    int b = blockIdx.z;
    float fm1 = (t - 1 >= 0) ? f0[(size_t)b * T + t - 1] : 0.f;
    float fc0 = f0[(size_t)b * T + t];
    float fp1 = (t + 1 < T) ? f0[(size_t)b * T + t + 1] : 0.f;
    float v = w[c * 3 + 0] * fm1 + w[c * 3 + 1] * fc0 + w[c * 3 + 2] * fp1 + fb[c];
    y[((size_t)b * C + c) * T + t] += v;
}

// ---------------- fused residual-add + LayerNorm + packed split output ----------------
__global__ void add_ln_p(const float* __restrict__ x, const float* __restrict__ y,
                         const float* __restrict__ g, const float* __restrict__ be,
                         float* __restrict__ out,
                         uint32_t* __restrict__ ph, uint32_t* __restrict__ pl)
{
    __shared__ float red0[8][32];
    __shared__ float red1[8][32];
    __shared__ float smv[2][32];
    const int tx = threadIdx.x, ty = threadIdx.y;
    const int t = blockIdx.x * 32 + tx;
    const int b = blockIdx.y;
    const size_t base = (size_t)b * C * T + t;

    float s = 0.f, sq = 0.f;
    for (int c2 = ty; c2 < C / 2; c2 += 8) {
        size_t i0 = base + (size_t)(2 * c2) * T;
        float v0 = x[i0] + y[i0];
        float v1 = x[i0 + T] + y[i0 + T];
        s += v0 + v1; sq += v0 * v0 + v1 * v1;
    }
    red0[ty][tx] = s; red1[ty][tx] = sq;
    __syncthreads();
    if (ty == 0) {
#pragma unroll
        for (int i = 1; i < 8; i++) { s += red0[i][tx]; sq += red1[i][tx]; }
        float mean = s * (1.f / C);
        float var  = sq * (1.f / C) - mean * mean;
        smv[0][tx] = mean;
        smv[1][tx] = rsqrtf(var + 1e-5f);
    }
    __syncthreads();
    float mean = smv[0][tx], rstd = smv[1][tx];
    for (int c2 = ty; c2 < C / 2; c2 += 8) {
        size_t i0 = base + (size_t)(2 * c2) * T;
        float v0 = (x[i0]     + y[i0]     - mean) * rstd * g[2 * c2]     + be[2 * c2];
        float v1 = (x[i0 + T] + y[i0 + T] - mean) * rstd * g[2 * c2 + 1] + be[2 * c2 + 1];
        out[i0]     = v0;
        out[i0 + T] = v1;
        float h0 = bf_hi_val(v0), h1 = bf_hi_val(v1);
        size_t d = ((size_t)b * (C / 2) + c2) * T + t;
        ph[d] = pack_bf2(h0, h1);
        pl[d] = pack_bf2(v0 - h0, v1 - h1);
    }
}

// ================= tensor-core causal flash attention =================
// smem word offsets
static constexpr int FQH = 0;            // [k2dk=32][72]
static constexpr int FQL = 2304;
static constexpr int FKH0 = 4608;        // 2 stages x (Kh,Kl) each 2304
static constexpr int FVH0 = 13824;       // 2 stages x (Vh,Vl) each 2304 ([d=64][36])
static constexpr int FSS  = 23040;       // float S [q=64][68]
static constexpr int FPH  = 27392;       // P packed [k2key=32][72]
static constexpr int FPL  = 29696;
static constexpr int FCORR = 32000;      // float[64]
static constexpr int FMST  = 32064;
static constexpr int FLST  = 32128;
static constexpr int FLASH2_WORDS = 32192;
static constexpr int FLASH2_SMEM = FLASH2_WORDS * 4;   // 128768 B

__global__ __launch_bounds__(256, 1) void flash_mma(
    const uint32_t* __restrict__ qh, const uint32_t* __restrict__ ql,
    const uint32_t* __restrict__ kh, const uint32_t* __restrict__ kl,
    const uint32_t* __restrict__ vh, const uint32_t* __restrict__ vl,
    uint32_t* __restrict__ oh, uint32_t* __restrict__ ol)
{
    extern __shared__ uint32_t fs[];
    float* fsf = (float*)fs;
    const uint32_t sb = smem_u32(fs);

    const int tid  = threadIdx.x;
    const int lane = tid & 31;
    const int wid  = tid >> 5;
    const int gid  = lane >> 2;
    const int tig  = lane & 3;
    const int wm   = wid & 3;            // 4 m-warps
    const int wn   = wid >> 2;           // 2 n-warps
    const int mbase = wm * 16;
    const int nbase = wn * 32;

    const int mb = (int)gridDim.x - 1 - (int)blockIdx.x;   // big tiles first
    const int m0 = mb * 64;
    const int bhh = blockIdx.y;
    const int b = bhh >> 3;
    const int h = bhh & 7;

    const uint32_t* qhB = qh + ((size_t)b * (C / 2) + h * 32) * T + m0;
    const uint32_t* qlB = ql + ((size_t)b * (C / 2) + h * 32) * T + m0;
    const uint32_t* khB = kh + ((size_t)b * (C / 2) + h * 32) * T;
    const uint32_t* klB = kl + ((size_t)b * (C / 2) + h * 32) * T;
    const uint32_t* vhB = vh + ((size_t)b * C + h * 64) * (T / 2);
    const uint32_t* vlB = vl + ((size_t)b * C + h * 64) * (T / 2);

    if (tid < 64) { fsf[FMST + tid] = -1e30f; fsf[FLST + tid] = 0.f; }

    // Q load (once): 32 rows x 16 chunks x {h,l}
    {
        int selq = tid >> 7, r = tid & 127, k2 = r >> 2, cq = (r & 3) * 4;
        const uint32_t* src = (selq ? qlB : qhB) + (size_t)k2 * T;
        uint32_t dst = sb + (uint32_t)((selq ? FQL : FQH) + k2 * 72) * 4u;
#pragma unroll
        for (int i = 0; i < 4; i++) cp16(dst + (cq + i) * 16, src + (cq + i) * 4);
    }
    auto loadKV = [&](int kbk, int s) {
        const int kn0 = kbk * 64;
        {
            int selq = tid >> 7, r = tid & 127, k2 = r >> 2, cq = (r & 3) * 4;
            const uint32_t* src = (selq ? klB : khB) + (size_t)k2 * T + kn0;
            uint32_t dst = sb + (uint32_t)(FKH0 + s * 4608 + selq * 2304 + k2 * 72) * 4u;
#pragma unroll
            for (int i = 0; i < 4; i++) cp16(dst + (cq + i) * 16, src + (cq + i) * 4);
        }
        {
            int selq = tid >> 7, r = tid & 127, d = r >> 1, cq = (r & 1) * 4;
            const uint32_t* src = (selq ? vlB : vhB) + (size_t)d * (T / 2) + (kn0 >> 1);
            uint32_t dst = sb + (uint32_t)(FVH0 + s * 4608 + selq * 2304 + d * 36) * 4u;
#pragma unroll
            for (int i = 0; i < 4; i++) cp16(dst + (cq + i) * 16, src + (cq + i) * 4);
        }
    };
    loadKV(0, 0); cp_commit();

    float oacc[4][4];
#pragma unroll
    for (int i = 0; i < 4; i++)
#pragma unroll
        for (int j = 0; j < 4; j++) oacc[i][j] = 0.f;

    for (int kbk = 0; kbk <= mb; kbk++) {
        const int s = kbk & 1;
        const int kn0 = kbk * 64;
        cp_wait<0>();
        __syncthreads();
        if (kbk < mb) { loadKV(kbk + 1, s ^ 1); cp_commit(); }

        const uint32_t* Qh_ = fs + FQH;
        const uint32_t* Ql_ = fs + FQL;
        const uint32_t* Kh_ = fs + FKH0 + s * 4608;
        const uint32_t* Kl_ = Kh_ + 2304;
        const uint32_t* Vh_ = fs + FVH0 + s * 4608;
        const uint32_t* Vl_ = Vh_ + 2304;

        // ---- QK MMA: S[q][key] ----
        float sacc[4][4];
#pragma unroll
        for (int i = 0; i < 4; i++)
#pragma unroll
            for (int j = 0; j < 4; j++) sacc[i][j] = 0.f;

#pragma unroll
        for (int kt = 0; kt < 4; kt++) {
            const int k2a = kt * 8 + tig;
            const int k2b = k2a + 4;
            const int mq = mbase + gid;
            uint32_t aqh[4] = { Qh_[k2a * 72 + mq], Qh_[k2a * 72 + mq + 8],
                                Qh_[k2b * 72 + mq], Qh_[k2b * 72 + mq + 8] };
            uint32_t aql[4] = { Ql_[k2a * 72 + mq], Ql_[k2a * 72 + mq + 8],
                                Ql_[k2b * 72 + mq], Ql_[k2b * 72 + mq + 8] };
#pragma unroll
            for (int nt = 0; nt < 4; nt++) {
                int n = nbase + nt * 8 + gid;
                uint32_t bkh[2] = { Kh_[k2a * 72 + n], Kh_[k2b * 72 + n] };
                uint32_t bkl[2] = { Kl_[k2a * 72 + n], Kl_[k2b * 72 + n] };
                mma_bf16(sacc[nt], aqh, bkh);
                mma_bf16(sacc[nt], aqh, bkl);
                mma_bf16(sacc[nt], aql, bkh);
            }
        }
        // store S to smem
#pragma unroll
        for (int nt = 0; nt < 4; nt++) {
            int col = nbase + nt * 8 + 2 * tig;
            int r0 = mbase + gid;
            *(float2*)&fsf[FSS + r0 * 68 + col]       = make_float2(sacc[nt][0], sacc[nt][1]);
            *(float2*)&fsf[FSS + (r0 + 8) * 68 + col] = make_float2(sacc[nt][2], sacc[nt][3]);
        }
        __syncthreads();

        // ---- softmax (8 queries per warp) ----
#pragma unroll
        for (int r = 0; r < 8; r++) {
            int q = wid * 8 + r;
            int tq = m0 + q;
            float s0 = fsf[FSS + q * 68 + lane] * 0.125f;
            float s1 = fsf[FSS + q * 68 + lane + 32] * 0.125f;
            if (kn0 + lane      > tq) s0 = -1e4f;
            if (kn0 + lane + 32 > tq) s1 = -1e4f;
            float mx = fmaxf(s0, s1);
#pragma unroll
            for (int off = 16; off; off >>= 1)
                mx = fmaxf(mx, __shfl_xor_sync(0xffffffffu, mx, off));
            float mold = fsf[FMST + q];
            float mnew = fmaxf(mold, mx);
            float p0 = __expf(s0 - mnew);
            float p1 = __expf(s1 - mnew);
            float ps = p0 + p1;
#pragma unroll
            for (int off = 16; off; off >>= 1)
                ps += __shfl_xor_sync(0xffffffffu, ps, off);
            float corrv = __expf(mold - mnew);
            if (lane == 0) {
                fsf[FMST + q]  = mnew;
                fsf[FLST + q]  = fsf[FLST + q] * corrv + ps;
                fsf[FCORR + q] = corrv;
            }
            float p0p = __shfl_xor_sync(0xffffffffu, p0, 1);
            float p1p = __shfl_xor_sync(0xffffffffu, p1, 1);
            if ((lane & 1) == 0) {
                int k2 = lane >> 1;
                float h0 = bf_hi_val(p0), h1 = bf_hi_val(p0p);
                fs[FPH + k2 * 72 + q] = pack_bf2(h0, h1);
                fs[FPL + k2 * 72 + q] = pack_bf2(p0 - h0, p0p - h1);
                h0 = bf_hi_val(p1); h1 = bf_hi_val(p1p);
                fs[FPH + (k2 + 16) * 72 + q] = pack_bf2(h0, h1);
                fs[FPL + (k2 + 16) * 72 + q] = pack_bf2(p1 - h0, p1p - h1);
            }
        }
        __syncthreads();

        // ---- rescale O^T accumulators by corr[col] ----
#pragma unroll
        for (int nt = 0; nt < 4; nt++) {
            int col = nbase + nt * 8 + 2 * tig;
            float c0 = fsf[FCORR + col];
            float c1 = fsf[FCORR + col + 1];
            oacc[nt][0] *= c0; oacc[nt][1] *= c1;
            oacc[nt][2] *= c0; oacc[nt][3] *= c1;
        }
        // ---- PV MMA: O^T[d][q] += V[d][key] * P^T ----
#pragma unroll
        for (int kt = 0; kt < 4; kt++) {
            const int k2a = kt * 8 + tig;
            const int k2b = k2a + 4;
            const int md = mbase + gid;
            uint32_t avh[4] = { Vh_[md * 36 + k2a], Vh_[(md + 8) * 36 + k2a],
                                Vh_[md * 36 + k2b], Vh_[(md + 8) * 36 + k2b] };
            uint32_t avl[4] = { Vl_[md * 36 + k2a], Vl_[(md + 8) * 36 + k2a],
                                Vl_[md * 36 + k2b], Vl_[(md + 8) * 36 + k2b] };
#pragma unroll
            for (int nt = 0; nt < 4; nt++) {
                int n = nbase + nt * 8 + gid;
                uint32_t bph[2] = { fs[FPH + k2a * 72 + n], fs[FPH + k2b * 72 + n] };
                uint32_t bpl[2] = { fs[FPL + k2a * 72 + n], fs[FPL + k2b * 72 + n] };
                mma_bf16(oacc[nt], avh, bph);
                mma_bf16(oacc[nt], avh, bpl);
                mma_bf16(oacc[nt], avl, bph);
            }
        }
    }

    // ---- output: packed channel-paired [c2][t] ----
#pragma unroll
    for (int nt = 0; nt < 4; nt++) {
        int col = nbase + nt * 8 + 2 * tig;
        float i0 = 1.f / fsf[FLST + col];
        float i1 = 1.f / fsf[FLST + col + 1];
        float v0 = oacc[nt][0] * i0;
        float v1 = oacc[nt][1] * i1;
        float v2 = oacc[nt][2] * i0;
        float v3 = oacc[nt][3] * i1;
        float q0 = __shfl_xor_sync(0xffffffffu, v0, 4);
        float q1 = __shfl_xor_sync(0xffffffffu, v1, 4);
        float q2 = __shfl_xor_sync(0xffffffffu, v2, 4);
        float q3 = __shfl_xor_sync(0xffffffffu, v3, 4);
        if ((gid & 1) == 0) {
            int d0 = h * 64 + mbase + gid;          // even
            int c2a = d0 >> 1;
            size_t ra = ((size_t)b * (C / 2) + c2a) * T + m0 + col;
            size_t rb = ((size_t)b * (C / 2) + c2a + 4) * T + m0 + col;
            float h0 = bf_hi_val(v0), hq = bf_hi_val(q0);
            oh[ra]     = pack_bf2(h0, hq);
            ol[ra]     = pack_bf2(v0 - h0, q0 - hq);
            h0 = bf_hi_val(v1); hq = bf_hi_val(q1);
            oh[ra + 1] = pack_bf2(h0, hq);
            ol[ra + 1] = pack_bf2(v1 - h0, q1 - hq);
            h0 = bf_hi_val(v2); hq = bf_hi_val(q2);
            oh[rb]     = pack_bf2(h0, hq);
            ol[rb]     = pack_bf2(v2 - h0, q2 - hq);
            h0 = bf_hi_val(v3); hq = bf_hi_val(q3);
            oh[rb + 1] = pack_bf2(h0, hq);
            ol[rb + 1] = pack_bf2(v3 - h0, q3 - hq);
        }
    }
}

// ---------------- final 1-channel projection ----------------
__global__ void proj_out(const float* __restrict__ x, const float* __restrict__ w,
                         const float* __restrict__ pb, const float* __restrict__ mask,
                         float* __restrict__ out)
{
    int t = blockIdx.x * 256 + threadIdx.x;
    int b = blockIdx.y;
    float s = pb[0];
    const float* xb = x + (size_t)b * C * T;
    for (int c = 0; c < C; c++)
        s += w[c] * xb[(size_t)c * T + t];
    out[(size_t)b * T + t] = s * mask[(size_t)b * T + t];
}

// ---------------- launch ----------------
extern "C" void kernel_launch(void* const* d_in, const int* in_sizes, int n_in,
                              void* d_out, int out_size)
{
    const float* x    = (const float*)d_in[0];
    const float* f0   = (const float*)d_in[1];
    const float* mask = (const float*)d_in[2];
    const float* spk  = (const float*)d_in[3];
    const float* prw  = (const float*)d_in[4];
    const float* prb  = (const float*)d_in[5];
    const float* f0w  = (const float*)d_in[6];
    const float* f0b  = (const float*)d_in[7];
    const float* cw   = (const float*)d_in[8];
    const float* cb   = (const float*)d_in[9];
    const float* pw   = (const float*)d_in[10];
    const float* pb   = (const float*)d_in[11];
    const float* qw   = (const float*)d_in[12];
    const float* qb   = (const float*)d_in[13];
    const float* kw   = (const float*)d_in[14];
    const float* kb   = (const float*)d_in[15];
    const float* vw   = (const float*)d_in[16];
    const float* vb   = (const float*)d_in[17];
    const float* ow   = (const float*)d_in[18];
    const float* ob   = (const float*)d_in[19];
    const float* ln0g = (const float*)d_in[20];
    const float* ln0b = (const float*)d_in[21];
    const float* ln1g = (const float*)d_in[22];
    const float* ln1b = (const float*)d_in[23];
    const float* f1w  = (const float*)d_in[24];
    const float* f1b  = (const float*)d_in[25];
    const float* f2w  = (const float*)d_in[26];
    const float* f2b  = (const float*)d_in[27];
    float* out = (float*)d_out;

    float *gx, *gy;
    uint32_t *wh, *wl, *ah, *al, *bh2, *bl2;
    cudaGetSymbolAddress((void**)&gx,  g_x);
    cudaGetSymbolAddress((void**)&gy,  g_y);
    cudaGetSymbolAddress((void**)&wh,  g_wh);
    cudaGetSymbolAddress((void**)&wl,  g_wl);
    cudaGetSymbolAddress((void**)&ah,  g_ah);
    cudaGetSymbolAddress((void**)&al,  g_al);
    cudaGetSymbolAddress((void**)&bh2, g_bh);
    cudaGetSymbolAddress((void**)&bl2, g_bl);

    uint32_t* qh_ = bh2 + RG_Q;  uint32_t* ql_ = bl2 + RG_Q;
    uint32_t* kh_ = bh2 + RG_K;  uint32_t* kl_ = bl2 + RG_K;
    uint32_t* vh_ = bh2 + RG_V;  uint32_t* vl_ = bl2 + RG_V;
    uint32_t* th_ = bh2 + RG_A;  uint32_t* tl_ = bl2 + RG_A;

    cudaFuncSetAttribute(flash_mma, cudaFuncAttributeMaxDynamicSharedMemorySize, FLASH2_SMEM);
    cudaFuncSetAttribute(mma_gemm_p<1,0,false,false,true ,1,0>, cudaFuncAttributeMaxDynamicSharedMemorySize, GEMM_SMEM);
    cudaFuncSetAttribute(mma_gemm_p<3,1,false,true ,false,1,0>, cudaFuncAttributeMaxDynamicSharedMemorySize, GEMM_SMEM);
    cudaFuncSetAttribute(mma_gemm_p<1,0,false,false,false,3,2>, cudaFuncAttributeMaxDynamicSharedMemorySize, GEMM_SMEM);
    cudaFuncSetAttribute(mma_gemm_p<1,0,false,false,false,1,0>, cudaFuncAttributeMaxDynamicSharedMemorySize, GEMM_SMEM);
    cudaFuncSetAttribute(mma_gemm_p<3,2,true ,false,false,1,1>, cudaFuncAttributeMaxDynamicSharedMemorySize, GEMM_SMEM);
    cudaFuncSetAttribute(mma_gemm_p<3,2,false,true ,false,1,0>, cudaFuncAttributeMaxDynamicSharedMemorySize, GEMM_SMEM);

    // ---- pack all weights ----
    pack_w<<<dim3(65536 / 256, 1), 256>>>(cw, 0, OFF_COND, 0, S, 1, 8);
    pack_w<<<dim3(393216 / 256, 1), 256>>>(prw, 0, OFF_PRE, 0, C, 3, 48);
    pack_w<<<dim3(131072 / 256, L), 256>>>(qw, (size_t)C * C, OFF_QKV + 0,      QKV_LSTR, C, 1, 16);
    pack_w<<<dim3(131072 / 256, L), 256>>>(kw, (size_t)C * C, OFF_QKV + 131072, QKV_LSTR, C, 1, 16);
    pack_w<<<dim3(131072 / 256, L), 256>>>(vw, (size_t)C * C, OFF_QKV + 262144, QKV_LSTR, C, 1, 16);
    pack_w<<<dim3(131072 / 256, L), 256>>>(ow, (size_t)C * C, OFF_OUT, OUT_LSTR, C, 1, 16);
    pack_w<<<dim3(1572864 / 256, L), 256>>>(f1w, (size_t)FC * C * 3, OFF_F1, F1_LSTR, C,  3, 48);
    pack_w<<<dim3(1572864 / 256, L), 256>>>(f2w, (size_t)C * FC * 3, OFF_F2, F2_LSTR, FC, 3, 192);

    // ---- prep ----
    split_act<<<dim3(T / 256, S / 2, B), 256>>>(spk, ah, al, S / 2);
    mma_gemm_p<1, 0, false, false, true, 1, 0><<<dim3(T / 128, 4, B), 256, GEMM_SMEM>>>(
        ah, al, wh + OFF_COND, wl + OFF_COND, cb, cb, cb, nullptr, x,
        gy, nullptr, nullptr, nullptr, nullptr, nullptr, nullptr, gy, gy, S, C);
    add_f0<<<dim3(T / 256, C, B), 256>>>(f0, f0w, f0b, gy);
    split_act<<<dim3(T / 256, C / 2, B), 256>>>(gy, ah, al, C / 2);
    mma_gemm_p<3, 1, false, true, false, 1, 0><<<dim3(T / 128, 4, B), 256, GEMM_SMEM>>>(
        ah, al, wh + OFF_PRE, wl + OFF_PRE, prb, prb, prb, mask, nullptr,
        gx, nullptr, nullptr, nullptr, nullptr, nullptr, nullptr, gx, gx, C, C);
    split_act<<<dim3(T / 256, C / 2, B), 256>>>(gx, ah, al, C / 2);

    for (int l = 0; l < L; l++) {
        // fused QKV -> packed q/k (channel pairs), v (time pairs)
        mma_gemm_p<1, 0, false, false, false, 3, 2><<<dim3(T / 128, 12, B), 256, GEMM_SMEM>>>(
            ah, al, wh + OFF_QKV + (size_t)l * QKV_LSTR, wl + OFF_QKV + (size_t)l * QKV_LSTR,
            qb + l * C, kb + l * C, vb + l * C, nullptr, nullptr,
            nullptr, qh_, ql_, kh_, kl_, vh_, vl_, nullptr, nullptr, C, C);

        // tensor-core attention -> packed attn
        flash_mma<<<dim3(T / 64, B * H), 256, FLASH2_SMEM>>>(
            qh_, ql_, kh_, kl_, vh_, vl_, th_, tl_);

        // out-proj from packed attn -> gy float
        mma_gemm_p<1, 0, false, false, false, 1, 0><<<dim3(T / 128, 4, B), 256, GEMM_SMEM>>>(
            th_, tl_, wh + OFF_OUT + (size_t)l * OUT_LSTR, wl + OFF_OUT + (size_t)l * OUT_LSTR,
            ob + l * C, nullptr, nullptr, nullptr, nullptr,
            gy, nullptr, nullptr, nullptr, nullptr, nullptr, nullptr, nullptr, nullptr, C, C);

        add_ln_p<<<dim3(T / 32, B), dim3(32, 8)>>>(gx, gy, ln0g + l * C, ln0b + l * C, gx, ah, al);

        // FFN1 -> packed B-buf (relu)
        mma_gemm_p<3, 2, true, false, false, 1, 1><<<dim3(T / 128, FC / 128, B), 256, GEMM_SMEM>>>(
            ah, al, wh + OFF_F1 + (size_t)l * F1_LSTR, wl + OFF_F1 + (size_t)l * F1_LSTR,
            f1b + l * FC, nullptr, nullptr, nullptr, nullptr,
            nullptr, bh2, bl2, nullptr, nullptr, nullptr, nullptr, nullptr, nullptr, C, FC);

        // FFN2 -> gy float (mask)
        mma_gemm_p<3, 2, false, true, false, 1, 0><<<dim3(T / 128, 4, B), 256, GEMM_SMEM>>>(
            bh2, bl2, wh + OFF_F2 + (size_t)l * F2_LSTR, wl + OFF_F2 + (size_t)l * F2_LSTR,
            f2b + l * C, nullptr, nullptr, mask, nullptr,
            gy, nullptr, nullptr, nullptr, nullptr, nullptr, nullptr, nullptr, nullptr, FC, C);

        add_ln_p<<<dim3(T / 32, B), dim3(32, 8)>>>(gx, gy, ln1g + l * C, ln1b + l * C, gx, ah, al);
    }

    proj_out<<<dim3(T / 256, B), 256>>>(gx, pw, pb, mask, out);
}

// round 10
// speedup vs baseline: 1.4665x; 1.1274x over previous
#include <cuda_runtime.h>
#include <cuda_bf16.h>
#include <cstdint>
#include <cstddef>

// ---------------- problem constants ----------------
static constexpr int B  = 4;
static constexpr int C  = 512;
static constexpr int T  = 2048;
static constexpr int H  = 8;
static constexpr int FC = 2048;
static constexpr int L  = 6;
static constexpr int S  = 256;
static constexpr int DK = 64;

// ---------------- device scratch ----------------
__device__ float g_x[B * C * T];
__device__ float g_y[B * C * T];

// packed split weights (hi/lo bf16x2), pretiled [omBlk][chunk][m(128)][k2(16)]
static constexpr size_t OFF_COND = 0;
static constexpr size_t OFF_PRE  = 65536;
static constexpr size_t OFF_QKV  = 458752;
static constexpr size_t QKV_LSTR = 393216;
static constexpr size_t OFF_OUT  = 2818048;
static constexpr size_t OUT_LSTR = 131072;
static constexpr size_t OFF_F1   = 3604480;
static constexpr size_t F1_LSTR  = 1572864;
static constexpr size_t OFF_F2   = 13041664;
static constexpr size_t F2_LSTR  = 1572864;
static constexpr size_t W_TOTAL  = 22478848;

__device__ uint32_t g_wh[W_TOTAL];
__device__ uint32_t g_wl[W_TOTAL];
// packed split activations, ping-pong buffers
__device__ uint32_t g_ah[(size_t)B * (FC / 2) * T];
__device__ uint32_t g_al[(size_t)B * (FC / 2) * T];
__device__ uint32_t g_bh[(size_t)B * (FC / 2) * T];
__device__ uint32_t g_bl[(size_t)B * (FC / 2) * T];

// region offsets inside g_bh/g_bl (words): q, k, vT, attn (2M each)
static constexpr size_t RG_Q = 0;
static constexpr size_t RG_K = 2097152;
static constexpr size_t RG_V = 4194304;
static constexpr size_t RG_A = 6291456;

// ---------------- helpers ----------------
__device__ __forceinline__ uint32_t pack_bf2(float a, float b) {
    uint32_t r;
    asm("cvt.rn.bf16x2.f32 %0, %1, %2;" : "=r"(r) : "f"(b), "f"(a));
    return r;
}
__device__ __forceinline__ float bf_hi_val(float v) {
    __nv_bfloat16 h = __float2bfloat16_rn(v);
    return __bfloat162float(h);
}
__device__ __forceinline__ void mma_bf16(float* d, const uint32_t* a, const uint32_t* b) {
    asm volatile("mma.sync.aligned.m16n8k16.row.col.f32.bf16.bf16.f32 "
        "{%0,%1,%2,%3}, {%4,%5,%6,%7}, {%8,%9}, {%0,%1,%2,%3};"
        : "+f"(d[0]), "+f"(d[1]), "+f"(d[2]), "+f"(d[3])
        : "r"(a[0]), "r"(a[1]), "r"(a[2]), "r"(a[3]), "r"(b[0]), "r"(b[1]));
}
__device__ __forceinline__ uint32_t smem_u32(const void* p) {
    uint32_t a;
    asm("{ .reg .u64 t; cvta.to.shared.u64 t, %1; cvt.u32.u64 %0, t; }" : "=r"(a) : "l"(p));
    return a;
}
__device__ __forceinline__ void ldm4(uint32_t* r, uint32_t addr) {
    asm volatile("ldmatrix.sync.aligned.m8n8.x4.shared.b16 {%0,%1,%2,%3}, [%4];"
        : "=r"(r[0]), "=r"(r[1]), "=r"(r[2]), "=r"(r[3]) : "r"(addr));
}
__device__ __forceinline__ void cp16(uint32_t dst, const void* src) {
    asm volatile("cp.async.cg.shared.global [%0], [%1], 16;" :: "r"(dst), "l"(src));
}
__device__ __forceinline__ void cp8(uint32_t dst, const void* src) {
    asm volatile("cp.async.ca.shared.global [%0], [%1], 8;" :: "r"(dst), "l"(src));
}
__device__ __forceinline__ void cp4z(uint32_t dst, const void* src, int srcsz) {
    asm volatile("cp.async.ca.shared.global [%0], [%1], 4, %2;"
                 :: "r"(dst), "l"(src), "r"(srcsz));
}
__device__ __forceinline__ void cp_commit() {
    asm volatile("cp.async.commit_group;" ::: "memory");
}
template <int N>
__device__ __forceinline__ void cp_wait() {
    asm volatile("cp.async.wait_group %0;" :: "n"(N) : "memory");
}

// ---------------- weight packing ----------------
__global__ void pack_w(const float* __restrict__ src, size_t src_lstride,
                       size_t dst_base, size_t dst_lstride,
                       int Cin, int KW, int chunks)
{
    const int l = blockIdx.y;
    const int w = blockIdx.x * 256 + threadIdx.x;
    const int per_blk = chunks * 2048;
    const int omBlk = w / per_blk;
    const int r  = w % per_blk;
    const int ch = r / 2048, r2 = r % 2048;
    const int m  = r2 >> 4;
    const int k2 = ch * 16 + (r2 & 15);
    int ka, kb;
    if (KW == 1) { ka = 2 * k2; kb = ka + 1; }
    else { int half = Cin >> 1; int c2 = k2 % half, kk = k2 / half;
           ka = (2 * c2) * KW + kk; kb = ka + KW; }
    const float* s = src + (size_t)l * src_lstride + (size_t)(omBlk * 128 + m) * Cin * KW;
    float va = s[ka], vb = s[kb];
    float ha = bf_hi_val(va), hb = bf_hi_val(vb);
    size_t d = dst_base + (size_t)l * dst_lstride + w;
    g_wh[d] = pack_bf2(ha, hb);
    g_wl[d] = pack_bf2(va - ha, vb - hb);
}

// ---------------- activation split/pack (prep only) ----------------
__global__ void split_act(const float* __restrict__ X, uint32_t* __restrict__ Xh,
                          uint32_t* __restrict__ Xl, int Chalf)
{
    const int t  = blockIdx.x * 256 + threadIdx.x;
    const int c2 = blockIdx.y;
    const int b  = blockIdx.z;
    const float* x0 = X + ((size_t)b * 2 * Chalf + 2 * c2) * T;
    float va = x0[t], vb = x0[T + t];
    float ha = bf_hi_val(va), hb = bf_hi_val(vb);
    size_t d = ((size_t)b * Chalf + c2) * T + t;
    Xh[d] = pack_bf2(ha, hb);
    Xl[d] = pack_bf2(va - ha, vb - hb);
}

// ================= cp.async pipelined bf16x2-split mma.sync conv-GEMM =================
static constexpr int ASTR = 20;
static constexpr int KSTR = 136;
static constexpr int A_WORDS = 128 * ASTR;
static constexpr int B_WORDS = 16 * KSTR;
static constexpr int STG_WORDS = 2 * A_WORDS + 2 * B_WORDS;
static constexpr int GEMM_SMEM = 2 * STG_WORDS * 4;

// OMODE: 0 = float out, 1 = channel-pair packed out, 2 = QKV (sel0/1 packout, sel2 vpackt)
template <int KW, int PL, bool RELU, bool DOMASK, bool ADDSRC, int NOUT, int OMODE>
__global__ __launch_bounds__(256, 2) void mma_gemm_p(
    const uint32_t* __restrict__ Xh, const uint32_t* __restrict__ Xl,
    const uint32_t* __restrict__ Wh, const uint32_t* __restrict__ Wl,
    const float* __restrict__ b0, const float* __restrict__ b1, const float* __restrict__ b2,
    const float* __restrict__ mask, const float* __restrict__ src,
    float* __restrict__ Y0,
    uint32_t* __restrict__ poh,  uint32_t* __restrict__ pol,
    uint32_t* __restrict__ poh2, uint32_t* __restrict__ pol2,
    uint32_t* __restrict__ poh3, uint32_t* __restrict__ pol3,
    float* __restrict__ Y1, float* __restrict__ Y2,
    int Cin, int Cout)
{
    extern __shared__ uint32_t dsm[];
    const uint32_t sbase = smem_u32(dsm);

    const int tid  = threadIdx.x;
    const int lane = tid & 31;
    const int wid  = tid >> 5;
    const int mw   = wid & 1;
    const int nw   = wid >> 1;
    const int gid  = lane >> 2;
    const int tig  = lane & 3;

    const int b   = blockIdx.z;
    const int tn0 = blockIdx.x * 128;
    int sel, om;
    if (NOUT == 3) { sel = blockIdx.y >> 2; om = (blockIdx.y & 3) * 128; }
    else           { sel = 0;               om = blockIdx.y * 128; }
    const float* bias = (NOUT == 3) ? (sel == 0 ? b0 : sel == 1 ? b1 : b2) : b0;
    float* Y          = (NOUT == 3) ? (sel == 0 ? Y0 : sel == 1 ? Y1 : Y2) : Y0;

    const int Chalf  = Cin >> 1;
    const int chunks = (Cin * KW) >> 5;
    const uint32_t* wtH = Wh + (size_t)blockIdx.y * chunks * 2048;
    const uint32_t* wtL = Wl + (size_t)blockIdx.y * chunks * 2048;
    const uint32_t* XhB = Xh + (size_t)b * Chalf * T;
    const uint32_t* XlB = Xl + (size_t)b * Chalf * T;

    const int lm  = tid >> 1;
    const int lh  = tid & 1;
    const int lk2 = tid >> 4;
    const int lq  = tid & 15;

    const int qq   = lane >> 3;
    const int rrow = lane & 7;
    const uint32_t laneOff = ((uint32_t)((mw * 64 + (qq & 1) * 8 + rrow) * ASTR
                             + (qq >> 1) * 4)) * 4u;

    auto issueA = [&](int ch, int s) {
        const uint32_t* aH = wtH + ch * 2048 + lm * 16 + lh * 8;
        const uint32_t* aL = wtL + ch * 2048 + lm * 16 + lh * 8;
        uint32_t d = sbase + (uint32_t)(s * STG_WORDS + lm * ASTR + lh * 8) * 4u;
        cp16(d, aH);
        cp16(d + 16, aH + 4);
        cp16(d + A_WORDS * 4, aL);
        cp16(d + A_WORDS * 4 + 16, aL + 4);
    };
    auto issueB = [&](int ch, int s) {
        const int k2g = ch * 16 + lk2;
        uint32_t dh = sbase + (uint32_t)(s * STG_WORDS + 2 * A_WORDS + lk2 * KSTR + lq * 8) * 4u;
        uint32_t dl = dh + B_WORDS * 4;
        if (KW == 1) {
            const uint32_t* rH = XhB + (size_t)k2g * T + tn0 + lq * 8;
            const uint32_t* rL = XlB + (size_t)k2g * T + tn0 + lq * 8;
            cp16(dh, rH); cp16(dh + 16, rH + 4);
            cp16(dl, rL); cp16(dl + 16, rL + 4);
        } else {
            const int c2 = k2g % Chalf;
            const int kk = k2g / Chalf;
            const int dt = kk - PL;
            const uint32_t* rH = XhB + (size_t)c2 * T;
            const uint32_t* rL = XlB + (size_t)c2 * T;
            const int t0 = tn0 + lq * 8 + dt;
            if (dt == 0) {
                cp16(dh, rH + t0); cp16(dh + 16, rH + t0 + 4);
                cp16(dl, rL + t0); cp16(dl + 16, rL + t0 + 4);
            } else if (t0 >= 0 && t0 + 8 <= T) {
                if ((dt & 1) == 0) {
#pragma unroll
                    for (int j = 0; j < 4; j++) {
                        cp8(dh + j * 8, rH + t0 + j * 2);
                        cp8(dl + j * 8, rL + t0 + j * 2);
                    }
                } else {
#pragma unroll
                    for (int j = 0; j < 8; j++) {
                        cp4z(dh + j * 4, rH + t0 + j, 4);
                        cp4z(dl + j * 4, rL + t0 + j, 4);
                    }
                }
            } else {
#pragma unroll
                for (int j = 0; j < 8; j++) {
                    int t = t0 + j;
                    bool ok = (unsigned)t < (unsigned)T;
                    int tc = ok ? t : 0;
                    int sz = ok ? 4 : 0;
                    cp4z(dh + j * 4, rH + tc, sz);
                    cp4z(dl + j * 4, rL + tc, sz);
                }
            }
        }
    };

    float acc[4][4][4];
#pragma unroll
    for (int i = 0; i < 4; i++)
#pragma unroll
        for (int j = 0; j < 4; j++)
#pragma unroll
            for (int r = 0; r < 4; r++) acc[i][j][r] = 0.f;

    issueA(0, 0); issueB(0, 0); cp_commit();

    for (int ch = 0; ch < chunks; ch++) {
        const int s = ch & 1;
        if (ch + 1 < chunks) {
            issueA(ch + 1, s ^ 1); issueB(ch + 1, s ^ 1); cp_commit();
            cp_wait<1>();
        } else {
            cp_wait<0>();
        }
        __syncthreads();

        const uint32_t aAh = sbase + (uint32_t)(s * STG_WORDS) * 4u;
        const uint32_t aAl = aAh + A_WORDS * 4u;
        const uint32_t* BhS = dsm + s * STG_WORDS + 2 * A_WORDS;
        const uint32_t* BlS = BhS + B_WORDS;

#pragma unroll
        for (int ks = 0; ks < 2; ks++) {
            const int k2a = ks * 8 + tig;
            const int k2b = ks * 8 + 4 + tig;
            uint32_t bfh[4][2], bfl[4][2];
#pragma unroll
            for (int nt = 0; nt < 4; nt++) {
                int n = nw * 32 + nt * 8 + gid;
                bfh[nt][0] = BhS[k2a * KSTR + n];
                bfh[nt][1] = BhS[k2b * KSTR + n];
                bfl[nt][0] = BlS[k2a * KSTR + n];
                bfl[nt][1] = BlS[k2b * KSTR + n];
            }
#pragma unroll
            for (int mt = 0; mt < 4; mt++) {
                uint32_t afh[4], afl[4];
                const uint32_t off = laneOff + (uint32_t)(mt * 16 * ASTR + ks * 8) * 4u;
                ldm4(afh, aAh + off);
                ldm4(afl, aAl + off);
#pragma unroll
                for (int nt = 0; nt < 4; nt++) {
                    mma_bf16(acc[mt][nt], afh, bfh[nt]);
                    mma_bf16(acc[mt][nt], afh, bfl[nt]);
                    mma_bf16(acc[mt][nt], afl, bfh[nt]);
                }
            }
        }
        __syncthreads();
    }

    // ---- epilogue ----
    const int ChalfO = Cout >> 1;
    uint32_t* th = poh; uint32_t* tl = pol;
    if (OMODE == 2 && sel == 1) { th = poh2; tl = pol2; }
#pragma unroll
    for (int mt = 0; mt < 4; mt++) {
        int o0 = om + mw * 64 + mt * 16 + gid;
        float bb0 = bias[o0];
        float bb1 = bias[o0 + 8];
#pragma unroll
        for (int nt = 0; nt < 4; nt++) {
            int t0 = tn0 + nw * 32 + nt * 8 + 2 * tig;
            float v0 = acc[mt][nt][0] + bb0;
            float v1 = acc[mt][nt][1] + bb0;
            float v2 = acc[mt][nt][2] + bb1;
            float v3 = acc[mt][nt][3] + bb1;
            if (RELU) {
                v0 = fmaxf(v0, 0.f); v1 = fmaxf(v1, 0.f);
                v2 = fmaxf(v2, 0.f); v3 = fmaxf(v3, 0.f);
            }
            if (OMODE == 2 && sel == 2) {
                size_t ia = ((size_t)b * Cout + o0)     * (T / 2) + (t0 >> 1);
                size_t ib = ((size_t)b * Cout + o0 + 8) * (T / 2) + (t0 >> 1);
                float h0 = bf_hi_val(v0), h1 = bf_hi_val(v1);
                poh3[ia] = pack_bf2(h0, h1);
                pol3[ia] = pack_bf2(v0 - h0, v1 - h1);
                h0 = bf_hi_val(v2); h1 = bf_hi_val(v3);
                poh3[ib] = pack_bf2(h0, h1);
                pol3[ib] = pack_bf2(v2 - h0, v3 - h1);
            } else if (OMODE == 1 || OMODE == 2) {
                float q0 = __shfl_xor_sync(0xffffffffu, v0, 4);
                float q1 = __shfl_xor_sync(0xffffffffu, v1, 4);
                float q2 = __shfl_xor_sync(0xffffffffu, v2, 4);
                float q3 = __shfl_xor_sync(0xffffffffu, v3, 4);
                if ((gid & 1) == 0) {
                    size_t da = ((size_t)b * ChalfO + (o0 >> 1)) * T + t0;
                    size_t db = ((size_t)b * ChalfO + ((o0 + 8) >> 1)) * T + t0;
                    float h;
                    h = bf_hi_val(v0); float hq = bf_hi_val(q0);
                    th[da]     = pack_bf2(h, hq);
                    tl[da]     = pack_bf2(v0 - h, q0 - hq);
                    h = bf_hi_val(v1); hq = bf_hi_val(q1);
                    th[da + 1] = pack_bf2(h, hq);
                    tl[da + 1] = pack_bf2(v1 - h, q1 - hq);
                    h = bf_hi_val(v2); hq = bf_hi_val(q2);
                    th[db]     = pack_bf2(h, hq);
                    tl[db]     = pack_bf2(v2 - h, q2 - hq);
                    h = bf_hi_val(v3); hq = bf_hi_val(q3);
                    th[db + 1] = pack_bf2(h, hq);
                    tl[db + 1] = pack_bf2(v3 - h, q3 - hq);
                }
            } else {
                float m0v = 1.f, m1v = 1.f;
                if (DOMASK) {
                    m0v = mask[(size_t)b * T + t0];
                    m1v = mask[(size_t)b * T + t0 + 1];
                }
                size_t oi0 = ((size_t)b * Cout + o0)     * T + t0;
                size_t oi1 = ((size_t)b * Cout + o0 + 8) * T + t0;
                if (ADDSRC) {
                    float2 s0 = *(const float2*)(src + oi0);
                    float2 s1 = *(const float2*)(src + oi1);
                    v0 += s0.x; v1 += s0.y; v2 += s1.x; v3 += s1.y;
                }
                if (DOMASK) { v0 *= m0v; v1 *= m1v; v2 *= m0v; v3 *= m1v; }
                *(float2*)(Y + oi0) = make_float2(v0, v1);
                *(float2*)(Y + oi1) = make_float2(v2, v3);
            }
        }
    }
}

// ---------------- f0 prenet added in-place ----------------
__global__ void add_f0(const float* __restrict__ f0, const float* __restrict__ w,
                       const float* __restrict__ fb, float* __restrict__ y)
{
    int t = blockIdx.x * 256 + threadIdx.x;
    int c = blockIdx.y;
    int b = blockIdx.z;
    float fm1 = (t - 1 >= 0) ? f0[(size_t)b * T + t - 1] : 0.f;
    float fc0 = f0[(size_t)b * T + t];
    float fp1 = (t + 1 < T) ? f0[(size_t)b * T + t + 1] : 0.f;
    float v = w[c * 3 + 0] * fm1 + w[c * 3 + 1] * fc0 + w[c * 3 + 2] * fp1 + fb[c];
    y[((size_t)b * C + c) * T + t] += v;
}

// ---------------- fused residual-add + LayerNorm + packed split output ----------------
// dynamic smem: cache[512*32] + red0[256] + red1[256] + smv[64]
static constexpr int LN_SMEM = (512 * 32 + 256 + 256 + 64) * 4;

__global__ void add_ln_p(const float* __restrict__ x, const float* __restrict__ y,
                         const float* __restrict__ g, const float* __restrict__ be,
                         float* __restrict__ out,
                         uint32_t* __restrict__ ph, uint32_t* __restrict__ pl)
{
    extern __shared__ float lns[];
    float* cache = lns;                 // [c][tx] stride 32
    float* red0  = lns + 512 * 32;      // [ty][tx]
    float* red1  = red0 + 256;
    float* smv   = red1 + 256;          // [2][32]
    const int tx = threadIdx.x, ty = threadIdx.y;
    const int t = blockIdx.x * 32 + tx;
    const int b = blockIdx.y;
    const size_t base = (size_t)b * C * T + t;

    float s = 0.f, sq = 0.f;
    for (int c2 = ty; c2 < C / 2; c2 += 8) {
        size_t i0 = base + (size_t)(2 * c2) * T;
        float v0 = x[i0] + y[i0];
        float v1 = x[i0 + T] + y[i0 + T];
        cache[(2 * c2) * 32 + tx]     = v0;
        cache[(2 * c2 + 1) * 32 + tx] = v1;
        s += v0 + v1; sq += v0 * v0 + v1 * v1;
    }
    red0[ty * 32 + tx] = s; red1[ty * 32 + tx] = sq;
    __syncthreads();
    if (ty == 0) {
#pragma unroll
        for (int i = 1; i < 8; i++) { s += red0[i * 32 + tx]; sq += red1[i * 32 + tx]; }
        float mean = s * (1.f / C);
        float var  = sq * (1.f / C) - mean * mean;
        smv[tx]      = mean;
        smv[32 + tx] = rsqrtf(var + 1e-5f);
    }
    __syncthreads();
    float mean = smv[tx], rstd = smv[32 + tx];
    for (int c2 = ty; c2 < C / 2; c2 += 8) {
        size_t i0 = base + (size_t)(2 * c2) * T;
        float v0 = (cache[(2 * c2) * 32 + tx]     - mean) * rstd * g[2 * c2]     + be[2 * c2];
        float v1 = (cache[(2 * c2 + 1) * 32 + tx] - mean) * rstd * g[2 * c2 + 1] + be[2 * c2 + 1];
        out[i0]     = v0;
        out[i0 + T] = v1;
        float h0 = bf_hi_val(v0), h1 = bf_hi_val(v1);
        size_t d = ((size_t)b * (C / 2) + c2) * T + t;
        ph[d] = pack_bf2(h0, h1);
        pl[d] = pack_bf2(v0 - h0, v1 - h1);
    }
}

// ================= tensor-core causal flash attention (2 CTA/SM) =================
// smem word offsets
static constexpr int FQH = 0;            // [k2dk=32][72]
static constexpr int FQL = 2304;
static constexpr int FKH0 = 4608;        // 2 stages x (Kh,Kl) each 2304
static constexpr int FVH  = 13824;       // single stage (Vh,Vl) each 2304 ([d=64][36])
static constexpr int FSS  = 18432;       // float S [q=64][68]
static constexpr int FPH  = 22784;       // P packed [k2key=32][72]
static constexpr int FPL  = 25088;
static constexpr int FCORR = 27392;      // float[64]
static constexpr int FMST  = 27456;
static constexpr int FLST  = 27520;
static constexpr int FLASH2_WORDS = 27584;
static constexpr int FLASH2_SMEM = FLASH2_WORDS * 4;   // 110336 B

__global__ __launch_bounds__(256, 2) void flash_mma(
    const uint32_t* __restrict__ qh, const uint32_t* __restrict__ ql,
    const uint32_t* __restrict__ kh, const uint32_t* __restrict__ kl,
    const uint32_t* __restrict__ vh, const uint32_t* __restrict__ vl,
    uint32_t* __restrict__ oh, uint32_t* __restrict__ ol)
{
    extern __shared__ uint32_t fs[];
    float* fsf = (float*)fs;
    const uint32_t sb = smem_u32(fs);

    const int tid  = threadIdx.x;
    const int lane = tid & 31;
    const int wid  = tid >> 5;
    const int gid  = lane >> 2;
    const int tig  = lane & 3;
    const int wm   = wid & 3;
    const int wn   = wid >> 2;
    const int mbase = wm * 16;
    const int nbase = wn * 32;

    const int mb = (int)gridDim.x - 1 - (int)blockIdx.x;
    const int m0 = mb * 64;
    const int bhh = blockIdx.y;
    const int b = bhh >> 3;
    const int h = bhh & 7;

    const uint32_t* qhB = qh + ((size_t)b * (C / 2) + h * 32) * T + m0;
    const uint32_t* qlB = ql + ((size_t)b * (C / 2) + h * 32) * T + m0;
    const uint32_t* khB = kh + ((size_t)b * (C / 2) + h * 32) * T;
    const uint32_t* klB = kl + ((size_t)b * (C / 2) + h * 32) * T;
    const uint32_t* vhB = vh + ((size_t)b * C + h * 64) * (T / 2);
    const uint32_t* vlB = vl + ((size_t)b * C + h * 64) * (T / 2);

    if (tid < 64) { fsf[FMST + tid] = -1e30f; fsf[FLST + tid] = 0.f; }

    // Q load (once)
    {
        int selq = tid >> 7, r = tid & 127, k2 = r >> 2, cq = (r & 3) * 4;
        const uint32_t* src = (selq ? qlB : qhB) + (size_t)k2 * T;
        uint32_t dst = sb + (uint32_t)((selq ? FQL : FQH) + k2 * 72) * 4u;
#pragma unroll
        for (int i = 0; i < 4; i++) cp16(dst + (cq + i) * 16, src + (cq + i) * 4);
    }
    auto loadK = [&](int kbk, int s) {
        const int kn0 = kbk * 64;
        int selq = tid >> 7, r = tid & 127, k2 = r >> 2, cq = (r & 3) * 4;
        const uint32_t* src = (selq ? klB : khB) + (size_t)k2 * T + kn0;
        uint32_t dst = sb + (uint32_t)(FKH0 + s * 4608 + selq * 2304 + k2 * 72) * 4u;
#pragma unroll
        for (int i = 0; i < 4; i++) cp16(dst + (cq + i) * 16, src + (cq + i) * 4);
    };
    auto loadV = [&](int kbk) {
        const int kn0 = kbk * 64;
        int selq = tid >> 7, r = tid & 127, d = r >> 1, cq = (r & 1) * 4;
        const uint32_t* src = (selq ? vlB : vhB) + (size_t)d * (T / 2) + (kn0 >> 1);
        uint32_t dst = sb + (uint32_t)(FVH + selq * 2304 + d * 36) * 4u;
#pragma unroll
        for (int i = 0; i < 4; i++) cp16(dst + (cq + i) * 16, src + (cq + i) * 4);
    };
    loadK(0, 0); cp_commit();

    float oacc[4][4];
#pragma unroll
    for (int i = 0; i < 4; i++)
#pragma unroll
        for (int j = 0; j < 4; j++) oacc[i][j] = 0.f;

    for (int kbk = 0; kbk <= mb; kbk++) {
        const int s = kbk & 1;
        const int kn0 = kbk * 64;
        cp_wait<0>();           // K_kbk ready (V of prev iter already drained)
        __syncthreads();
        loadV(kbk); cp_commit();
        if (kbk < mb) { loadK(kbk + 1, s ^ 1); cp_commit(); }

        const uint32_t* Qh_ = fs + FQH;
        const uint32_t* Ql_ = fs + FQL;
        const uint32_t* Kh_ = fs + FKH0 + s * 4608;
        const uint32_t* Kl_ = Kh_ + 2304;
        const uint32_t* Vh_ = fs + FVH;
        const uint32_t* Vl_ = Vh_ + 2304;

        // ---- QK MMA ----
        float sacc[4][4];
#pragma unroll
        for (int i = 0; i < 4; i++)
#pragma unroll
            for (int j = 0; j < 4; j++) sacc[i][j] = 0.f;

#pragma unroll
        for (int kt = 0; kt < 4; kt++) {
            const int k2a = kt * 8 + tig;
            const int k2b = k2a + 4;
            const int mq = mbase + gid;
            uint32_t aqh[4] = { Qh_[k2a * 72 + mq], Qh_[k2a * 72 + mq + 8],
                                Qh_[k2b * 72 + mq], Qh_[k2b * 72 + mq + 8] };
            uint32_t aql[4] = { Ql_[k2a * 72 + mq], Ql_[k2a * 72 + mq + 8],
                                Ql_[k2b * 72 + mq], Ql_[k2b * 72 + mq + 8] };
#pragma unroll
            for (int nt = 0; nt < 4; nt++) {
                int n = nbase + nt * 8 + gid;
                uint32_t bkh[2] = { Kh_[k2a * 72 + n], Kh_[k2b * 72 + n] };
                uint32_t bkl[2] = { Kl_[k2a * 72 + n], Kl_[k2b * 72 + n] };
                mma_bf16(sacc[nt], aqh, bkh);
                mma_bf16(sacc[nt], aqh, bkl);
                mma_bf16(sacc[nt], aql, bkh);
            }
        }
#pragma unroll
        for (int nt = 0; nt < 4; nt++) {
            int col = nbase + nt * 8 + 2 * tig;
            int r0 = mbase + gid;
            *(float2*)&fsf[FSS + r0 * 68 + col]       = make_float2(sacc[nt][0], sacc[nt][1]);
            *(float2*)&fsf[FSS + (r0 + 8) * 68 + col] = make_float2(sacc[nt][2], sacc[nt][3]);
        }
        __syncthreads();

        // ---- softmax ----
#pragma unroll
        for (int r = 0; r < 8; r++) {
            int q = wid * 8 + r;
            int tq = m0 + q;
            float s0 = fsf[FSS + q * 68 + lane] * 0.125f;
            float s1 = fsf[FSS + q * 68 + lane + 32] * 0.125f;
            if (kn0 + lane      > tq) s0 = -1e4f;
            if (kn0 + lane + 32 > tq) s1 = -1e4f;
            float mx = fmaxf(s0, s1);
#pragma unroll
            for (int off = 16; off; off >>= 1)
                mx = fmaxf(mx, __shfl_xor_sync(0xffffffffu, mx, off));
            float mold = fsf[FMST + q];
            float mnew = fmaxf(mold, mx);
            float p0 = __expf(s0 - mnew);
            float p1 = __expf(s1 - mnew);
            float ps = p0 + p1;
#pragma unroll
            for (int off = 16; off; off >>= 1)
                ps += __shfl_xor_sync(0xffffffffu, ps, off);
            float corrv = __expf(mold - mnew);
            if (lane == 0) {
                fsf[FMST + q]  = mnew;
                fsf[FLST + q]  = fsf[FLST + q] * corrv + ps;
                fsf[FCORR + q] = corrv;
            }
            float p0p = __shfl_xor_sync(0xffffffffu, p0, 1);
            float p1p = __shfl_xor_sync(0xffffffffu, p1, 1);
            if ((lane & 1) == 0) {
                int k2 = lane >> 1;
                float h0 = bf_hi_val(p0), h1 = bf_hi_val(p0p);
                fs[FPH + k2 * 72 + q] = pack_bf2(h0, h1);
                fs[FPL + k2 * 72 + q] = pack_bf2(p0 - h0, p0p - h1);
                h0 = bf_hi_val(p1); h1 = bf_hi_val(p1p);
                fs[FPH + (k2 + 16) * 72 + q] = pack_bf2(h0, h1);
                fs[FPL + (k2 + 16) * 72 + q] = pack_bf2(p1 - h0, p1p - h1);
            }
        }
        __syncthreads();
        if (kbk < mb) cp_wait<1>(); else cp_wait<0>();   // V ready (K_{kbk+1} may fly)
        __syncthreads();

        // ---- rescale + PV MMA ----
#pragma unroll
        for (int nt = 0; nt < 4; nt++) {
            int col = nbase + nt * 8 + 2 * tig;
            float c0 = fsf[FCORR + col];
            float c1 = fsf[FCORR + col + 1];
            oacc[nt][0] *= c0; oacc[nt][1] *= c1;
            oacc[nt][2] *= c0; oacc[nt][3] *= c1;
        }
#pragma unroll
        for (int kt = 0; kt < 4; kt++) {
            const int k2a = kt * 8 + tig;
            const int k2b = k2a + 4;
            const int md = mbase + gid;
            uint32_t avh[4] = { Vh_[md * 36 + k2a], Vh_[(md + 8) * 36 + k2a],
                                Vh_[md * 36 + k2b], Vh_[(md + 8) * 36 + k2b] };
            uint32_t avl[4] = { Vl_[md * 36 + k2a], Vl_[(md + 8) * 36 + k2a],
                                Vl_[md * 36 + k2b], Vl_[(md + 8) * 36 + k2b] };
#pragma unroll
            for (int nt = 0; nt < 4; nt++) {
                int n = nbase + nt * 8 + gid;
                uint32_t bph[2] = { fs[FPH + k2a * 72 + n], fs[FPH + k2b * 72 + n] };
                uint32_t bpl[2] = { fs[FPL + k2a * 72 + n], fs[FPL + k2b * 72 + n] };
                mma_bf16(oacc[nt], avh, bph);
                mma_bf16(oacc[nt], avh, bpl);
                mma_bf16(oacc[nt], avl, bph);
            }
        }
    }

    // ---- output: packed channel-paired [c2][t] ----
#pragma unroll
    for (int nt = 0; nt < 4; nt++) {
        int col = nbase + nt * 8 + 2 * tig;
        float i0 = 1.f / fsf[FLST + col];
        float i1 = 1.f / fsf[FLST + col + 1];
        float v0 = oacc[nt][0] * i0;
        float v1 = oacc[nt][1] * i1;
        float v2 = oacc[nt][2] * i0;
        float v3 = oacc[nt][3] * i1;
        float q0 = __shfl_xor_sync(0xffffffffu, v0, 4);
        float q1 = __shfl_xor_sync(0xffffffffu, v1, 4);
        float q2 = __shfl_xor_sync(0xffffffffu, v2, 4);
        float q3 = __shfl_xor_sync(0xffffffffu, v3, 4);
        if ((gid & 1) == 0) {
            int d0 = h * 64 + mbase + gid;
            int c2a = d0 >> 1;
            size_t ra = ((size_t)b * (C / 2) + c2a) * T + m0 + col;
            size_t rb = ((size_t)b * (C / 2) + c2a + 4) * T + m0 + col;
            float h0 = bf_hi_val(v0), hq = bf_hi_val(q0);
            oh[ra]     = pack_bf2(h0, hq);
            ol[ra]     = pack_bf2(v0 - h0, q0 - hq);
            h0 = bf_hi_val(v1); hq = bf_hi_val(q1);
            oh[ra + 1] = pack_bf2(h0, hq);
            ol[ra + 1] = pack_bf2(v1 - h0, q1 - hq);
            h0 = bf_hi_val(v2); hq = bf_hi_val(q2);
            oh[rb]     = pack_bf2(h0, hq);
            ol[rb]     = pack_bf2(v2 - h0, q2 - hq);
            h0 = bf_hi_val(v3); hq = bf_hi_val(q3);
            oh[rb + 1] = pack_bf2(h0, hq);
            ol[rb + 1] = pack_bf2(v3 - h0, q3 - hq);
        }
    }
}

// ---------------- final 1-channel projection (4-way channel split) ----------------
__global__ void proj_out(const float* __restrict__ x, const float* __restrict__ w,
                         const float* __restrict__ pb, const float* __restrict__ mask,
                         float* __restrict__ out)
{
    __shared__ float red[256];
    const int tl   = threadIdx.x & 63;     // local t
    const int csub = threadIdx.x >> 6;     // 0..3
    const int t = blockIdx.x * 64 + tl;
    const int b = blockIdx.y;
    const float* xb = x + (size_t)b * C * T;
    float s = 0.f;
    for (int i = 0; i < 128; i++) {
        int c = csub * 128 + i;
        s += w[c] * xb[(size_t)c * T + t];
    }
    red[csub * 64 + tl] = s;
    __syncthreads();
    if (csub == 0) {
        float tot = red[tl] + red[64 + tl] + red[128 + tl] + red[192 + tl] + pb[0];
        out[(size_t)b * T + t] = tot * mask[(size_t)b * T + t];
    }
}

// ---------------- launch ----------------
extern "C" void kernel_launch(void* const* d_in, const int* in_sizes, int n_in,
                              void* d_out, int out_size)
{
    const float* x    = (const float*)d_in[0];
    const float* f0   = (const float*)d_in[1];
    const float* mask = (const float*)d_in[2];
    const float* spk  = (const float*)d_in[3];
    const float* prw  = (const float*)d_in[4];
    const float* prb  = (const float*)d_in[5];
    const float* f0w  = (const float*)d_in[6];
    const float* f0b  = (const float*)d_in[7];
    const float* cw   = (const float*)d_in[8];
    const float* cb   = (const float*)d_in[9];
    const float* pw   = (const float*)d_in[10];
    const float* pb   = (const float*)d_in[11];
    const float* qw   = (const float*)d_in[12];
    const float* qb   = (const float*)d_in[13];
    const float* kw   = (const float*)d_in[14];
    const float* kb   = (const float*)d_in[15];
    const float* vw   = (const float*)d_in[16];
    const float* vb   = (const float*)d_in[17];
    const float* ow   = (const float*)d_in[18];
    const float* ob   = (const float*)d_in[19];
    const float* ln0g = (const float*)d_in[20];
    const float* ln0b = (const float*)d_in[21];
    const float* ln1g = (const float*)d_in[22];
    const float* ln1b = (const float*)d_in[23];
    const float* f1w  = (const float*)d_in[24];
    const float* f1b  = (const float*)d_in[25];
    const float* f2w  = (const float*)d_in[26];
    const float* f2b  = (const float*)d_in[27];
    float* out = (float*)d_out;

    float *gx, *gy;
    uint32_t *wh, *wl, *ah, *al, *bh2, *bl2;
    cudaGetSymbolAddress((void**)&gx,  g_x);
    cudaGetSymbolAddress((void**)&gy,  g_y);
    cudaGetSymbolAddress((void**)&wh,  g_wh);
    cudaGetSymbolAddress((void**)&wl,  g_wl);
    cudaGetSymbolAddress((void**)&ah,  g_ah);
    cudaGetSymbolAddress((void**)&al,  g_al);
    cudaGetSymbolAddress((void**)&bh2, g_bh);
    cudaGetSymbolAddress((void**)&bl2, g_bl);

    uint32_t* qh_ = bh2 + RG_Q;  uint32_t* ql_ = bl2 + RG_Q;
    uint32_t* kh_ = bh2 + RG_K;  uint32_t* kl_ = bl2 + RG_K;
    uint32_t* vh_ = bh2 + RG_V;  uint32_t* vl_ = bl2 + RG_V;
    uint32_t* th_ = bh2 + RG_A;  uint32_t* tl_ = bl2 + RG_A;

    cudaFuncSetAttribute(flash_mma, cudaFuncAttributeMaxDynamicSharedMemorySize, FLASH2_SMEM);
    cudaFuncSetAttribute(add_ln_p, cudaFuncAttributeMaxDynamicSharedMemorySize, LN_SMEM);
    cudaFuncSetAttribute(mma_gemm_p<1,0,false,false,true ,1,0>, cudaFuncAttributeMaxDynamicSharedMemorySize, GEMM_SMEM);
    cudaFuncSetAttribute(mma_gemm_p<3,1,false,true ,false,1,0>, cudaFuncAttributeMaxDynamicSharedMemorySize, GEMM_SMEM);
    cudaFuncSetAttribute(mma_gemm_p<1,0,false,false,false,3,2>, cudaFuncAttributeMaxDynamicSharedMemorySize, GEMM_SMEM);
    cudaFuncSetAttribute(mma_gemm_p<1,0,false,false,false,1,0>, cudaFuncAttributeMaxDynamicSharedMemorySize, GEMM_SMEM);
    cudaFuncSetAttribute(mma_gemm_p<3,2,true ,false,false,1,1>, cudaFuncAttributeMaxDynamicSharedMemorySize, GEMM_SMEM);
    cudaFuncSetAttribute(mma_gemm_p<3,2,false,true ,false,1,0>, cudaFuncAttributeMaxDynamicSharedMemorySize, GEMM_SMEM);

    // ---- pack all weights ----
    pack_w<<<dim3(65536 / 256, 1), 256>>>(cw, 0, OFF_COND, 0, S, 1, 8);
    pack_w<<<dim3(393216 / 256, 1), 256>>>(prw, 0, OFF_PRE, 0, C, 3, 48);
    pack_w<<<dim3(131072 / 256, L), 256>>>(qw, (size_t)C * C, OFF_QKV + 0,      QKV_LSTR, C, 1, 16);
    pack_w<<<dim3(131072 / 256, L), 256>>>(kw, (size_t)C * C, OFF_QKV + 131072, QKV_LSTR, C, 1, 16);
    pack_w<<<dim3(131072 / 256, L), 256>>>(vw, (size_t)C * C, OFF_QKV + 262144, QKV_LSTR, C, 1, 16);
    pack_w<<<dim3(131072 / 256, L), 256>>>(ow, (size_t)C * C, OFF_OUT, OUT_LSTR, C, 1, 16);
    pack_w<<<dim3(1572864 / 256, L), 256>>>(f1w, (size_t)FC * C * 3, OFF_F1, F1_LSTR, C,  3, 48);
    pack_w<<<dim3(1572864 / 256, L), 256>>>(f2w, (size_t)C * FC * 3, OFF_F2, F2_LSTR, FC, 3, 192);

    // ---- prep ----
    split_act<<<dim3(T / 256, S / 2, B), 256>>>(spk, ah, al, S / 2);
    mma_gemm_p<1, 0, false, false, true, 1, 0><<<dim3(T / 128, 4, B), 256, GEMM_SMEM>>>(
        ah, al, wh + OFF_COND, wl + OFF_COND, cb, cb, cb, nullptr, x,
        gy, nullptr, nullptr, nullptr, nullptr, nullptr, nullptr, gy, gy, S, C);
    add_f0<<<dim3(T / 256, C, B), 256>>>(f0, f0w, f0b, gy);
    split_act<<<dim3(T / 256, C / 2, B), 256>>>(gy, ah, al, C / 2);
    mma_gemm_p<3, 1, false, true, false, 1, 0><<<dim3(T / 128, 4, B), 256, GEMM_SMEM>>>(
        ah, al, wh + OFF_PRE, wl + OFF_PRE, prb, prb, prb, mask, nullptr,
        gx, nullptr, nullptr, nullptr, nullptr, nullptr, nullptr, gx, gx, C, C);
    split_act<<<dim3(T / 256, C / 2, B), 256>>>(gx, ah, al, C / 2);

    for (int l = 0; l < L; l++) {
        mma_gemm_p<1, 0, false, false, false, 3, 2><<<dim3(T / 128, 12, B), 256, GEMM_SMEM>>>(
            ah, al, wh + OFF_QKV + (size_t)l * QKV_LSTR, wl + OFF_QKV + (size_t)l * QKV_LSTR,
            qb + l * C, kb + l * C, vb + l * C, nullptr, nullptr,
            nullptr, qh_, ql_, kh_, kl_, vh_, vl_, nullptr, nullptr, C, C);

        flash_mma<<<dim3(T / 64, B * H), 256, FLASH2_SMEM>>>(
            qh_, ql_, kh_, kl_, vh_, vl_, th_, tl_);

        mma_gemm_p<1, 0, false, false, false, 1, 0><<<dim3(T / 128, 4, B), 256, GEMM_SMEM>>>(
            th_, tl_, wh + OFF_OUT + (size_t)l * OUT_LSTR, wl + OFF_OUT + (size_t)l * OUT_LSTR,
            ob + l * C, nullptr, nullptr, nullptr, nullptr,
            gy, nullptr, nullptr, nullptr, nullptr, nullptr, nullptr, nullptr, nullptr, C, C);

        add_ln_p<<<dim3(T / 32, B), dim3(32, 8), LN_SMEM>>>(
            gx, gy, ln0g + l * C, ln0b + l * C, gx, ah, al);

        mma_gemm_p<3, 2, true, false, false, 1, 1><<<dim3(T / 128, FC / 128, B), 256, GEMM_SMEM>>>(
            ah, al, wh + OFF_F1 + (size_t)l * F1_LSTR, wl + OFF_F1 + (size_t)l * F1_LSTR,
            f1b + l * FC, nullptr, nullptr, nullptr, nullptr,
            nullptr, bh2, bl2, nullptr, nullptr, nullptr, nullptr, nullptr, nullptr, C, FC);

        mma_gemm_p<3, 2, false, true, false, 1, 0><<<dim3(T / 128, 4, B), 256, GEMM_SMEM>>>(
            bh2, bl2, wh + OFF_F2 + (size_t)l * F2_LSTR, wl + OFF_F2 + (size_t)l * F2_LSTR,
            f2b + l * C, nullptr, nullptr, mask, nullptr,
            gy, nullptr, nullptr, nullptr, nullptr, nullptr, nullptr, nullptr, nullptr, FC, C);

        add_ln_p<<<dim3(T / 32, B), dim3(32, 8), LN_SMEM>>>(
            gx, gy, ln1g + l * C, ln1b + l * C, gx, ah, al);
    }

    proj_out<<<dim3(T / 64, B), 256>>>(gx, pw, pb, mask, out);
}

// round 12
// speedup vs baseline: 1.5009x; 1.0234x over previous
#include <cuda_runtime.h>
#include <cuda_bf16.h>
#include <cstdint>
#include <cstddef>

// ---------------- problem constants ----------------
static constexpr int B  = 4;
static constexpr int C  = 512;
static constexpr int T  = 2048;
static constexpr int H  = 8;
static constexpr int FC = 2048;
static constexpr int L  = 6;
static constexpr int S  = 256;
static constexpr int DK = 64;

// ---------------- device scratch ----------------
__device__ float g_x [B * C * T];
__device__ float g_y [B * C * T];
__device__ float g_y2[B * C * T];

// packed split weights (hi/lo bf16x2), pretiled [omBlk][chunk][m(128)][k2(16)]
static constexpr size_t OFF_COND = 0;
static constexpr size_t OFF_PRE  = 65536;
static constexpr size_t OFF_QKV  = 458752;
static constexpr size_t QKV_LSTR = 393216;
static constexpr size_t OFF_OUT  = 2818048;
static constexpr size_t OUT_LSTR = 131072;
static constexpr size_t OFF_F1   = 3604480;
static constexpr size_t F1_LSTR  = 1572864;
static constexpr size_t OFF_F2   = 13041664;
static constexpr size_t F2_LSTR  = 1572864;
static constexpr size_t W_TOTAL  = 22478848;

__device__ uint32_t g_wh[W_TOTAL];
__device__ uint32_t g_wl[W_TOTAL];
// packed split activations, ping-pong buffers
__device__ uint32_t g_ah[(size_t)B * (FC / 2) * T];
__device__ uint32_t g_al[(size_t)B * (FC / 2) * T];
__device__ uint32_t g_bh[(size_t)B * (FC / 2) * T];
__device__ uint32_t g_bl[(size_t)B * (FC / 2) * T];

// region offsets inside g_bh/g_bl (words): q, k, vT, attn (2M each)
static constexpr size_t RG_Q = 0;
static constexpr size_t RG_K = 2097152;
static constexpr size_t RG_V = 4194304;
static constexpr size_t RG_A = 6291456;

// ---------------- helpers ----------------
__device__ __forceinline__ uint32_t pack_bf2(float a, float b) {
    uint32_t r;
    asm("cvt.rn.bf16x2.f32 %0, %1, %2;" : "=r"(r) : "f"(b), "f"(a));
    return r;
}
__device__ __forceinline__ float bf_hi_val(float v) {
    __nv_bfloat16 h = __float2bfloat16_rn(v);
    return __bfloat162float(h);
}
__device__ __forceinline__ void mma_bf16(float* d, const uint32_t* a, const uint32_t* b) {
    asm volatile("mma.sync.aligned.m16n8k16.row.col.f32.bf16.bf16.f32 "
        "{%0,%1,%2,%3}, {%4,%5,%6,%7}, {%8,%9}, {%0,%1,%2,%3};"
        : "+f"(d[0]), "+f"(d[1]), "+f"(d[2]), "+f"(d[3])
        : "r"(a[0]), "r"(a[1]), "r"(a[2]), "r"(a[3]), "r"(b[0]), "r"(b[1]));
}
__device__ __forceinline__ uint32_t smem_u32(const void* p) {
    uint32_t a;
    asm("{ .reg .u64 t; cvta.to.shared.u64 t, %1; cvt.u32.u64 %0, t; }" : "=r"(a) : "l"(p));
    return a;
}
__device__ __forceinline__ void ldm4(uint32_t* r, uint32_t addr) {
    asm volatile("ldmatrix.sync.aligned.m8n8.x4.shared.b16 {%0,%1,%2,%3}, [%4];"
        : "=r"(r[0]), "=r"(r[1]), "=r"(r[2]), "=r"(r[3]) : "r"(addr));
}
__device__ __forceinline__ void cp16(uint32_t dst, const void* src) {
    asm volatile("cp.async.cg.shared.global [%0], [%1], 16;" :: "r"(dst), "l"(src));
}
__device__ __forceinline__ void cp8(uint32_t dst, const void* src) {
    asm volatile("cp.async.ca.shared.global [%0], [%1], 8;" :: "r"(dst), "l"(src));
}
__device__ __forceinline__ void cp4z(uint32_t dst, const void* src, int srcsz) {
    asm volatile("cp.async.ca.shared.global [%0], [%1], 4, %2;"
                 :: "r"(dst), "l"(src), "r"(srcsz));
}
__device__ __forceinline__ void cp_commit() {
    asm volatile("cp.async.commit_group;" ::: "memory");
}
template <int N>
__device__ __forceinline__ void cp_wait() {
    asm volatile("cp.async.wait_group %0;" :: "n"(N) : "memory");
}

// ---------------- weight packing ----------------
__global__ void pack_w(const float* __restrict__ src, size_t src_lstride,
                       size_t dst_base, size_t dst_lstride,
                       int Cin, int KW, int chunks)
{
    const int l = blockIdx.y;
    const int w = blockIdx.x * 256 + threadIdx.x;
    const int per_blk = chunks * 2048;
    const int omBlk = w / per_blk;
    const int r  = w % per_blk;
    const int ch = r / 2048, r2 = r % 2048;
    const int m  = r2 >> 4;
    const int k2 = ch * 16 + (r2 & 15);
    int ka, kb;
    if (KW == 1) { ka = 2 * k2; kb = ka + 1; }
    else { int half = Cin >> 1; int c2 = k2 % half, kk = k2 / half;
           ka = (2 * c2) * KW + kk; kb = ka + KW; }
    const float* s = src + (size_t)l * src_lstride + (size_t)(omBlk * 128 + m) * Cin * KW;
    float va = s[ka], vb = s[kb];
    float ha = bf_hi_val(va), hb = bf_hi_val(vb);
    size_t d = dst_base + (size_t)l * dst_lstride + w;
    g_wh[d] = pack_bf2(ha, hb);
    g_wl[d] = pack_bf2(va - ha, vb - hb);
}

// ---------------- activation split/pack (prep only) ----------------
__global__ void split_act(const float* __restrict__ X, uint32_t* __restrict__ Xh,
                          uint32_t* __restrict__ Xl, int Chalf)
{
    const int t  = blockIdx.x * 256 + threadIdx.x;
    const int c2 = blockIdx.y;
    const int b  = blockIdx.z;
    const float* x0 = X + ((size_t)b * 2 * Chalf + 2 * c2) * T;
    float va = x0[t], vb = x0[T + t];
    float ha = bf_hi_val(va), hb = bf_hi_val(vb);
    size_t d = ((size_t)b * Chalf + c2) * T + t;
    Xh[d] = pack_bf2(ha, hb);
    Xl[d] = pack_bf2(va - ha, vb - hb);
}

// ================= cp.async pipelined bf16x2-split mma.sync conv-GEMM =================
static constexpr int ASTR = 20;
static constexpr int KSTR = 136;
static constexpr int A_WORDS = 128 * ASTR;
static constexpr int B_WORDS = 16 * KSTR;
static constexpr int STG_WORDS = 2 * A_WORDS + 2 * B_WORDS;
static constexpr int GEMM_SMEM = 2 * STG_WORDS * 4;

// OMODE: 0 = float out, 1 = channel-pair packed out, 2 = QKV (sel0/1 packout, sel2 vpackt)
// KSPLIT: 1 = full K per CTA; 2 = K split in halves (NOUT==1, OMODE==0 only;
//         half 0 adds bias -> Y0, half 1 raw partial -> Y1)
template <int KW, int PL, bool RELU, bool DOMASK, bool ADDSRC, int NOUT, int OMODE, int KSPLIT>
__global__ __launch_bounds__(256, 2) void mma_gemm_p(
    const uint32_t* __restrict__ Xh, const uint32_t* __restrict__ Xl,
    const uint32_t* __restrict__ Wh, const uint32_t* __restrict__ Wl,
    const float* __restrict__ b0, const float* __restrict__ b1, const float* __restrict__ b2,
    const float* __restrict__ mask, const float* __restrict__ src,
    float* __restrict__ Y0,
    uint32_t* __restrict__ poh,  uint32_t* __restrict__ pol,
    uint32_t* __restrict__ poh2, uint32_t* __restrict__ pol2,
    uint32_t* __restrict__ poh3, uint32_t* __restrict__ pol3,
    float* __restrict__ Y1, float* __restrict__ Y2,
    int Cin, int Cout)
{
    extern __shared__ uint32_t dsm[];
    const uint32_t sbase = smem_u32(dsm);

    const int tid  = threadIdx.x;
    const int lane = tid & 31;
    const int wid  = tid >> 5;
    const int mw   = wid & 1;
    const int nw   = wid >> 1;
    const int gid  = lane >> 2;
    const int tig  = lane & 3;

    const int b   = blockIdx.z;
    const int tn0 = blockIdx.x * 128;
    int sel, om, omIdx, khalf;
    if (NOUT == 3)      { sel = blockIdx.y >> 2; omIdx = blockIdx.y & 3; khalf = 0; }
    else if (KSPLIT==2) { sel = 0; omIdx = blockIdx.y & 3; khalf = blockIdx.y >> 2; }
    else                { sel = 0; omIdx = blockIdx.y; khalf = 0; }
    om = omIdx * 128;
    const float* bias = (NOUT == 3) ? (sel == 0 ? b0 : sel == 1 ? b1 : b2) : b0;
    float* Y;
    if (NOUT == 3)      Y = (sel == 0 ? Y0 : sel == 1 ? Y1 : Y2);
    else if (KSPLIT==2) Y = khalf ? Y1 : Y0;
    else                Y = Y0;

    const int Chalf  = Cin >> 1;
    const int chunksT = (Cin * KW) >> 5;
    const int chunks  = (KSPLIT == 2) ? (chunksT >> 1) : chunksT;
    const int kbase   = khalf * chunks;
    const int wblk = (NOUT == 3) ? blockIdx.y : omIdx;
    const uint32_t* wtH = Wh + (size_t)wblk * chunksT * 2048 + (size_t)kbase * 2048;
    const uint32_t* wtL = Wl + (size_t)wblk * chunksT * 2048 + (size_t)kbase * 2048;
    const uint32_t* XhB = Xh + (size_t)b * Chalf * T;
    const uint32_t* XlB = Xl + (size_t)b * Chalf * T;

    const int lm  = tid >> 1;
    const int lh  = tid & 1;
    const int lk2 = tid >> 4;
    const int lq  = tid & 15;

    const int qq   = lane >> 3;
    const int rrow = lane & 7;
    const uint32_t laneOff = ((uint32_t)((mw * 64 + (qq & 1) * 8 + rrow) * ASTR
                             + (qq >> 1) * 4)) * 4u;

    auto issueA = [&](int ch, int s) {
        const uint32_t* aH = wtH + ch * 2048 + lm * 16 + lh * 8;
        const uint32_t* aL = wtL + ch * 2048 + lm * 16 + lh * 8;
        uint32_t d = sbase + (uint32_t)(s * STG_WORDS + lm * ASTR + lh * 8) * 4u;
        cp16(d, aH);
        cp16(d + 16, aH + 4);
        cp16(d + A_WORDS * 4, aL);
        cp16(d + A_WORDS * 4 + 16, aL + 4);
    };
    auto issueB = [&](int ch, int s) {
        const int k2g = (kbase + ch) * 16 + lk2;
        uint32_t dh = sbase + (uint32_t)(s * STG_WORDS + 2 * A_WORDS + lk2 * KSTR + lq * 8) * 4u;
        uint32_t dl = dh + B_WORDS * 4;
        if (KW == 1) {
            const uint32_t* rH = XhB + (size_t)k2g * T + tn0 + lq * 8;
            const uint32_t* rL = XlB + (size_t)k2g * T + tn0 + lq * 8;
            cp16(dh, rH); cp16(dh + 16, rH + 4);
            cp16(dl, rL); cp16(dl + 16, rL + 4);
        } else {
            const int c2 = k2g % Chalf;
            const int kk = k2g / Chalf;
            const int dt = kk - PL;
            const uint32_t* rH = XhB + (size_t)c2 * T;
            const uint32_t* rL = XlB + (size_t)c2 * T;
            const int t0 = tn0 + lq * 8 + dt;
            if (dt == 0) {
                cp16(dh, rH + t0); cp16(dh + 16, rH + t0 + 4);
                cp16(dl, rL + t0); cp16(dl + 16, rL + t0 + 4);
            } else if (t0 >= 0 && t0 + 8 <= T) {
                if ((dt & 1) == 0) {
#pragma unroll
                    for (int j = 0; j < 4; j++) {
                        cp8(dh + j * 8, rH + t0 + j * 2);
                        cp8(dl + j * 8, rL + t0 + j * 2);
                    }
                } else {
#pragma unroll
                    for (int j = 0; j < 8; j++) {
                        cp4z(dh + j * 4, rH + t0 + j, 4);
                        cp4z(dl + j * 4, rL + t0 + j, 4);
                    }
                }
            } else {
#pragma unroll
                for (int j = 0; j < 8; j++) {
                    int t = t0 + j;
                    bool ok = (unsigned)t < (unsigned)T;
                    int tc = ok ? t : 0;
                    int sz = ok ? 4 : 0;
                    cp4z(dh + j * 4, rH + tc, sz);
                    cp4z(dl + j * 4, rL + tc, sz);
                }
            }
        }
    };

    float acc[4][4][4];
#pragma unroll
    for (int i = 0; i < 4; i++)
#pragma unroll
        for (int j = 0; j < 4; j++)
#pragma unroll
            for (int r = 0; r < 4; r++) acc[i][j][r] = 0.f;

    issueA(0, 0); issueB(0, 0); cp_commit();

    for (int ch = 0; ch < chunks; ch++) {
        const int s = ch & 1;
        if (ch + 1 < chunks) {
            issueA(ch + 1, s ^ 1); issueB(ch + 1, s ^ 1); cp_commit();
            cp_wait<1>();
        } else {
            cp_wait<0>();
        }
        __syncthreads();

        const uint32_t aAh = sbase + (uint32_t)(s * STG_WORDS) * 4u;
        const uint32_t aAl = aAh + A_WORDS * 4u;
        const uint32_t* BhS = dsm + s * STG_WORDS + 2 * A_WORDS;
        const uint32_t* BlS = BhS + B_WORDS;

#pragma unroll
        for (int ks = 0; ks < 2; ks++) {
            const int k2a = ks * 8 + tig;
            const int k2b = ks * 8 + 4 + tig;
            uint32_t bfh[4][2], bfl[4][2];
#pragma unroll
            for (int nt = 0; nt < 4; nt++) {
                int n = nw * 32 + nt * 8 + gid;
                bfh[nt][0] = BhS[k2a * KSTR + n];
                bfh[nt][1] = BhS[k2b * KSTR + n];
                bfl[nt][0] = BlS[k2a * KSTR + n];
                bfl[nt][1] = BlS[k2b * KSTR + n];
            }
#pragma unroll
            for (int mt = 0; mt < 4; mt++) {
                uint32_t afh[4], afl[4];
                const uint32_t off = laneOff + (uint32_t)(mt * 16 * ASTR + ks * 8) * 4u;
                ldm4(afh, aAh + off);
                ldm4(afl, aAl + off);
#pragma unroll
                for (int nt = 0; nt < 4; nt++) {
                    mma_bf16(acc[mt][nt], afh, bfh[nt]);
                    mma_bf16(acc[mt][nt], afh, bfl[nt]);
                    mma_bf16(acc[mt][nt], afl, bfh[nt]);
                }
            }
        }
        __syncthreads();
    }

    // ---- epilogue ----
    const int ChalfO = Cout >> 1;
    uint32_t* th = poh; uint32_t* tl = pol;
    if (OMODE == 2 && sel == 1) { th = poh2; tl = pol2; }
#pragma unroll
    for (int mt = 0; mt < 4; mt++) {
        int o0 = om + mw * 64 + mt * 16 + gid;
        float bb0 = (KSPLIT == 2 && khalf) ? 0.f : bias[o0];
        float bb1 = (KSPLIT == 2 && khalf) ? 0.f : bias[o0 + 8];
#pragma unroll
        for (int nt = 0; nt < 4; nt++) {
            int t0 = tn0 + nw * 32 + nt * 8 + 2 * tig;
            float v0 = acc[mt][nt][0] + bb0;
            float v1 = acc[mt][nt][1] + bb0;
            float v2 = acc[mt][nt][2] + bb1;
            float v3 = acc[mt][nt][3] + bb1;
            if (RELU) {
                v0 = fmaxf(v0, 0.f); v1 = fmaxf(v1, 0.f);
                v2 = fmaxf(v2, 0.f); v3 = fmaxf(v3, 0.f);
            }
            if (OMODE == 2 && sel == 2) {
                size_t ia = ((size_t)b * Cout + o0)     * (T / 2) + (t0 >> 1);
                size_t ib = ((size_t)b * Cout + o0 + 8) * (T / 2) + (t0 >> 1);
                float h0 = bf_hi_val(v0), h1 = bf_hi_val(v1);
                poh3[ia] = pack_bf2(h0, h1);
                pol3[ia] = pack_bf2(v0 - h0, v1 - h1);
                h0 = bf_hi_val(v2); h1 = bf_hi_val(v3);
                poh3[ib] = pack_bf2(h0, h1);
                pol3[ib] = pack_bf2(v2 - h0, v3 - h1);
            } else if (OMODE == 1 || OMODE == 2) {
                float q0 = __shfl_xor_sync(0xffffffffu, v0, 4);
                float q1 = __shfl_xor_sync(0xffffffffu, v1, 4);
                float q2 = __shfl_xor_sync(0xffffffffu, v2, 4);
                float q3 = __shfl_xor_sync(0xffffffffu, v3, 4);
                if ((gid & 1) == 0) {
                    size_t da = ((size_t)b * ChalfO + (o0 >> 1)) * T + t0;
                    size_t db = ((size_t)b * ChalfO + ((o0 + 8) >> 1)) * T + t0;
                    float h;
                    h = bf_hi_val(v0); float hq = bf_hi_val(q0);
                    th[da]     = pack_bf2(h, hq);
                    tl[da]     = pack_bf2(v0 - h, q0 - hq);
                    h = bf_hi_val(v1); hq = bf_hi_val(q1);
                    th[da + 1] = pack_bf2(h, hq);
                    tl[da + 1] = pack_bf2(v1 - h, q1 - hq);
                    h = bf_hi_val(v2); hq = bf_hi_val(q2);
                    th[db]     = pack_bf2(h, hq);
                    tl[db]     = pack_bf2(v2 - h, q2 - hq);
                    h = bf_hi_val(v3); hq = bf_hi_val(q3);
                    th[db + 1] = pack_bf2(h, hq);
                    tl[db + 1] = pack_bf2(v3 - h, q3 - hq);
                }
            } else {
                float m0v = 1.f, m1v = 1.f;
                if (DOMASK) {
                    m0v = mask[(size_t)b * T + t0];
                    m1v = mask[(size_t)b * T + t0 + 1];
                }
                size_t oi0 = ((size_t)b * Cout + o0)     * T + t0;
                size_t oi1 = ((size_t)b * Cout + o0 + 8) * T + t0;
                if (ADDSRC) {
                    float2 s0 = *(const float2*)(src + oi0);
                    float2 s1 = *(const float2*)(src + oi1);
                    v0 += s0.x; v1 += s0.y; v2 += s1.x; v3 += s1.y;
                }
                if (DOMASK) { v0 *= m0v; v1 *= m1v; v2 *= m0v; v3 *= m1v; }
                *(float2*)(Y + oi0) = make_float2(v0, v1);
                *(float2*)(Y + oi1) = make_float2(v2, v3);
            }
        }
    }
}

// ---------------- f0 prenet added in-place ----------------
__global__ void add_f0(const float* __restrict__ f0, const float* __restrict__ w,
                       const float* __restrict__ fb, float* __restrict__ y)
{
    int t = blockIdx.x * 256 + threadIdx.x;
    int c = blockIdx.y;
    int b = blockIdx.z;
    float fm1 = (t - 1 >= 0) ? f0[(size_t)b * T + t - 1] : 0.f;
    float fc0 = f0[(size_t)b * T + t];
    float fp1 = (t + 1 < T) ? f0[(size_t)b * T + t + 1] : 0.f;
    float v = w[c * 3 + 0] * fm1 + w[c * 3 + 1] * fc0 + w[c * 3 + 2] * fp1 + fb[c];
    y[((size_t)b * C + c) * T + t] += v;
}

// ---------------- fused residual-add + LayerNorm + packed split output ----------------
// y_total = (y + y2?) * mask?; v = x + y_total; LN over channels.
static constexpr int LN_SMEM = (512 * 32 + 256 + 256 + 64) * 4;

template <bool TWOY, bool YMASK>
__global__ void add_ln_p(const float* __restrict__ x, const float* __restrict__ y,
                         const float* __restrict__ y2, const float* __restrict__ maskt,
                         const float* __restrict__ g, const float* __restrict__ be,
                         float* __restrict__ out,
                         uint32_t* __restrict__ ph, uint32_t* __restrict__ pl)
{
    extern __shared__ float lns[];
    float* cache = lns;                 // [c][tx] stride 32
    float* red0  = lns + 512 * 32;
    float* red1  = red0 + 256;
    float* smv   = red1 + 256;
    const int tx = threadIdx.x, ty = threadIdx.y;
    const int t = blockIdx.x * 32 + tx;
    const int b = blockIdx.y;
    const size_t base = (size_t)b * C * T + t;
    const float mv = YMASK ? maskt[(size_t)b * T + t] : 1.f;

    float s = 0.f, sq = 0.f;
    for (int c2 = ty; c2 < C / 2; c2 += 8) {
        size_t i0 = base + (size_t)(2 * c2) * T;
        float yv0 = y[i0],     yv1 = y[i0 + T];
        if (TWOY) { yv0 += y2[i0]; yv1 += y2[i0 + T]; }
        if (YMASK) { yv0 *= mv; yv1 *= mv; }
        float v0 = x[i0] + yv0;
        float v1 = x[i0 + T] + yv1;
        cache[(2 * c2) * 32 + tx]     = v0;
        cache[(2 * c2 + 1) * 32 + tx] = v1;
        s += v0 + v1; sq += v0 * v0 + v1 * v1;
    }
    red0[ty * 32 + tx] = s; red1[ty * 32 + tx] = sq;
    __syncthreads();
    if (ty == 0) {
#pragma unroll
        for (int i = 1; i < 8; i++) { s += red0[i * 32 + tx]; sq += red1[i * 32 + tx]; }
        float mean = s * (1.f / C);
        float var  = sq * (1.f / C) - mean * mean;
        smv[tx]      = mean;
        smv[32 + tx] = rsqrtf(var + 1e-5f);
    }
    __syncthreads();
    float mean = smv[tx], rstd = smv[32 + tx];
    for (int c2 = ty; c2 < C / 2; c2 += 8) {
        size_t i0 = base + (size_t)(2 * c2) * T;
        float v0 = (cache[(2 * c2) * 32 + tx]     - mean) * rstd * g[2 * c2]     + be[2 * c2];
        float v1 = (cache[(2 * c2 + 1) * 32 + tx] - mean) * rstd * g[2 * c2 + 1] + be[2 * c2 + 1];
        out[i0]     = v0;
        out[i0 + T] = v1;
        float h0 = bf_hi_val(v0), h1 = bf_hi_val(v1);
        size_t d = ((size_t)b * (C / 2) + c2) * T + t;
        ph[d] = pack_bf2(h0, h1);
        pl[d] = pack_bf2(v0 - h0, v1 - h1);
    }
}

// ================= tensor-core causal flash attention (2 CTA/SM) =================
static constexpr int FQH = 0;
static constexpr int FQL = 2304;
static constexpr int FKH0 = 4608;
static constexpr int FVH  = 13824;
static constexpr int FSS  = 18432;
static constexpr int FPH  = 22784;
static constexpr int FPL  = 25088;
static constexpr int FCORR = 27392;
static constexpr int FMST  = 27456;
static constexpr int FLST  = 27520;
static constexpr int FLASH2_WORDS = 27584;
static constexpr int FLASH2_SMEM = FLASH2_WORDS * 4;

__global__ __launch_bounds__(256, 2) void flash_mma(
    const uint32_t* __restrict__ qh, const uint32_t* __restrict__ ql,
    const uint32_t* __restrict__ kh, const uint32_t* __restrict__ kl,
    const uint32_t* __restrict__ vh, const uint32_t* __restrict__ vl,
    uint32_t* __restrict__ oh, uint32_t* __restrict__ ol)
{
    extern __shared__ uint32_t fs[];
    float* fsf = (float*)fs;
    const uint32_t sb = smem_u32(fs);

    const int tid  = threadIdx.x;
    const int lane = tid & 31;
    const int wid  = tid >> 5;
    const int gid  = lane >> 2;
    const int tig  = lane & 3;
    const int wm   = wid & 3;
    const int wn   = wid >> 2;
    const int mbase = wm * 16;
    const int nbase = wn * 32;

    const int mb = (int)gridDim.x - 1 - (int)blockIdx.x;
    const int m0 = mb * 64;
    const int bhh = blockIdx.y;
    const int b = bhh >> 3;
    const int h = bhh & 7;

    const uint32_t* qhB = qh + ((size_t)b * (C / 2) + h * 32) * T + m0;
    const uint32_t* qlB = ql + ((size_t)b * (C / 2) + h * 32) * T + m0;
    const uint32_t* khB = kh + ((size_t)b * (C / 2) + h * 32) * T;
    const uint32_t* klB = kl + ((size_t)b * (C / 2) + h * 32) * T;
    const uint32_t* vhB = vh + ((size_t)b * C + h * 64) * (T / 2);
    const uint32_t* vlB = vl + ((size_t)b * C + h * 64) * (T / 2);

    if (tid < 64) { fsf[FMST + tid] = -1e30f; fsf[FLST + tid] = 0.f; }

    {
        int selq = tid >> 7, r = tid & 127, k2 = r >> 2, cq = (r & 3) * 4;
        const uint32_t* src = (selq ? qlB : qhB) + (size_t)k2 * T;
        uint32_t dst = sb + (uint32_t)((selq ? FQL : FQH) + k2 * 72) * 4u;
#pragma unroll
        for (int i = 0; i < 4; i++) cp16(dst + (cq + i) * 16, src + (cq + i) * 4);
    }
    auto loadK = [&](int kbk, int s) {
        const int kn0 = kbk * 64;
        int selq = tid >> 7, r = tid & 127, k2 = r >> 2, cq = (r & 3) * 4;
        const uint32_t* src = (selq ? klB : khB) + (size_t)k2 * T + kn0;
        uint32_t dst = sb + (uint32_t)(FKH0 + s * 4608 + selq * 2304 + k2 * 72) * 4u;
#pragma unroll
        for (int i = 0; i < 4; i++) cp16(dst + (cq + i) * 16, src + (cq + i) * 4);
    };
    auto loadV = [&](int kbk) {
        const int kn0 = kbk * 64;
        int selq = tid >> 7, r = tid & 127, d = r >> 1, cq = (r & 1) * 4;
        const uint32_t* src = (selq ? vlB : vhB) + (size_t)d * (T / 2) + (kn0 >> 1);
        uint32_t dst = sb + (uint32_t)(FVH + selq * 2304 + d * 36) * 4u;
#pragma unroll
        for (int i = 0; i < 4; i++) cp16(dst + (cq + i) * 16, src + (cq + i) * 4);
    };
    loadK(0, 0); cp_commit();

    float oacc[4][4];
#pragma unroll
    for (int i = 0; i < 4; i++)
#pragma unroll
        for (int j = 0; j < 4; j++) oacc[i][j] = 0.f;

    for (int kbk = 0; kbk <= mb; kbk++) {
        const int s = kbk & 1;
        const int kn0 = kbk * 64;
        cp_wait<0>();
        __syncthreads();
        loadV(kbk); cp_commit();
        if (kbk < mb) { loadK(kbk + 1, s ^ 1); cp_commit(); }

        const uint32_t* Qh_ = fs + FQH;
        const uint32_t* Ql_ = fs + FQL;
        const uint32_t* Kh_ = fs + FKH0 + s * 4608;
        const uint32_t* Kl_ = Kh_ + 2304;
        const uint32_t* Vh_ = fs + FVH;
        const uint32_t* Vl_ = Vh_ + 2304;

        float sacc[4][4];
#pragma unroll
        for (int i = 0; i < 4; i++)
#pragma unroll
            for (int j = 0; j < 4; j++) sacc[i][j] = 0.f;

#pragma unroll
        for (int kt = 0; kt < 4; kt++) {
            const int k2a = kt * 8 + tig;
            const int k2b = k2a + 4;
            const int mq = mbase + gid;
            uint32_t aqh[4] = { Qh_[k2a * 72 + mq], Qh_[k2a * 72 + mq + 8],
                                Qh_[k2b * 72 + mq], Qh_[k2b * 72 + mq + 8] };
            uint32_t aql[4] = { Ql_[k2a * 72 + mq], Ql_[k2a * 72 + mq + 8],
                                Ql_[k2b * 72 + mq], Ql_[k2b * 72 + mq + 8] };
#pragma unroll
            for (int nt = 0; nt < 4; nt++) {
                int n = nbase + nt * 8 + gid;
                uint32_t bkh[2] = { Kh_[k2a * 72 + n], Kh_[k2b * 72 + n] };
                uint32_t bkl[2] = { Kl_[k2a * 72 + n], Kl_[k2b * 72 + n] };
                mma_bf16(sacc[nt], aqh, bkh);
                mma_bf16(sacc[nt], aqh, bkl);
                mma_bf16(sacc[nt], aql, bkh);
            }
        }
#pragma unroll
        for (int nt = 0; nt < 4; nt++) {
            int col = nbase + nt * 8 + 2 * tig;
            int r0 = mbase + gid;
            *(float2*)&fsf[FSS + r0 * 68 + col]       = make_float2(sacc[nt][0], sacc[nt][1]);
            *(float2*)&fsf[FSS + (r0 + 8) * 68 + col] = make_float2(sacc[nt][2], sacc[nt][3]);
        }
        __syncthreads();

#pragma unroll
        for (int r = 0; r < 8; r++) {
            int q = wid * 8 + r;
            int tq = m0 + q;
            float s0 = fsf[FSS + q * 68 + lane] * 0.125f;
            float s1 = fsf[FSS + q * 68 + lane + 32] * 0.125f;
            if (kn0 + lane      > tq) s0 = -1e4f;
            if (kn0 + lane + 32 > tq) s1 = -1e4f;
            float mx = fmaxf(s0, s1);
#pragma unroll
            for (int off = 16; off; off >>= 1)
                mx = fmaxf(mx, __shfl_xor_sync(0xffffffffu, mx, off));
            float mold = fsf[FMST + q];
            float mnew = fmaxf(mold, mx);
            float p0 = __expf(s0 - mnew);
            float p1 = __expf(s1 - mnew);
            float ps = p0 + p1;
#pragma unroll
            for (int off = 16; off; off >>= 1)
                ps += __shfl_xor_sync(0xffffffffu, ps, off);
            float corrv = __expf(mold - mnew);
            if (lane == 0) {
                fsf[FMST + q]  = mnew;
                fsf[FLST + q]  = fsf[FLST + q] * corrv + ps;
                fsf[FCORR + q] = corrv;
            }
            float p0p = __shfl_xor_sync(0xffffffffu, p0, 1);
            float p1p = __shfl_xor_sync(0xffffffffu, p1, 1);
            if ((lane & 1) == 0) {
                int k2 = lane >> 1;
                float h0 = bf_hi_val(p0), h1 = bf_hi_val(p0p);
                fs[FPH + k2 * 72 + q] = pack_bf2(h0, h1);
                fs[FPL + k2 * 72 + q] = pack_bf2(p0 - h0, p0p - h1);
                h0 = bf_hi_val(p1); h1 = bf_hi_val(p1p);
                fs[FPH + (k2 + 16) * 72 + q] = pack_bf2(h0, h1);
                fs[FPL + (k2 + 16) * 72 + q] = pack_bf2(p1 - h0, p1p - h1);
            }
        }
        __syncthreads();
        if (kbk < mb) cp_wait<1>(); else cp_wait<0>();
        __syncthreads();

#pragma unroll
        for (int nt = 0; nt < 4; nt++) {
            int col = nbase + nt * 8 + 2 * tig;
            float c0 = fsf[FCORR + col];
            float c1 = fsf[FCORR + col + 1];
            oacc[nt][0] *= c0; oacc[nt][1] *= c1;
            oacc[nt][2] *= c0; oacc[nt][3] *= c1;
        }
#pragma unroll
        for (int kt = 0; kt < 4; kt++) {
            const int k2a = kt * 8 + tig;
            const int k2b = k2a + 4;
            const int md = mbase + gid;
            uint32_t avh[4] = { Vh_[md * 36 + k2a], Vh_[(md + 8) * 36 + k2a],
                                Vh_[md * 36 + k2b], Vh_[(md + 8) * 36 + k2b] };
            uint32_t avl[4] = { Vl_[md * 36 + k2a], Vl_[(md + 8) * 36 + k2a],
                                Vl_[md * 36 + k2b], Vl_[(md + 8) * 36 + k2b] };
#pragma unroll
            for (int nt = 0; nt < 4; nt++) {
                int n = nbase + nt * 8 + gid;
                uint32_t bph[2] = { fs[FPH + k2a * 72 + n], fs[FPH + k2b * 72 + n] };
                uint32_t bpl[2] = { fs[FPL + k2a * 72 + n], fs[FPL + k2b * 72 + n] };
                mma_bf16(oacc[nt], avh, bph);
                mma_bf16(oacc[nt], avh, bpl);
                mma_bf16(oacc[nt], avl, bph);
            }
        }
    }

#pragma unroll
    for (int nt = 0; nt < 4; nt++) {
        int col = nbase + nt * 8 + 2 * tig;
        float i0 = 1.f / fsf[FLST + col];
        float i1 = 1.f / fsf[FLST + col + 1];
        float v0 = oacc[nt][0] * i0;
        float v1 = oacc[nt][1] * i1;
        float v2 = oacc[nt][2] * i0;
        float v3 = oacc[nt][3] * i1;
        float q0 = __shfl_xor_sync(0xffffffffu, v0, 4);
        float q1 = __shfl_xor_sync(0xffffffffu, v1, 4);
        float q2 = __shfl_xor_sync(0xffffffffu, v2, 4);
        float q3 = __shfl_xor_sync(0xffffffffu, v3, 4);
        if ((gid & 1) == 0) {
            int d0 = h * 64 + mbase + gid;
            int c2a = d0 >> 1;
            size_t ra = ((size_t)b * (C / 2) + c2a) * T + m0 + col;
            size_t rb = ((size_t)b * (C / 2) + c2a + 4) * T + m0 + col;
            float h0 = bf_hi_val(v0), hq = bf_hi_val(q0);
            oh[ra]     = pack_bf2(h0, hq);
            ol[ra]     = pack_bf2(v0 - h0, q0 - hq);
            h0 = bf_hi_val(v1); hq = bf_hi_val(q1);
            oh[ra + 1] = pack_bf2(h0, hq);
            ol[ra + 1] = pack_bf2(v1 - h0, q1 - hq);
            h0 = bf_hi_val(v2); hq = bf_hi_val(q2);
            oh[rb]     = pack_bf2(h0, hq);
            ol[rb]     = pack_bf2(v2 - h0, q2 - hq);
            h0 = bf_hi_val(v3); hq = bf_hi_val(q3);
            oh[rb + 1] = pack_bf2(h0, hq);
            ol[rb + 1] = pack_bf2(v3 - h0, q3 - hq);
        }
    }
}

// ---------------- final 1-channel projection (4-way channel split) ----------------
__global__ void proj_out(const float* __restrict__ x, const float* __restrict__ w,
                         const float* __restrict__ pb, const float* __restrict__ mask,
                         float* __restrict__ out)
{
    __shared__ float red[256];
    const int tl   = threadIdx.x & 63;
    const int csub = threadIdx.x >> 6;
    const int t = blockIdx.x * 64 + tl;
    const int b = blockIdx.y;
    const float* xb = x + (size_t)b * C * T;
    float s = 0.f;
    for (int i = 0; i < 128; i++) {
        int c = csub * 128 + i;
        s += w[c] * xb[(size_t)c * T + t];
    }
    red[csub * 64 + tl] = s;
    __syncthreads();
    if (csub == 0) {
        float tot = red[tl] + red[64 + tl] + red[128 + tl] + red[192 + tl] + pb[0];
        out[(size_t)b * T + t] = tot * mask[(size_t)b * T + t];
    }
}

// ---------------- launch ----------------
extern "C" void kernel_launch(void* const* d_in, const int* in_sizes, int n_in,
                              void* d_out, int out_size)
{
    const float* x    = (const float*)d_in[0];
    const float* f0   = (const float*)d_in[1];
    const float* mask = (const float*)d_in[2];
    const float* spk  = (const float*)d_in[3];
    const float* prw  = (const float*)d_in[4];
    const float* prb  = (const float*)d_in[5];
    const float* f0w  = (const float*)d_in[6];
    const float* f0b  = (const float*)d_in[7];
    const float* cw   = (const float*)d_in[8];
    const float* cb   = (const float*)d_in[9];
    const float* pw   = (const float*)d_in[10];
    const float* pb   = (const float*)d_in[11];
    const float* qw   = (const float*)d_in[12];
    const float* qb   = (const float*)d_in[13];
    const float* kw   = (const float*)d_in[14];
    const float* kb   = (const float*)d_in[15];
    const float* vw   = (const float*)d_in[16];
    const float* vb   = (const float*)d_in[17];
    const float* ow   = (const float*)d_in[18];
    const float* ob   = (const float*)d_in[19];
    const float* ln0g = (const float*)d_in[20];
    const float* ln0b = (const float*)d_in[21];
    const float* ln1g = (const float*)d_in[22];
    const float* ln1b = (const float*)d_in[23];
    const float* f1w  = (const float*)d_in[24];
    const float* f1b  = (const float*)d_in[25];
    const float* f2w  = (const float*)d_in[26];
    const float* f2b  = (const float*)d_in[27];
    float* out = (float*)d_out;

    float *gx, *gy, *gy2;
    uint32_t *wh, *wl, *ah, *al, *bh2, *bl2;
    cudaGetSymbolAddress((void**)&gx,  g_x);
    cudaGetSymbolAddress((void**)&gy,  g_y);
    cudaGetSymbolAddress((void**)&gy2, g_y2);
    cudaGetSymbolAddress((void**)&wh,  g_wh);
    cudaGetSymbolAddress((void**)&wl,  g_wl);
    cudaGetSymbolAddress((void**)&ah,  g_ah);
    cudaGetSymbolAddress((void**)&al,  g_al);
    cudaGetSymbolAddress((void**)&bh2, g_bh);
    cudaGetSymbolAddress((void**)&bl2, g_bl);

    uint32_t* qh_ = bh2 + RG_Q;  uint32_t* ql_ = bl2 + RG_Q;
    uint32_t* kh_ = bh2 + RG_K;  uint32_t* kl_ = bl2 + RG_K;
    uint32_t* vh_ = bh2 + RG_V;  uint32_t* vl_ = bl2 + RG_V;
    uint32_t* th_ = bh2 + RG_A;  uint32_t* tl_ = bl2 + RG_A;

    cudaFuncSetAttribute(flash_mma, cudaFuncAttributeMaxDynamicSharedMemorySize, FLASH2_SMEM);
    cudaFuncSetAttribute(add_ln_p<true,false>, cudaFuncAttributeMaxDynamicSharedMemorySize, LN_SMEM);
    cudaFuncSetAttribute(add_ln_p<true,true >, cudaFuncAttributeMaxDynamicSharedMemorySize, LN_SMEM);
    cudaFuncSetAttribute(mma_gemm_p<1,0,false,false,true ,1,0,1>, cudaFuncAttributeMaxDynamicSharedMemorySize, GEMM_SMEM);
    cudaFuncSetAttribute(mma_gemm_p<3,1,false,true ,false,1,0,1>, cudaFuncAttributeMaxDynamicSharedMemorySize, GEMM_SMEM);
    cudaFuncSetAttribute(mma_gemm_p<1,0,false,false,false,3,2,1>, cudaFuncAttributeMaxDynamicSharedMemorySize, GEMM_SMEM);
    cudaFuncSetAttribute(mma_gemm_p<1,0,false,false,false,1,0,2>, cudaFuncAttributeMaxDynamicSharedMemorySize, GEMM_SMEM);
    cudaFuncSetAttribute(mma_gemm_p<3,2,true ,false,false,1,1,1>, cudaFuncAttributeMaxDynamicSharedMemorySize, GEMM_SMEM);
    cudaFuncSetAttribute(mma_gemm_p<3,2,false,false,false,1,0,2>, cudaFuncAttributeMaxDynamicSharedMemorySize, GEMM_SMEM);

    // ---- pack all weights ----
    pack_w<<<dim3(65536 / 256, 1), 256>>>(cw, 0, OFF_COND, 0, S, 1, 8);
    pack_w<<<dim3(393216 / 256, 1), 256>>>(prw, 0, OFF_PRE, 0, C, 3, 48);
    pack_w<<<dim3(131072 / 256, L), 256>>>(qw, (size_t)C * C, OFF_QKV + 0,      QKV_LSTR, C, 1, 16);
    pack_w<<<dim3(131072 / 256, L), 256>>>(kw, (size_t)C * C, OFF_QKV + 131072, QKV_LSTR, C, 1, 16);
    pack_w<<<dim3(131072 / 256, L), 256>>>(vw, (size_t)C * C, OFF_QKV + 262144, QKV_LSTR, C, 1, 16);
    pack_w<<<dim3(131072 / 256, L), 256>>>(ow, (size_t)C * C, OFF_OUT, OUT_LSTR, C, 1, 16);
    pack_w<<<dim3(1572864 / 256, L), 256>>>(f1w, (size_t)FC * C * 3, OFF_F1, F1_LSTR, C,  3, 48);
    pack_w<<<dim3(1572864 / 256, L), 256>>>(f2w, (size_t)C * FC * 3, OFF_F2, F2_LSTR, FC, 3, 192);

    // ---- prep ----
    split_act<<<dim3(T / 256, S / 2, B), 256>>>(spk, ah, al, S / 2);
    mma_gemm_p<1, 0, false, false, true, 1, 0, 1><<<dim3(T / 128, 4, B), 256, GEMM_SMEM>>>(
        ah, al, wh + OFF_COND, wl + OFF_COND, cb, cb, cb, nullptr, x,
        gy, nullptr, nullptr, nullptr, nullptr, nullptr, nullptr, gy, gy, S, C);
    add_f0<<<dim3(T / 256, C, B), 256>>>(f0, f0w, f0b, gy);
    split_act<<<dim3(T / 256, C / 2, B), 256>>>(gy, ah, al, C / 2);
    mma_gemm_p<3, 1, false, true, false, 1, 0, 1><<<dim3(T / 128, 4, B), 256, GEMM_SMEM>>>(
        ah, al, wh + OFF_PRE, wl + OFF_PRE, prb, prb, prb, mask, nullptr,
        gx, nullptr, nullptr, nullptr, nullptr, nullptr, nullptr, gx, gx, C, C);
    split_act<<<dim3(T / 256, C / 2, B), 256>>>(gx, ah, al, C / 2);

    for (int l = 0; l < L; l++) {
        // fused QKV -> packed q/k (channel pairs), v (time pairs)
        mma_gemm_p<1, 0, false, false, false, 3, 2, 1><<<dim3(T / 128, 12, B), 256, GEMM_SMEM>>>(
            ah, al, wh + OFF_QKV + (size_t)l * QKV_LSTR, wl + OFF_QKV + (size_t)l * QKV_LSTR,
            qb + l * C, kb + l * C, vb + l * C, nullptr, nullptr,
            nullptr, qh_, ql_, kh_, kl_, vh_, vl_, nullptr, nullptr, C, C);

        flash_mma<<<dim3(T / 64, B * H), 256, FLASH2_SMEM>>>(
            qh_, ql_, kh_, kl_, vh_, vl_, th_, tl_);

        // out-proj, K split in 2 -> gy (half0 + bias) and gy2 (half1)
        mma_gemm_p<1, 0, false, false, false, 1, 0, 2><<<dim3(T / 128, 8, B), 256, GEMM_SMEM>>>(
            th_, tl_, wh + OFF_OUT + (size_t)l * OUT_LSTR, wl + OFF_OUT + (size_t)l * OUT_LSTR,
            ob + l * C, nullptr, nullptr, nullptr, nullptr,
            gy, nullptr, nullptr, nullptr, nullptr, nullptr, nullptr, gy2, nullptr, C, C);

        add_ln_p<true, false><<<dim3(T / 32, B), dim3(32, 8), LN_SMEM>>>(
            gx, gy, gy2, nullptr, ln0g + l * C, ln0b + l * C, gx, ah, al);

        // FFN1 -> packed B-buf (relu)
        mma_gemm_p<3, 2, true, false, false, 1, 1, 1><<<dim3(T / 128, FC / 128, B), 256, GEMM_SMEM>>>(
            ah, al, wh + OFF_F1 + (size_t)l * F1_LSTR, wl + OFF_F1 + (size_t)l * F1_LSTR,
            f1b + l * FC, nullptr, nullptr, nullptr, nullptr,
            nullptr, bh2, bl2, nullptr, nullptr, nullptr, nullptr, nullptr, nullptr, C, FC);

        // FFN2, K split in 2 -> gy/gy2 raw partials; mask applied in add_ln
        mma_gemm_p<3, 2, false, false, false, 1, 0, 2><<<dim3(T / 128, 8, B), 256, GEMM_SMEM>>>(
            bh2, bl2, wh + OFF_F2 + (size_t)l * F2_LSTR, wl + OFF_F2 + (size_t)l * F2_LSTR,
            f2b + l * C, nullptr, nullptr, nullptr, nullptr,
            gy, nullptr, nullptr, nullptr, nullptr, nullptr, nullptr, gy2, nullptr, FC, C);

        add_ln_p<true, true><<<dim3(T / 32, B), dim3(32, 8), LN_SMEM>>>(
            gx, gy, gy2, mask, ln1g + l * C, ln1b + l * C, gx, ah, al);
    }

    proj_out<<<dim3(T / 64, B), 256>>>(gx, pw, pb, mask, out);
}

// round 13
// speedup vs baseline: 1.5339x; 1.0220x over previous
#include <cuda_runtime.h>
#include <cuda_bf16.h>
#include <cstdint>
#include <cstddef>

// ---------------- problem constants ----------------
static constexpr int B  = 4;
static constexpr int C  = 512;
static constexpr int T  = 2048;
static constexpr int H  = 8;
static constexpr int FC = 2048;
static constexpr int L  = 6;
static constexpr int S  = 256;
static constexpr int DK = 64;

// ---------------- device scratch ----------------
__device__ float g_x [B * C * T];
__device__ float g_y [B * C * T];
__device__ float g_y2[B * C * T];

// packed split weights (hi/lo bf16x2), pretiled [omBlk][chunk][m(128)][k2(16)]
static constexpr size_t OFF_COND = 0;
static constexpr size_t OFF_PRE  = 65536;
static constexpr size_t OFF_QKV  = 458752;
static constexpr size_t QKV_LSTR = 393216;
static constexpr size_t OFF_OUT  = 2818048;
static constexpr size_t OUT_LSTR = 131072;
static constexpr size_t OFF_F1   = 3604480;
static constexpr size_t F1_LSTR  = 1572864;
static constexpr size_t OFF_F2   = 13041664;
static constexpr size_t F2_LSTR  = 1572864;
static constexpr size_t W_TOTAL  = 22478848;

__device__ uint32_t g_wh[W_TOTAL];
__device__ uint32_t g_wl[W_TOTAL];
// packed split activations, ping-pong buffers
__device__ uint32_t g_ah[(size_t)B * (FC / 2) * T];
__device__ uint32_t g_al[(size_t)B * (FC / 2) * T];
__device__ uint32_t g_bh[(size_t)B * (FC / 2) * T];
__device__ uint32_t g_bl[(size_t)B * (FC / 2) * T];

// region offsets inside g_bh/g_bl (words): q, k, vT, attn (2M each)
static constexpr size_t RG_Q = 0;
static constexpr size_t RG_K = 2097152;
static constexpr size_t RG_V = 4194304;
static constexpr size_t RG_A = 6291456;

// ---------------- helpers ----------------
__device__ __forceinline__ uint32_t pack_bf2(float a, float b) {
    uint32_t r;
    asm("cvt.rn.bf16x2.f32 %0, %1, %2;" : "=r"(r) : "f"(b), "f"(a));
    return r;
}
__device__ __forceinline__ float bf_hi_val(float v) {
    __nv_bfloat16 h = __float2bfloat16_rn(v);
    return __bfloat162float(h);
}
__device__ __forceinline__ void mma_bf16(float* d, const uint32_t* a, const uint32_t* b) {
    asm volatile("mma.sync.aligned.m16n8k16.row.col.f32.bf16.bf16.f32 "
        "{%0,%1,%2,%3}, {%4,%5,%6,%7}, {%8,%9}, {%0,%1,%2,%3};"
        : "+f"(d[0]), "+f"(d[1]), "+f"(d[2]), "+f"(d[3])
        : "r"(a[0]), "r"(a[1]), "r"(a[2]), "r"(a[3]), "r"(b[0]), "r"(b[1]));
}
__device__ __forceinline__ uint32_t smem_u32(const void* p) {
    uint32_t a;
    asm("{ .reg .u64 t; cvta.to.shared.u64 t, %1; cvt.u32.u64 %0, t; }" : "=r"(a) : "l"(p));
    return a;
}
__device__ __forceinline__ void ldm4(uint32_t* r, uint32_t addr) {
    asm volatile("ldmatrix.sync.aligned.m8n8.x4.shared.b16 {%0,%1,%2,%3}, [%4];"
        : "=r"(r[0]), "=r"(r[1]), "=r"(r[2]), "=r"(r[3]) : "r"(addr));
}
__device__ __forceinline__ void cp16(uint32_t dst, const void* src) {
    asm volatile("cp.async.cg.shared.global [%0], [%1], 16;" :: "r"(dst), "l"(src));
}
__device__ __forceinline__ void cp8(uint32_t dst, const void* src) {
    asm volatile("cp.async.ca.shared.global [%0], [%1], 8;" :: "r"(dst), "l"(src));
}
__device__ __forceinline__ void cp4z(uint32_t dst, const void* src, int srcsz) {
    asm volatile("cp.async.ca.shared.global [%0], [%1], 4, %2;"
                 :: "r"(dst), "l"(src), "r"(srcsz));
}
__device__ __forceinline__ void cp_commit() {
    asm volatile("cp.async.commit_group;" ::: "memory");
}
template <int N>
__device__ __forceinline__ void cp_wait() {
    asm volatile("cp.async.wait_group %0;" :: "n"(N) : "memory");
}

// ---------------- weight packing ----------------
__global__ void pack_w(const float* __restrict__ src, size_t src_lstride,
                       size_t dst_base, size_t dst_lstride,
                       int Cin, int KW, int chunks)
{
    const int l = blockIdx.y;
    const int w = blockIdx.x * 256 + threadIdx.x;
    const int per_blk = chunks * 2048;
    const int omBlk = w / per_blk;
    const int r  = w % per_blk;
    const int ch = r / 2048, r2 = r % 2048;
    const int m  = r2 >> 4;
    const int k2 = ch * 16 + (r2 & 15);
    int ka, kb;
    if (KW == 1) { ka = 2 * k2; kb = ka + 1; }
    else { int half = Cin >> 1; int c2 = k2 % half, kk = k2 / half;
           ka = (2 * c2) * KW + kk; kb = ka + KW; }
    const float* s = src + (size_t)l * src_lstride + (size_t)(omBlk * 128 + m) * Cin * KW;
    float va = s[ka], vb = s[kb];
    float ha = bf_hi_val(va), hb = bf_hi_val(vb);
    size_t d = dst_base + (size_t)l * dst_lstride + w;
    g_wh[d] = pack_bf2(ha, hb);
    g_wl[d] = pack_bf2(va - ha, vb - hb);
}

// ---------------- activation split/pack (prep only) ----------------
__global__ void split_act(const float* __restrict__ X, uint32_t* __restrict__ Xh,
                          uint32_t* __restrict__ Xl, int Chalf)
{
    const int t  = blockIdx.x * 256 + threadIdx.x;
    const int c2 = blockIdx.y;
    const int b  = blockIdx.z;
    const float* x0 = X + ((size_t)b * 2 * Chalf + 2 * c2) * T;
    float va = x0[t], vb = x0[T + t];
    float ha = bf_hi_val(va), hb = bf_hi_val(vb);
    size_t d = ((size_t)b * Chalf + c2) * T + t;
    Xh[d] = pack_bf2(ha, hb);
    Xl[d] = pack_bf2(va - ha, vb - hb);
}

// ================= 3-stage cp.async pipelined bf16x2-split mma.sync conv-GEMM =================
static constexpr int ASTR = 20;
static constexpr int KSTR = 136;
static constexpr int A_WORDS = 128 * ASTR;
static constexpr int B_WORDS = 16 * KSTR;
static constexpr int STG_WORDS = 2 * A_WORDS + 2 * B_WORDS;   // 9472
static constexpr int NSTAGE = 3;
static constexpr int GEMM_SMEM = NSTAGE * STG_WORDS * 4;      // 113664 B

// OMODE: 0 = float out, 1 = channel-pair packed out, 2 = QKV (sel0/1 packout, sel2 vpackt)
// KSPLIT: 2 = K halves (half0 +bias -> Y0, half1 raw -> Y1)
template <int KW, int PL, bool RELU, bool DOMASK, bool ADDSRC, int NOUT, int OMODE, int KSPLIT>
__global__ __launch_bounds__(256, 2) void mma_gemm_p(
    const uint32_t* __restrict__ Xh, const uint32_t* __restrict__ Xl,
    const uint32_t* __restrict__ Wh, const uint32_t* __restrict__ Wl,
    const float* __restrict__ b0, const float* __restrict__ b1, const float* __restrict__ b2,
    const float* __restrict__ mask, const float* __restrict__ src,
    float* __restrict__ Y0,
    uint32_t* __restrict__ poh,  uint32_t* __restrict__ pol,
    uint32_t* __restrict__ poh2, uint32_t* __restrict__ pol2,
    uint32_t* __restrict__ poh3, uint32_t* __restrict__ pol3,
    float* __restrict__ Y1, float* __restrict__ Y2,
    int Cin, int Cout)
{
    extern __shared__ uint32_t dsm[];
    const uint32_t sbase = smem_u32(dsm);

    const int tid  = threadIdx.x;
    const int lane = tid & 31;
    const int wid  = tid >> 5;
    const int mw   = wid & 1;
    const int nw   = wid >> 1;
    const int gid  = lane >> 2;
    const int tig  = lane & 3;

    const int b   = blockIdx.z;
    const int tn0 = blockIdx.x * 128;
    int sel, om, omIdx, khalf;
    if (NOUT == 3)      { sel = blockIdx.y >> 2; omIdx = blockIdx.y & 3; khalf = 0; }
    else if (KSPLIT==2) { sel = 0; omIdx = blockIdx.y & 3; khalf = blockIdx.y >> 2; }
    else                { sel = 0; omIdx = blockIdx.y; khalf = 0; }
    om = omIdx * 128;
    const float* bias = (NOUT == 3) ? (sel == 0 ? b0 : sel == 1 ? b1 : b2) : b0;
    float* Y;
    if (NOUT == 3)      Y = (sel == 0 ? Y0 : sel == 1 ? Y1 : Y2);
    else if (KSPLIT==2) Y = khalf ? Y1 : Y0;
    else                Y = Y0;

    const int Chalf  = Cin >> 1;
    const int chunksT = (Cin * KW) >> 5;
    const int chunks  = (KSPLIT == 2) ? (chunksT >> 1) : chunksT;
    const int kbase   = khalf * chunks;
    const int wblk = (NOUT == 3) ? blockIdx.y : omIdx;
    const uint32_t* wtH = Wh + (size_t)wblk * chunksT * 2048 + (size_t)kbase * 2048;
    const uint32_t* wtL = Wl + (size_t)wblk * chunksT * 2048 + (size_t)kbase * 2048;
    const uint32_t* XhB = Xh + (size_t)b * Chalf * T;
    const uint32_t* XlB = Xl + (size_t)b * Chalf * T;

    const int lm  = tid >> 1;
    const int lh  = tid & 1;
    const int lk2 = tid >> 4;
    const int lq  = tid & 15;

    const int qq   = lane >> 3;
    const int rrow = lane & 7;
    const uint32_t laneOff = ((uint32_t)((mw * 64 + (qq & 1) * 8 + rrow) * ASTR
                             + (qq >> 1) * 4)) * 4u;

    auto issueA = [&](int ch, int s) {
        const uint32_t* aH = wtH + ch * 2048 + lm * 16 + lh * 8;
        const uint32_t* aL = wtL + ch * 2048 + lm * 16 + lh * 8;
        uint32_t d = sbase + (uint32_t)(s * STG_WORDS + lm * ASTR + lh * 8) * 4u;
        cp16(d, aH);
        cp16(d + 16, aH + 4);
        cp16(d + A_WORDS * 4, aL);
        cp16(d + A_WORDS * 4 + 16, aL + 4);
    };
    auto issueB = [&](int ch, int s) {
        const int k2g = (kbase + ch) * 16 + lk2;
        uint32_t dh = sbase + (uint32_t)(s * STG_WORDS + 2 * A_WORDS + lk2 * KSTR + lq * 8) * 4u;
        uint32_t dl = dh + B_WORDS * 4;
        if (KW == 1) {
            const uint32_t* rH = XhB + (size_t)k2g * T + tn0 + lq * 8;
            const uint32_t* rL = XlB + (size_t)k2g * T + tn0 + lq * 8;
            cp16(dh, rH); cp16(dh + 16, rH + 4);
            cp16(dl, rL); cp16(dl + 16, rL + 4);
        } else {
            const int c2 = k2g % Chalf;
            const int kk = k2g / Chalf;
            const int dt = kk - PL;
            const uint32_t* rH = XhB + (size_t)c2 * T;
            const uint32_t* rL = XlB + (size_t)c2 * T;
            const int t0 = tn0 + lq * 8 + dt;
            if (dt == 0) {
                cp16(dh, rH + t0); cp16(dh + 16, rH + t0 + 4);
                cp16(dl, rL + t0); cp16(dl + 16, rL + t0 + 4);
            } else if (t0 >= 0 && t0 + 8 <= T) {
                if ((dt & 1) == 0) {
#pragma unroll
                    for (int j = 0; j < 4; j++) {
                        cp8(dh + j * 8, rH + t0 + j * 2);
                        cp8(dl + j * 8, rL + t0 + j * 2);
                    }
                } else {
#pragma unroll
                    for (int j = 0; j < 8; j++) {
                        cp4z(dh + j * 4, rH + t0 + j, 4);
                        cp4z(dl + j * 4, rL + t0 + j, 4);
                    }
                }
            } else {
#pragma unroll
                for (int j = 0; j < 8; j++) {
                    int t = t0 + j;
                    bool ok = (unsigned)t < (unsigned)T;
                    int tc = ok ? t : 0;
                    int sz = ok ? 4 : 0;
                    cp4z(dh + j * 4, rH + tc, sz);
                    cp4z(dl + j * 4, rL + tc, sz);
                }
            }
        }
    };

    float acc[4][4][4];
#pragma unroll
    for (int i = 0; i < 4; i++)
#pragma unroll
        for (int j = 0; j < 4; j++)
#pragma unroll
            for (int r = 0; r < 4; r++) acc[i][j][r] = 0.f;

    // prologue: two chunks in flight (chunks >= 8 for every instantiation)
    issueA(0, 0); issueB(0, 0); cp_commit();
    issueA(1, 1); issueB(1, 1); cp_commit();

    int scur = 0;      // stage of the chunk being computed
    int snext = 2;     // stage receiving chunk ch+2

    for (int ch = 0; ch < chunks; ch++) {
        if (ch + 1 < chunks) cp_wait<1>(); else cp_wait<0>();
        __syncthreads();   // single barrier: guards buffer reuse + data visibility
        if (ch + 2 < chunks) {
            issueA(ch + 2, snext); issueB(ch + 2, snext); cp_commit();
            snext = (snext == 2) ? 0 : snext + 1;
        }

        const uint32_t aAh = sbase + (uint32_t)(scur * STG_WORDS) * 4u;
        const uint32_t aAl = aAh + A_WORDS * 4u;
        const uint32_t* BhS = dsm + scur * STG_WORDS + 2 * A_WORDS;
        const uint32_t* BlS = BhS + B_WORDS;

#pragma unroll
        for (int ks = 0; ks < 2; ks++) {
            const int k2a = ks * 8 + tig;
            const int k2b = ks * 8 + 4 + tig;
            uint32_t bfh[4][2], bfl[4][2];
#pragma unroll
            for (int nt = 0; nt < 4; nt++) {
                int n = nw * 32 + nt * 8 + gid;
                bfh[nt][0] = BhS[k2a * KSTR + n];
                bfh[nt][1] = BhS[k2b * KSTR + n];
                bfl[nt][0] = BlS[k2a * KSTR + n];
                bfl[nt][1] = BlS[k2b * KSTR + n];
            }
#pragma unroll
            for (int mt = 0; mt < 4; mt++) {
                uint32_t afh[4], afl[4];
                const uint32_t off = laneOff + (uint32_t)(mt * 16 * ASTR + ks * 8) * 4u;
                ldm4(afh, aAh + off);
                ldm4(afl, aAl + off);
#pragma unroll
                for (int nt = 0; nt < 4; nt++) {
                    mma_bf16(acc[mt][nt], afh, bfh[nt]);
                    mma_bf16(acc[mt][nt], afh, bfl[nt]);
                    mma_bf16(acc[mt][nt], afl, bfh[nt]);
                }
            }
        }
        scur = (scur == 2) ? 0 : scur + 1;
    }

    // ---- epilogue ----
    const int ChalfO = Cout >> 1;
    uint32_t* th = poh; uint32_t* tl = pol;
    if (OMODE == 2 && sel == 1) { th = poh2; tl = pol2; }
#pragma unroll
    for (int mt = 0; mt < 4; mt++) {
        int o0 = om + mw * 64 + mt * 16 + gid;
        float bb0 = (KSPLIT == 2 && khalf) ? 0.f : bias[o0];
        float bb1 = (KSPLIT == 2 && khalf) ? 0.f : bias[o0 + 8];
#pragma unroll
        for (int nt = 0; nt < 4; nt++) {
            int t0 = tn0 + nw * 32 + nt * 8 + 2 * tig;
            float v0 = acc[mt][nt][0] + bb0;
            float v1 = acc[mt][nt][1] + bb0;
            float v2 = acc[mt][nt][2] + bb1;
            float v3 = acc[mt][nt][3] + bb1;
            if (RELU) {
                v0 = fmaxf(v0, 0.f); v1 = fmaxf(v1, 0.f);
                v2 = fmaxf(v2, 0.f); v3 = fmaxf(v3, 0.f);
            }
            if (OMODE == 2 && sel == 2) {
                size_t ia = ((size_t)b * Cout + o0)     * (T / 2) + (t0 >> 1);
                size_t ib = ((size_t)b * Cout + o0 + 8) * (T / 2) + (t0 >> 1);
                float h0 = bf_hi_val(v0), h1 = bf_hi_val(v1);
                poh3[ia] = pack_bf2(h0, h1);
                pol3[ia] = pack_bf2(v0 - h0, v1 - h1);
                h0 = bf_hi_val(v2); h1 = bf_hi_val(v3);
                poh3[ib] = pack_bf2(h0, h1);
                pol3[ib] = pack_bf2(v2 - h0, v3 - h1);
            } else if (OMODE == 1 || OMODE == 2) {
                float q0 = __shfl_xor_sync(0xffffffffu, v0, 4);
                float q1 = __shfl_xor_sync(0xffffffffu, v1, 4);
                float q2 = __shfl_xor_sync(0xffffffffu, v2, 4);
                float q3 = __shfl_xor_sync(0xffffffffu, v3, 4);
                if ((gid & 1) == 0) {
                    size_t da = ((size_t)b * ChalfO + (o0 >> 1)) * T + t0;
                    size_t db = ((size_t)b * ChalfO + ((o0 + 8) >> 1)) * T + t0;
                    float h;
                    h = bf_hi_val(v0); float hq = bf_hi_val(q0);
                    th[da]     = pack_bf2(h, hq);
                    tl[da]     = pack_bf2(v0 - h, q0 - hq);
                    h = bf_hi_val(v1); hq = bf_hi_val(q1);
                    th[da + 1] = pack_bf2(h, hq);
                    tl[da + 1] = pack_bf2(v1 - h, q1 - hq);
                    h = bf_hi_val(v2); hq = bf_hi_val(q2);
                    th[db]     = pack_bf2(h, hq);
                    tl[db]     = pack_bf2(v2 - h, q2 - hq);
                    h = bf_hi_val(v3); hq = bf_hi_val(q3);
                    th[db + 1] = pack_bf2(h, hq);
                    tl[db + 1] = pack_bf2(v3 - h, q3 - hq);
                }
            } else {
                float m0v = 1.f, m1v = 1.f;
                if (DOMASK) {
                    m0v = mask[(size_t)b * T + t0];
                    m1v = mask[(size_t)b * T + t0 + 1];
                }
                size_t oi0 = ((size_t)b * Cout + o0)     * T + t0;
                size_t oi1 = ((size_t)b * Cout + o0 + 8) * T + t0;
                if (ADDSRC) {
                    float2 s0 = *(const float2*)(src + oi0);
                    float2 s1 = *(const float2*)(src + oi1);
                    v0 += s0.x; v1 += s0.y; v2 += s1.x; v3 += s1.y;
                }
                if (DOMASK) { v0 *= m0v; v1 *= m1v; v2 *= m0v; v3 *= m1v; }
                *(float2*)(Y + oi0) = make_float2(v0, v1);
                *(float2*)(Y + oi1) = make_float2(v2, v3);
            }
        }
    }
}

// ---------------- f0 prenet added in-place ----------------
__global__ void add_f0(const float* __restrict__ f0, const float* __restrict__ w,
                       const float* __restrict__ fb, float* __restrict__ y)
{
    int t = blockIdx.x * 256 + threadIdx.x;
    int c = blockIdx.y;
    int b = blockIdx.z;
    float fm1 = (t - 1 >= 0) ? f0[(size_t)b * T + t - 1] : 0.f;
    float fc0 = f0[(size_t)b * T + t];
    float fp1 = (t + 1 < T) ? f0[(size_t)b * T + t + 1] : 0.f;
    float v = w[c * 3 + 0] * fm1 + w[c * 3 + 1] * fc0 + w[c * 3 + 2] * fp1 + fb[c];
    y[((size_t)b * C + c) * T + t] += v;
}

// ---------------- fused residual-add + LayerNorm + packed split output ----------------
static constexpr int LN_SMEM = (512 * 32 + 256 + 256 + 64) * 4;

template <bool TWOY, bool YMASK>
__global__ void add_ln_p(const float* __restrict__ x, const float* __restrict__ y,
                         const float* __restrict__ y2, const float* __restrict__ maskt,
                         const float* __restrict__ g, const float* __restrict__ be,
                         float* __restrict__ out,
                         uint32_t* __restrict__ ph, uint32_t* __restrict__ pl)
{
    extern __shared__ float lns[];
    float* cache = lns;
    float* red0  = lns + 512 * 32;
    float* red1  = red0 + 256;
    float* smv   = red1 + 256;
    const int tx = threadIdx.x, ty = threadIdx.y;
    const int t = blockIdx.x * 32 + tx;
    const int b = blockIdx.y;
    const size_t base = (size_t)b * C * T + t;
    const float mv = YMASK ? maskt[(size_t)b * T + t] : 1.f;

    float s = 0.f, sq = 0.f;
    for (int c2 = ty; c2 < C / 2; c2 += 8) {
        size_t i0 = base + (size_t)(2 * c2) * T;
        float yv0 = y[i0],     yv1 = y[i0 + T];
        if (TWOY) { yv0 += y2[i0]; yv1 += y2[i0 + T]; }
        if (YMASK) { yv0 *= mv; yv1 *= mv; }
        float v0 = x[i0] + yv0;
        float v1 = x[i0 + T] + yv1;
        cache[(2 * c2) * 32 + tx]     = v0;
        cache[(2 * c2 + 1) * 32 + tx] = v1;
        s += v0 + v1; sq += v0 * v0 + v1 * v1;
    }
    red0[ty * 32 + tx] = s; red1[ty * 32 + tx] = sq;
    __syncthreads();
    if (ty == 0) {
#pragma unroll
        for (int i = 1; i < 8; i++) { s += red0[i * 32 + tx]; sq += red1[i * 32 + tx]; }
        float mean = s * (1.f / C);
        float var  = sq * (1.f / C) - mean * mean;
        smv[tx]      = mean;
        smv[32 + tx] = rsqrtf(var + 1e-5f);
    }
    __syncthreads();
    float mean = smv[tx], rstd = smv[32 + tx];
    for (int c2 = ty; c2 < C / 2; c2 += 8) {
        size_t i0 = base + (size_t)(2 * c2) * T;
        float v0 = (cache[(2 * c2) * 32 + tx]     - mean) * rstd * g[2 * c2]     + be[2 * c2];
        float v1 = (cache[(2 * c2 + 1) * 32 + tx] - mean) * rstd * g[2 * c2 + 1] + be[2 * c2 + 1];
        out[i0]     = v0;
        out[i0 + T] = v1;
        float h0 = bf_hi_val(v0), h1 = bf_hi_val(v1);
        size_t d = ((size_t)b * (C / 2) + c2) * T + t;
        ph[d] = pack_bf2(h0, h1);
        pl[d] = pack_bf2(v0 - h0, v1 - h1);
    }
}

// ================= tensor-core causal flash attention (2 CTA/SM) =================
static constexpr int FQH = 0;
static constexpr int FQL = 2304;
static constexpr int FKH0 = 4608;
static constexpr int FVH  = 13824;
static constexpr int FSS  = 18432;
static constexpr int FPH  = 22784;
static constexpr int FPL  = 25088;
static constexpr int FCORR = 27392;
static constexpr int FMST  = 27456;
static constexpr int FLST  = 27520;
static constexpr int FLASH2_WORDS = 27584;
static constexpr int FLASH2_SMEM = FLASH2_WORDS * 4;

__global__ __launch_bounds__(256, 2) void flash_mma(
    const uint32_t* __restrict__ qh, const uint32_t* __restrict__ ql,
    const uint32_t* __restrict__ kh, const uint32_t* __restrict__ kl,
    const uint32_t* __restrict__ vh, const uint32_t* __restrict__ vl,
    uint32_t* __restrict__ oh, uint32_t* __restrict__ ol)
{
    extern __shared__ uint32_t fs[];
    float* fsf = (float*)fs;
    const uint32_t sb = smem_u32(fs);

    const int tid  = threadIdx.x;
    const int lane = tid & 31;
    const int wid  = tid >> 5;
    const int gid  = lane >> 2;
    const int tig  = lane & 3;
    const int wm   = wid & 3;
    const int wn   = wid >> 2;
    const int mbase = wm * 16;
    const int nbase = wn * 32;

    const int mb = (int)gridDim.x - 1 - (int)blockIdx.x;
    const int m0 = mb * 64;
    const int bhh = blockIdx.y;
    const int b = bhh >> 3;
    const int h = bhh & 7;

    const uint32_t* qhB = qh + ((size_t)b * (C / 2) + h * 32) * T + m0;
    const uint32_t* qlB = ql + ((size_t)b * (C / 2) + h * 32) * T + m0;
    const uint32_t* khB = kh + ((size_t)b * (C / 2) + h * 32) * T;
    const uint32_t* klB = kl + ((size_t)b * (C / 2) + h * 32) * T;
    const uint32_t* vhB = vh + ((size_t)b * C + h * 64) * (T / 2);
    const uint32_t* vlB = vl + ((size_t)b * C + h * 64) * (T / 2);

    if (tid < 64) { fsf[FMST + tid] = -1e30f; fsf[FLST + tid] = 0.f; }

    {
        int selq = tid >> 7, r = tid & 127, k2 = r >> 2, cq = (r & 3) * 4;
        const uint32_t* src = (selq ? qlB : qhB) + (size_t)k2 * T;
        uint32_t dst = sb + (uint32_t)((selq ? FQL : FQH) + k2 * 72) * 4u;
#pragma unroll
        for (int i = 0; i < 4; i++) cp16(dst + (cq + i) * 16, src + (cq + i) * 4);
    }
    auto loadK = [&](int kbk, int s) {
        const int kn0 = kbk * 64;
        int selq = tid >> 7, r = tid & 127, k2 = r >> 2, cq = (r & 3) * 4;
        const uint32_t* src = (selq ? klB : khB) + (size_t)k2 * T + kn0;
        uint32_t dst = sb + (uint32_t)(FKH0 + s * 4608 + selq * 2304 + k2 * 72) * 4u;
#pragma unroll
        for (int i = 0; i < 4; i++) cp16(dst + (cq + i) * 16, src + (cq + i) * 4);
    };
    auto loadV = [&](int kbk) {
        const int kn0 = kbk * 64;
        int selq = tid >> 7, r = tid & 127, d = r >> 1, cq = (r & 1) * 4;
        const uint32_t* src = (selq ? vlB : vhB) + (size_t)d * (T / 2) + (kn0 >> 1);
        uint32_t dst = sb + (uint32_t)(FVH + selq * 2304 + d * 36) * 4u;
#pragma unroll
        for (int i = 0; i < 4; i++) cp16(dst + (cq + i) * 16, src + (cq + i) * 4);
    };
    loadK(0, 0); cp_commit();

    float oacc[4][4];
#pragma unroll
    for (int i = 0; i < 4; i++)
#pragma unroll
        for (int j = 0; j < 4; j++) oacc[i][j] = 0.f;

    for (int kbk = 0; kbk <= mb; kbk++) {
        const int s = kbk & 1;
        const int kn0 = kbk * 64;
        cp_wait<0>();
        __syncthreads();
        loadV(kbk); cp_commit();
        if (kbk < mb) { loadK(kbk + 1, s ^ 1); cp_commit(); }

        const uint32_t* Qh_ = fs + FQH;
        const uint32_t* Ql_ = fs + FQL;
        const uint32_t* Kh_ = fs + FKH0 + s * 4608;
        const uint32_t* Kl_ = Kh_ + 2304;
        const uint32_t* Vh_ = fs + FVH;
        const uint32_t* Vl_ = Vh_ + 2304;

        float sacc[4][4];
#pragma unroll
        for (int i = 0; i < 4; i++)
#pragma unroll
            for (int j = 0; j < 4; j++) sacc[i][j] = 0.f;

#pragma unroll
        for (int kt = 0; kt < 4; kt++) {
            const int k2a = kt * 8 + tig;
            const int k2b = k2a + 4;
            const int mq = mbase + gid;
            uint32_t aqh[4] = { Qh_[k2a * 72 + mq], Qh_[k2a * 72 + mq + 8],
                                Qh_[k2b * 72 + mq], Qh_[k2b * 72 + mq + 8] };
            uint32_t aql[4] = { Ql_[k2a * 72 + mq], Ql_[k2a * 72 + mq + 8],
                                Ql_[k2b * 72 + mq], Ql_[k2b * 72 + mq + 8] };
#pragma unroll
            for (int nt = 0; nt < 4; nt++) {
                int n = nbase + nt * 8 + gid;
                uint32_t bkh[2] = { Kh_[k2a * 72 + n], Kh_[k2b * 72 + n] };
                uint32_t bkl[2] = { Kl_[k2a * 72 + n], Kl_[k2b * 72 + n] };
                mma_bf16(sacc[nt], aqh, bkh);
                mma_bf16(sacc[nt], aqh, bkl);
                mma_bf16(sacc[nt], aql, bkh);
            }
        }
#pragma unroll
        for (int nt = 0; nt < 4; nt++) {
            int col = nbase + nt * 8 + 2 * tig;
            int r0 = mbase + gid;
            *(float2*)&fsf[FSS + r0 * 68 + col]       = make_float2(sacc[nt][0], sacc[nt][1]);
            *(float2*)&fsf[FSS + (r0 + 8) * 68 + col] = make_float2(sacc[nt][2], sacc[nt][3]);
        }
        __syncthreads();

#pragma unroll
        for (int r = 0; r < 8; r++) {
            int q = wid * 8 + r;
            int tq = m0 + q;
            float s0 = fsf[FSS + q * 68 + lane] * 0.125f;
            float s1 = fsf[FSS + q * 68 + lane + 32] * 0.125f;
            if (kn0 + lane      > tq) s0 = -1e4f;
            if (kn0 + lane + 32 > tq) s1 = -1e4f;
            float mx = fmaxf(s0, s1);
#pragma unroll
            for (int off = 16; off; off >>= 1)
                mx = fmaxf(mx, __shfl_xor_sync(0xffffffffu, mx, off));
            float mold = fsf[FMST + q];
            float mnew = fmaxf(mold, mx);
            float p0 = __expf(s0 - mnew);
            float p1 = __expf(s1 - mnew);
            float ps = p0 + p1;
#pragma unroll
            for (int off = 16; off; off >>= 1)
                ps += __shfl_xor_sync(0xffffffffu, ps, off);
            float corrv = __expf(mold - mnew);
            if (lane == 0) {
                fsf[FMST + q]  = mnew;
                fsf[FLST + q]  = fsf[FLST + q] * corrv + ps;
                fsf[FCORR + q] = corrv;
            }
            float p0p = __shfl_xor_sync(0xffffffffu, p0, 1);
            float p1p = __shfl_xor_sync(0xffffffffu, p1, 1);
            if ((lane & 1) == 0) {
                int k2 = lane >> 1;
                float h0 = bf_hi_val(p0), h1 = bf_hi_val(p0p);
                fs[FPH + k2 * 72 + q] = pack_bf2(h0, h1);
                fs[FPL + k2 * 72 + q] = pack_bf2(p0 - h0, p0p - h1);
                h0 = bf_hi_val(p1); h1 = bf_hi_val(p1p);
                fs[FPH + (k2 + 16) * 72 + q] = pack_bf2(h0, h1);
                fs[FPL + (k2 + 16) * 72 + q] = pack_bf2(p1 - h0, p1p - h1);
            }
        }
        __syncthreads();
        if (kbk < mb) cp_wait<1>(); else cp_wait<0>();
        __syncthreads();

#pragma unroll
        for (int nt = 0; nt < 4; nt++) {
            int col = nbase + nt * 8 + 2 * tig;
            float c0 = fsf[FCORR + col];
            float c1 = fsf[FCORR + col + 1];
            oacc[nt][0] *= c0; oacc[nt][1] *= c1;
            oacc[nt][2] *= c0; oacc[nt][3] *= c1;
        }
#pragma unroll
        for (int kt = 0; kt < 4; kt++) {
            const int k2a = kt * 8 + tig;
            const int k2b = k2a + 4;
            const int md = mbase + gid;
            uint32_t avh[4] = { Vh_[md * 36 + k2a], Vh_[(md + 8) * 36 + k2a],
                                Vh_[md * 36 + k2b], Vh_[(md + 8) * 36 + k2b] };
            uint32_t avl[4] = { Vl_[md * 36 + k2a], Vl_[(md + 8) * 36 + k2a],
                                Vl_[md * 36 + k2b], Vl_[(md + 8) * 36 + k2b] };
#pragma unroll
            for (int nt = 0; nt < 4; nt++) {
                int n = nbase + nt * 8 + gid;
                uint32_t bph[2] = { fs[FPH + k2a * 72 + n], fs[FPH + k2b * 72 + n] };
                uint32_t bpl[2] = { fs[FPL + k2a * 72 + n], fs[FPL + k2b * 72 + n] };
                mma_bf16(oacc[nt], avh, bph);
                mma_bf16(oacc[nt], avh, bpl);
                mma_bf16(oacc[nt], avl, bph);
            }
        }
    }

#pragma unroll
    for (int nt = 0; nt < 4; nt++) {
        int col = nbase + nt * 8 + 2 * tig;
        float i0 = 1.f / fsf[FLST + col];
        float i1 = 1.f / fsf[FLST + col + 1];
        float v0 = oacc[nt][0] * i0;
        float v1 = oacc[nt][1] * i1;
        float v2 = oacc[nt][2] * i0;
        float v3 = oacc[nt][3] * i1;
        float q0 = __shfl_xor_sync(0xffffffffu, v0, 4);
        float q1 = __shfl_xor_sync(0xffffffffu, v1, 4);
        float q2 = __shfl_xor_sync(0xffffffffu, v2, 4);
        float q3 = __shfl_xor_sync(0xffffffffu, v3, 4);
        if ((gid & 1) == 0) {
            int d0 = h * 64 + mbase + gid;
            int c2a = d0 >> 1;
            size_t ra = ((size_t)b * (C / 2) + c2a) * T + m0 + col;
            size_t rb = ((size_t)b * (C / 2) + c2a + 4) * T + m0 + col;
            float h0 = bf_hi_val(v0), hq = bf_hi_val(q0);
            oh[ra]     = pack_bf2(h0, hq);
            ol[ra]     = pack_bf2(v0 - h0, q0 - hq);
            h0 = bf_hi_val(v1); hq = bf_hi_val(q1);
            oh[ra + 1] = pack_bf2(h0, hq);
            ol[ra + 1] = pack_bf2(v1 - h0, q1 - hq);
            h0 = bf_hi_val(v2); hq = bf_hi_val(q2);
            oh[rb]     = pack_bf2(h0, hq);
            ol[rb]     = pack_bf2(v2 - h0, q2 - hq);
            h0 = bf_hi_val(v3); hq = bf_hi_val(q3);
            oh[rb + 1] = pack_bf2(h0, hq);
            ol[rb + 1] = pack_bf2(v3 - h0, q3 - hq);
        }
    }
}

// ---------------- final 1-channel projection (4-way channel split) ----------------
__global__ void proj_out(const float* __restrict__ x, const float* __restrict__ w,
                         const float* __restrict__ pb, const float* __restrict__ mask,
                         float* __restrict__ out)
{
    __shared__ float red[256];
    const int tl   = threadIdx.x & 63;
    const int csub = threadIdx.x >> 6;
    const int t = blockIdx.x * 64 + tl;
    const int b = blockIdx.y;
    const float* xb = x + (size_t)b * C * T;
    float s = 0.f;
    for (int i = 0; i < 128; i++) {
        int c = csub * 128 + i;
        s += w[c] * xb[(size_t)c * T + t];
    }
    red[csub * 64 + tl] = s;
    __syncthreads();
    if (csub == 0) {
        float tot = red[tl] + red[64 + tl] + red[128 + tl] + red[192 + tl] + pb[0];
        out[(size_t)b * T + t] = tot * mask[(size_t)b * T + t];
    }
}

// ---------------- launch ----------------
extern "C" void kernel_launch(void* const* d_in, const int* in_sizes, int n_in,
                              void* d_out, int out_size)
{
    const float* x    = (const float*)d_in[0];
    const float* f0   = (const float*)d_in[1];
    const float* mask = (const float*)d_in[2];
    const float* spk  = (const float*)d_in[3];
    const float* prw  = (const float*)d_in[4];
    const float* prb  = (const float*)d_in[5];
    const float* f0w  = (const float*)d_in[6];
    const float* f0b  = (const float*)d_in[7];
    const float* cw   = (const float*)d_in[8];
    const float* cb   = (const float*)d_in[9];
    const float* pw   = (const float*)d_in[10];
    const float* pb   = (const float*)d_in[11];
    const float* qw   = (const float*)d_in[12];
    const float* qb   = (const float*)d_in[13];
    const float* kw   = (const float*)d_in[14];
    const float* kb   = (const float*)d_in[15];
    const float* vw   = (const float*)d_in[16];
    const float* vb   = (const float*)d_in[17];
    const float* ow   = (const float*)d_in[18];
    const float* ob   = (const float*)d_in[19];
    const float* ln0g = (const float*)d_in[20];
    const float* ln0b = (const float*)d_in[21];
    const float* ln1g = (const float*)d_in[22];
    const float* ln1b = (const float*)d_in[23];
    const float* f1w  = (const float*)d_in[24];
    const float* f1b  = (const float*)d_in[25];
    const float* f2w  = (const float*)d_in[26];
    const float* f2b  = (const float*)d_in[27];
    float* out = (float*)d_out;

    float *gx, *gy, *gy2;
    uint32_t *wh, *wl, *ah, *al, *bh2, *bl2;
    cudaGetSymbolAddress((void**)&gx,  g_x);
    cudaGetSymbolAddress((void**)&gy,  g_y);
    cudaGetSymbolAddress((void**)&gy2, g_y2);
    cudaGetSymbolAddress((void**)&wh,  g_wh);
    cudaGetSymbolAddress((void**)&wl,  g_wl);
    cudaGetSymbolAddress((void**)&ah,  g_ah);
    cudaGetSymbolAddress((void**)&al,  g_al);
    cudaGetSymbolAddress((void**)&bh2, g_bh);
    cudaGetSymbolAddress((void**)&bl2, g_bl);

    uint32_t* qh_ = bh2 + RG_Q;  uint32_t* ql_ = bl2 + RG_Q;
    uint32_t* kh_ = bh2 + RG_K;  uint32_t* kl_ = bl2 + RG_K;
    uint32_t* vh_ = bh2 + RG_V;  uint32_t* vl_ = bl2 + RG_V;
    uint32_t* th_ = bh2 + RG_A;  uint32_t* tl_ = bl2 + RG_A;

    cudaFuncSetAttribute(flash_mma, cudaFuncAttributeMaxDynamicSharedMemorySize, FLASH2_SMEM);
    cudaFuncSetAttribute(add_ln_p<true,false>, cudaFuncAttributeMaxDynamicSharedMemorySize, LN_SMEM);
    cudaFuncSetAttribute(add_ln_p<true,true >, cudaFuncAttributeMaxDynamicSharedMemorySize, LN_SMEM);
    cudaFuncSetAttribute(mma_gemm_p<1,0,false,false,true ,1,0,1>, cudaFuncAttributeMaxDynamicSharedMemorySize, GEMM_SMEM);
    cudaFuncSetAttribute(mma_gemm_p<3,1,false,true ,false,1,0,1>, cudaFuncAttributeMaxDynamicSharedMemorySize, GEMM_SMEM);
    cudaFuncSetAttribute(mma_gemm_p<1,0,false,false,false,3,2,1>, cudaFuncAttributeMaxDynamicSharedMemorySize, GEMM_SMEM);
    cudaFuncSetAttribute(mma_gemm_p<1,0,false,false,false,1,0,2>, cudaFuncAttributeMaxDynamicSharedMemorySize, GEMM_SMEM);
    cudaFuncSetAttribute(mma_gemm_p<3,2,true ,false,false,1,1,1>, cudaFuncAttributeMaxDynamicSharedMemorySize, GEMM_SMEM);
    cudaFuncSetAttribute(mma_gemm_p<3,2,false,false,false,1,0,2>, cudaFuncAttributeMaxDynamicSharedMemorySize, GEMM_SMEM);

    // ---- pack all weights ----
    pack_w<<<dim3(65536 / 256, 1), 256>>>(cw, 0, OFF_COND, 0, S, 1, 8);
    pack_w<<<dim3(393216 / 256, 1), 256>>>(prw, 0, OFF_PRE, 0, C, 3, 48);
    pack_w<<<dim3(131072 / 256, L), 256>>>(qw, (size_t)C * C, OFF_QKV + 0,      QKV_LSTR, C, 1, 16);
    pack_w<<<dim3(131072 / 256, L), 256>>>(kw, (size_t)C * C, OFF_QKV + 131072, QKV_LSTR, C, 1, 16);
    pack_w<<<dim3(131072 / 256, L), 256>>>(vw, (size_t)C * C, OFF_QKV + 262144, QKV_LSTR, C, 1, 16);
    pack_w<<<dim3(131072 / 256, L), 256>>>(ow, (size_t)C * C, OFF_OUT, OUT_LSTR, C, 1, 16);
    pack_w<<<dim3(1572864 / 256, L), 256>>>(f1w, (size_t)FC * C * 3, OFF_F1, F1_LSTR, C,  3, 48);
    pack_w<<<dim3(1572864 / 256, L), 256>>>(f2w, (size_t)C * FC * 3, OFF_F2, F2_LSTR, FC, 3, 192);

    // ---- prep ----
    split_act<<<dim3(T / 256, S / 2, B), 256>>>(spk, ah, al, S / 2);
    mma_gemm_p<1, 0, false, false, true, 1, 0, 1><<<dim3(T / 128, 4, B), 256, GEMM_SMEM>>>(
        ah, al, wh + OFF_COND, wl + OFF_COND, cb, cb, cb, nullptr, x,
        gy, nullptr, nullptr, nullptr, nullptr, nullptr, nullptr, gy, gy, S, C);
    add_f0<<<dim3(T / 256, C, B), 256>>>(f0, f0w, f0b, gy);
    split_act<<<dim3(T / 256, C / 2, B), 256>>>(gy, ah, al, C / 2);
    mma_gemm_p<3, 1, false, true, false, 1, 0, 1><<<dim3(T / 128, 4, B), 256, GEMM_SMEM>>>(
        ah, al, wh + OFF_PRE, wl + OFF_PRE, prb, prb, prb, mask, nullptr,
        gx, nullptr, nullptr, nullptr, nullptr, nullptr, nullptr, gx, gx, C, C);
    split_act<<<dim3(T / 256, C / 2, B), 256>>>(gx, ah, al, C / 2);

    for (int l = 0; l < L; l++) {
        // fused QKV -> packed q/k (channel pairs), v (time pairs)
        mma_gemm_p<1, 0, false, false, false, 3, 2, 1><<<dim3(T / 128, 12, B), 256, GEMM_SMEM>>>(
            ah, al, wh + OFF_QKV + (size_t)l * QKV_LSTR, wl + OFF_QKV + (size_t)l * QKV_LSTR,
            qb + l * C, kb + l * C, vb + l * C, nullptr, nullptr,
            nullptr, qh_, ql_, kh_, kl_, vh_, vl_, nullptr, nullptr, C, C);

        flash_mma<<<dim3(T / 64, B * H), 256, FLASH2_SMEM>>>(
            qh_, ql_, kh_, kl_, vh_, vl_, th_, tl_);

        // out-proj, K split in 2 -> gy (half0 + bias) and gy2 (half1)
        mma_gemm_p<1, 0, false, false, false, 1, 0, 2><<<dim3(T / 128, 8, B), 256, GEMM_SMEM>>>(
            th_, tl_, wh + OFF_OUT + (size_t)l * OUT_LSTR, wl + OFF_OUT + (size_t)l * OUT_LSTR,
            ob + l * C, nullptr, nullptr, nullptr, nullptr,
            gy, nullptr, nullptr, nullptr, nullptr, nullptr, nullptr, gy2, nullptr, C, C);

        add_ln_p<true, false><<<dim3(T / 32, B), dim3(32, 8), LN_SMEM>>>(
            gx, gy, gy2, nullptr, ln0g + l * C, ln0b + l * C, gx, ah, al);

        // FFN1 -> packed B-buf (relu)
        mma_gemm_p<3, 2, true, false, false, 1, 1, 1><<<dim3(T / 128, FC / 128, B), 256, GEMM_SMEM>>>(
            ah, al, wh + OFF_F1 + (size_t)l * F1_LSTR, wl + OFF_F1 + (size_t)l * F1_LSTR,
            f1b + l * FC, nullptr, nullptr, nullptr, nullptr,
            nullptr, bh2, bl2, nullptr, nullptr, nullptr, nullptr, nullptr, nullptr, C, FC);

        // FFN2, K split in 2 -> gy/gy2 raw partials; mask applied in add_ln
        mma_gemm_p<3, 2, false, false, false, 1, 0, 2><<<dim3(T / 128, 8, B), 256, GEMM_SMEM>>>(
            bh2, bl2, wh + OFF_F2 + (size_t)l * F2_LSTR, wl + OFF_F2 + (size_t)l * F2_LSTR,
            f2b + l * C, nullptr, nullptr, nullptr, nullptr,
            gy, nullptr, nullptr, nullptr, nullptr, nullptr, nullptr, gy2, nullptr, FC, C);

        add_ln_p<true, true><<<dim3(T / 32, B), dim3(32, 8), LN_SMEM>>>(
            gx, gy, gy2, mask, ln1g + l * C, ln1b + l * C, gx, ah, al);
    }

    proj_out<<<dim3(T / 64, B), 256>>>(gx, pw, pb, mask, out);
}

// round 17
// speedup vs baseline: 1.6282x; 1.0615x over previous
#include <cuda_runtime.h>
#include <cuda_fp16.h>
#include <cstdint>
#include <cstddef>

// ---------------- problem constants ----------------
static constexpr int B  = 4;
static constexpr int C  = 512;
static constexpr int T  = 2048;
static constexpr int H  = 8;
static constexpr int FC = 2048;
static constexpr int L  = 6;
static constexpr int S  = 256;
static constexpr int DK = 64;

// ---------------- device scratch ----------------
__device__ float g_x [B * C * T];
__device__ float g_y [B * C * T];
__device__ float g_y2[B * C * T];

// packed fp16 weights (hi and lo planes), pretiled [omBlk][chunk][m(128)][k2(16)]
static constexpr size_t OFF_COND = 0;
static constexpr size_t OFF_PRE  = 65536;
static constexpr size_t OFF_QKV  = 458752;
static constexpr size_t QKV_LSTR = 393216;
static constexpr size_t OFF_OUT  = 2818048;
static constexpr size_t OUT_LSTR = 131072;
static constexpr size_t OFF_F1   = 3604480;
static constexpr size_t F1_LSTR  = 1572864;
static constexpr size_t OFF_F2   = 13041664;
static constexpr size_t F2_LSTR  = 1572864;
static constexpr size_t W_TOTAL  = 22478848;

__device__ uint32_t g_wh[W_TOTAL];
__device__ uint32_t g_wl[W_TOTAL];
// packed split activations (fp16 hi/lo), ping-pong buffers
__device__ uint32_t g_ah[(size_t)B * (FC / 2) * T];
__device__ uint32_t g_al[(size_t)B * (FC / 2) * T];
__device__ uint32_t g_bh[(size_t)B * (FC / 2) * T];
__device__ uint32_t g_bl[(size_t)B * (FC / 2) * T];

// region offsets inside g_bh/g_bl (words): q, k, vT, attn (2M each)
static constexpr size_t RG_Q = 0;
static constexpr size_t RG_K = 2097152;
static constexpr size_t RG_V = 4194304;
static constexpr size_t RG_A = 6291456;

// ---------------- helpers ----------------
__device__ __forceinline__ uint32_t pack_h2(float a, float b) {
    uint32_t r;
    asm("cvt.rn.f16x2.f32 %0, %1, %2;" : "=r"(r) : "f"(b), "f"(a));
    return r;
}
__device__ __forceinline__ float h_hi_val(float v) {
    return __half2float(__float2half_rn(v));
}
__device__ __forceinline__ void mma_f16(float* d, const uint32_t* a, const uint32_t* b) {
    asm volatile("mma.sync.aligned.m16n8k16.row.col.f32.f16.f16.f32 "
        "{%0,%1,%2,%3}, {%4,%5,%6,%7}, {%8,%9}, {%0,%1,%2,%3};"
        : "+f"(d[0]), "+f"(d[1]), "+f"(d[2]), "+f"(d[3])
        : "r"(a[0]), "r"(a[1]), "r"(a[2]), "r"(a[3]), "r"(b[0]), "r"(b[1]));
}
__device__ __forceinline__ uint32_t smem_u32(const void* p) {
    uint32_t a;
    asm("{ .reg .u64 t; cvta.to.shared.u64 t, %1; cvt.u32.u64 %0, t; }" : "=r"(a) : "l"(p));
    return a;
}
__device__ __forceinline__ void ldm4(uint32_t* r, uint32_t addr) {
    asm volatile("ldmatrix.sync.aligned.m8n8.x4.shared.b16 {%0,%1,%2,%3}, [%4];"
        : "=r"(r[0]), "=r"(r[1]), "=r"(r[2]), "=r"(r[3]) : "r"(addr));
}
__device__ __forceinline__ void cp16(uint32_t dst, const void* src) {
    asm volatile("cp.async.cg.shared.global [%0], [%1], 16;" :: "r"(dst), "l"(src));
}
__device__ __forceinline__ void cp8(uint32_t dst, const void* src) {
    asm volatile("cp.async.ca.shared.global [%0], [%1], 8;" :: "r"(dst), "l"(src));
}
__device__ __forceinline__ void cp4z(uint32_t dst, const void* src, int srcsz) {
    asm volatile("cp.async.ca.shared.global [%0], [%1], 4, %2;"
                 :: "r"(dst), "l"(src), "r"(srcsz));
}
__device__ __forceinline__ void cp_commit() {
    asm volatile("cp.async.commit_group;" ::: "memory");
}
template <int N>
__device__ __forceinline__ void cp_wait() {
    asm volatile("cp.async.wait_group %0;" :: "n"(N) : "memory");
}

// ---------------- weight packing (fp16 hi + lo) ----------------
__global__ void pack_w(const float* __restrict__ src, size_t src_lstride,
                       size_t dst_base, size_t dst_lstride,
                       int Cin, int KW, int chunks)
{
    const int l = blockIdx.y;
    const int w = blockIdx.x * 256 + threadIdx.x;
    const int per_blk = chunks * 2048;
    const int omBlk = w / per_blk;
    const int r  = w % per_blk;
    const int ch = r / 2048, r2 = r % 2048;
    const int m  = r2 >> 4;
    const int k2 = ch * 16 + (r2 & 15);
    int ka, kb;
    if (KW == 1) { ka = 2 * k2; kb = ka + 1; }
    else { int half = Cin >> 1; int c2 = k2 % half, kk = k2 / half;
           ka = (2 * c2) * KW + kk; kb = ka + KW; }
    const float* s = src + (size_t)l * src_lstride + (size_t)(omBlk * 128 + m) * Cin * KW;
    float va = s[ka], vb = s[kb];
    float ha = h_hi_val(va), hb = h_hi_val(vb);
    size_t d = dst_base + (size_t)l * dst_lstride + w;
    g_wh[d] = pack_h2(ha, hb);
    g_wl[d] = pack_h2(va - ha, vb - hb);
}

// ---------------- activation split/pack (prep only) ----------------
__global__ void split_act(const float* __restrict__ X, uint32_t* __restrict__ Xh,
                          uint32_t* __restrict__ Xl, int Chalf)
{
    const int t  = blockIdx.x * 256 + threadIdx.x;
    const int c2 = blockIdx.y;
    const int b  = blockIdx.z;
    const float* x0 = X + ((size_t)b * 2 * Chalf + 2 * c2) * T;
    float va = x0[t], vb = x0[T + t];
    float ha = h_hi_val(va), hb = h_hi_val(vb);
    size_t d = ((size_t)b * Chalf + c2) * T + t;
    Xh[d] = pack_h2(ha, hb);
    Xl[d] = pack_h2(va - ha, vb - hb);
}

// ================= 3-stage cp.async pipelined fp16 mma.sync conv-GEMM =================
// TERMS==3: acc = Wh*Bh + Wh*Bl + Wl*Bh   (residual ~2^-22)
// TERMS==2: acc = Wh*(Bh + Bl)            (residual ~2^-12, FFN1 only)
static constexpr int ASTR = 20;
static constexpr int KSTR = 136;
static constexpr int A_WORDS = 128 * ASTR;                    // 2560 per plane
static constexpr int B_WORDS = 16 * KSTR;                     // 2176
static constexpr int GEMM_SMEM_T3 = 3 * (2 * A_WORDS + 2 * B_WORDS) * 4;  // 113664
static constexpr int GEMM_SMEM_T2 = 3 * (A_WORDS + 2 * B_WORDS) * 4;      // 82944

// OMODE: 0 = float out, 1 = channel-pair packed out, 2 = QKV (sel0/1 packout, sel2 vpackt)
// KSPLIT: 2 = K halves (half0 +bias -> Y0, half1 raw -> Y1)
template <int KW, int PL, bool RELU, bool DOMASK, bool ADDSRC, int NOUT, int OMODE, int KSPLIT, int TERMS>
__global__ __launch_bounds__(256, 2) void mma_gemm_p(
    const uint32_t* __restrict__ Xh, const uint32_t* __restrict__ Xl,
    const uint32_t* __restrict__ Wh, const uint32_t* __restrict__ Wl,
    const float* __restrict__ b0, const float* __restrict__ b1, const float* __restrict__ b2,
    const float* __restrict__ mask, const float* __restrict__ src,
    float* __restrict__ Y0,
    uint32_t* __restrict__ poh,  uint32_t* __restrict__ pol,
    uint32_t* __restrict__ poh2, uint32_t* __restrict__ pol2,
    uint32_t* __restrict__ poh3, uint32_t* __restrict__ pol3,
    float* __restrict__ Y1, float* __restrict__ Y2,
    int Cin, int Cout)
{
    constexpr int AW  = (TERMS == 3) ? 2 * A_WORDS : A_WORDS;
    constexpr int STG = AW + 2 * B_WORDS;

    extern __shared__ uint32_t dsm[];
    const uint32_t sbase = smem_u32(dsm);

    const int tid  = threadIdx.x;
    const int lane = tid & 31;
    const int wid  = tid >> 5;
    const int mw   = wid & 1;
    const int nw   = wid >> 1;
    const int gid  = lane >> 2;
    const int tig  = lane & 3;

    const int b   = blockIdx.z;
    const int tn0 = blockIdx.x * 128;
    int sel, om, omIdx, khalf;
    if (NOUT == 3)      { sel = blockIdx.y >> 2; omIdx = blockIdx.y & 3; khalf = 0; }
    else if (KSPLIT==2) { sel = 0; omIdx = blockIdx.y & 3; khalf = blockIdx.y >> 2; }
    else                { sel = 0; omIdx = blockIdx.y; khalf = 0; }
    om = omIdx * 128;
    const float* bias = (NOUT == 3) ? (sel == 0 ? b0 : sel == 1 ? b1 : b2) : b0;
    float* Y;
    if (NOUT == 3)      Y = (sel == 0 ? Y0 : sel == 1 ? Y1 : Y2);
    else if (KSPLIT==2) Y = khalf ? Y1 : Y0;
    else                Y = Y0;

    const int Chalf  = Cin >> 1;
    const int chunksT = (Cin * KW) >> 5;
    const int chunks  = (KSPLIT == 2) ? (chunksT >> 1) : chunksT;
    const int kbase   = khalf * chunks;
    const int wblk = (NOUT == 3) ? blockIdx.y : omIdx;
    const uint32_t* wtH = Wh + (size_t)wblk * chunksT * 2048 + (size_t)kbase * 2048;
    const uint32_t* wtL = Wl + (size_t)wblk * chunksT * 2048 + (size_t)kbase * 2048;
    const uint32_t* XhB = Xh + (size_t)b * Chalf * T;
    const uint32_t* XlB = Xl + (size_t)b * Chalf * T;

    const int lm  = tid >> 1;
    const int lh  = tid & 1;
    const int lk2 = tid >> 4;
    const int lq  = tid & 15;

    const int qq   = lane >> 3;
    const int rrow = lane & 7;
    const uint32_t laneOff = ((uint32_t)((mw * 64 + (qq & 1) * 8 + rrow) * ASTR
                             + (qq >> 1) * 4)) * 4u;

    auto issueA = [&](int ch, int s) {
        const uint32_t* aH = wtH + ch * 2048 + lm * 16 + lh * 8;
        uint32_t d = sbase + (uint32_t)(s * STG + lm * ASTR + lh * 8) * 4u;
        cp16(d, aH);
        cp16(d + 16, aH + 4);
        if (TERMS == 3) {
            const uint32_t* aL = wtL + ch * 2048 + lm * 16 + lh * 8;
            uint32_t d2 = d + A_WORDS * 4;
            cp16(d2, aL);
            cp16(d2 + 16, aL + 4);
        }
    };
    auto issueB = [&](int ch, int s) {
        const int k2g = (kbase + ch) * 16 + lk2;
        uint32_t dh = sbase + (uint32_t)(s * STG + AW + lk2 * KSTR + lq * 8) * 4u;
        uint32_t dl = dh + B_WORDS * 4;
        if (KW == 1) {
            const uint32_t* rH = XhB + (size_t)k2g * T + tn0 + lq * 8;
            const uint32_t* rL = XlB + (size_t)k2g * T + tn0 + lq * 8;
            cp16(dh, rH); cp16(dh + 16, rH + 4);
            cp16(dl, rL); cp16(dl + 16, rL + 4);
        } else {
            const int c2 = k2g % Chalf;
            const int kk = k2g / Chalf;
            const int dt = kk - PL;
            const uint32_t* rH = XhB + (size_t)c2 * T;
            const uint32_t* rL = XlB + (size_t)c2 * T;
            const int t0 = tn0 + lq * 8 + dt;
            if (dt == 0) {
                cp16(dh, rH + t0); cp16(dh + 16, rH + t0 + 4);
                cp16(dl, rL + t0); cp16(dl + 16, rL + t0 + 4);
            } else if (t0 >= 0 && t0 + 8 <= T) {
                if ((dt & 1) == 0) {
#pragma unroll
                    for (int j = 0; j < 4; j++) {
                        cp8(dh + j * 8, rH + t0 + j * 2);
                        cp8(dl + j * 8, rL + t0 + j * 2);
                    }
                } else {
#pragma unroll
                    for (int j = 0; j < 8; j++) {
                        cp4z(dh + j * 4, rH + t0 + j, 4);
                        cp4z(dl + j * 4, rL + t0 + j, 4);
                    }
                }
            } else {
#pragma unroll
                for (int j = 0; j < 8; j++) {
                    int t = t0 + j;
                    bool ok = (unsigned)t < (unsigned)T;
                    int tc = ok ? t : 0;
                    int sz = ok ? 4 : 0;
                    cp4z(dh + j * 4, rH + tc, sz);
                    cp4z(dl + j * 4, rL + tc, sz);
                }
            }
        }
    };

    float acc[4][4][4];
#pragma unroll
    for (int i = 0; i < 4; i++)
#pragma unroll
        for (int j = 0; j < 4; j++)
#pragma unroll
            for (int r = 0; r < 4; r++) acc[i][j][r] = 0.f;

    issueA(0, 0); issueB(0, 0); cp_commit();
    issueA(1, 1); issueB(1, 1); cp_commit();

    int scur = 0;
    int snext = 2;

    for (int ch = 0; ch < chunks; ch++) {
        if (ch + 1 < chunks) cp_wait<1>(); else cp_wait<0>();
        __syncthreads();
        if (ch + 2 < chunks) {
            issueA(ch + 2, snext); issueB(ch + 2, snext); cp_commit();
            snext = (snext == 2) ? 0 : snext + 1;
        }

        const uint32_t aAh = sbase + (uint32_t)(scur * STG) * 4u;
        const uint32_t aAl = aAh + A_WORDS * 4u;
        const uint32_t* BhS = dsm + scur * STG + AW;
        const uint32_t* BlS = BhS + B_WORDS;

#pragma unroll
        for (int ks = 0; ks < 2; ks++) {
            const int k2a = ks * 8 + tig;
            const int k2b = ks * 8 + 4 + tig;
            uint32_t bfh[4][2], bfl[4][2];
#pragma unroll
            for (int nt = 0; nt < 4; nt++) {
                int n = nw * 32 + nt * 8 + gid;
                bfh[nt][0] = BhS[k2a * KSTR + n];
                bfh[nt][1] = BhS[k2b * KSTR + n];
                bfl[nt][0] = BlS[k2a * KSTR + n];
                bfl[nt][1] = BlS[k2b * KSTR + n];
            }
#pragma unroll
            for (int mt = 0; mt < 4; mt++) {
                uint32_t afh[4], afl[4];
                const uint32_t off = laneOff + (uint32_t)(mt * 16 * ASTR + ks * 8) * 4u;
                ldm4(afh, aAh + off);
                if (TERMS == 3) ldm4(afl, aAl + off);
#pragma unroll
                for (int nt = 0; nt < 4; nt++) {
                    mma_f16(acc[mt][nt], afh, bfh[nt]);
                    mma_f16(acc[mt][nt], afh, bfl[nt]);
                    if (TERMS == 3) mma_f16(acc[mt][nt], afl, bfh[nt]);
                }
            }
        }
        scur = (scur == 2) ? 0 : scur + 1;
    }

    // ---- epilogue ----
    const int ChalfO = Cout >> 1;
    uint32_t* th = poh; uint32_t* tl = pol;
    if (OMODE == 2 && sel == 1) { th = poh2; tl = pol2; }
#pragma unroll
    for (int mt = 0; mt < 4; mt++) {
        int o0 = om + mw * 64 + mt * 16 + gid;
        float bb0 = (KSPLIT == 2 && khalf) ? 0.f : bias[o0];
        float bb1 = (KSPLIT == 2 && khalf) ? 0.f : bias[o0 + 8];
#pragma unroll
        for (int nt = 0; nt < 4; nt++) {
            int t0 = tn0 + nw * 32 + nt * 8 + 2 * tig;
            float v0 = acc[mt][nt][0] + bb0;
            float v1 = acc[mt][nt][1] + bb0;
            float v2 = acc[mt][nt][2] + bb1;
            float v3 = acc[mt][nt][3] + bb1;
            if (RELU) {
                v0 = fmaxf(v0, 0.f); v1 = fmaxf(v1, 0.f);
                v2 = fmaxf(v2, 0.f); v3 = fmaxf(v3, 0.f);
            }
            if (OMODE == 2 && sel == 2) {
                size_t ia = ((size_t)b * Cout + o0)     * (T / 2) + (t0 >> 1);
                size_t ib = ((size_t)b * Cout + o0 + 8) * (T / 2) + (t0 >> 1);
                float h0 = h_hi_val(v0), h1 = h_hi_val(v1);
                poh3[ia] = pack_h2(h0, h1);
                pol3[ia] = pack_h2(v0 - h0, v1 - h1);
                h0 = h_hi_val(v2); h1 = h_hi_val(v3);
                poh3[ib] = pack_h2(h0, h1);
                pol3[ib] = pack_h2(v2 - h0, v3 - h1);
            } else if (OMODE == 1 || OMODE == 2) {
                float q0 = __shfl_xor_sync(0xffffffffu, v0, 4);
                float q1 = __shfl_xor_sync(0xffffffffu, v1, 4);
                float q2 = __shfl_xor_sync(0xffffffffu, v2, 4);
                float q3 = __shfl_xor_sync(0xffffffffu, v3, 4);
                if ((gid & 1) == 0) {
                    size_t da = ((size_t)b * ChalfO + (o0 >> 1)) * T + t0;
                    size_t db = ((size_t)b * ChalfO + ((o0 + 8) >> 1)) * T + t0;
                    float h;
                    h = h_hi_val(v0); float hq = h_hi_val(q0);
                    th[da]     = pack_h2(h, hq);
                    tl[da]     = pack_h2(v0 - h, q0 - hq);
                    h = h_hi_val(v1); hq = h_hi_val(q1);
                    th[da + 1] = pack_h2(h, hq);
                    tl[da + 1] = pack_h2(v1 - h, q1 - hq);
                    h = h_hi_val(v2); hq = h_hi_val(q2);
                    th[db]     = pack_h2(h, hq);
                    tl[db]     = pack_h2(v2 - h, q2 - hq);
                    h = h_hi_val(v3); hq = h_hi_val(q3);
                    th[db + 1] = pack_h2(h, hq);
                    tl[db + 1] = pack_h2(v3 - h, q3 - hq);
                }
            } else {
                float m0v = 1.f, m1v = 1.f;
                if (DOMASK) {
                    m0v = mask[(size_t)b * T + t0];
                    m1v = mask[(size_t)b * T + t0 + 1];
                }
                size_t oi0 = ((size_t)b * Cout + o0)     * T + t0;
                size_t oi1 = ((size_t)b * Cout + o0 + 8) * T + t0;
                if (ADDSRC) {
                    float2 s0 = *(const float2*)(src + oi0);
                    float2 s1 = *(const float2*)(src + oi1);
                    v0 += s0.x; v1 += s0.y; v2 += s1.x; v3 += s1.y;
                }
                if (DOMASK) { v0 *= m0v; v1 *= m1v; v2 *= m0v; v3 *= m1v; }
                *(float2*)(Y + oi0) = make_float2(v0, v1);
                *(float2*)(Y + oi1) = make_float2(v2, v3);
            }
        }
    }
}

// ---------------- f0 prenet added in-place ----------------
__global__ void add_f0(const float* __restrict__ f0, const float* __restrict__ w,
                       const float* __restrict__ fb, float* __restrict__ y)
{
    int t = blockIdx.x * 256 + threadIdx.x;
    int c = blockIdx.y;
    int b = blockIdx.z;
    float fm1 = (t - 1 >= 0) ? f0[(size_t)b * T + t - 1] : 0.f;
    float fc0 = f0[(size_t)b * T + t];
    float fp1 = (t + 1 < T) ? f0[(size_t)b * T + t + 1] : 0.f;
    float v = w[c * 3 + 0] * fm1 + w[c * 3 + 1] * fc0 + w[c * 3 + 2] * fp1 + fb[c];
    y[((size_t)b * C + c) * T + t] += v;
}

// ---------------- fused residual-add + LayerNorm + packed split output ----------------
static constexpr int LN_SMEM = (512 * 32 + 256 + 256 + 64) * 4;

template <bool TWOY, bool YMASK>
__global__ void add_ln_p(const float* __restrict__ x, const float* __restrict__ y,
                         const float* __restrict__ y2, const float* __restrict__ maskt,
                         const float* __restrict__ g, const float* __restrict__ be,
                         float* __restrict__ out,
                         uint32_t* __restrict__ ph, uint32_t* __restrict__ pl)
{
    extern __shared__ float lns[];
    float* cache = lns;
    float* red0  = lns + 512 * 32;
    float* red1  = red0 + 256;
    float* smv   = red1 + 256;
    const int tx = threadIdx.x, ty = threadIdx.y;
    const int t = blockIdx.x * 32 + tx;
    const int b = blockIdx.y;
    const size_t base = (size_t)b * C * T + t;
    const float mv = YMASK ? maskt[(size_t)b * T + t] : 1.f;

    float s = 0.f, sq = 0.f;
    for (int c2 = ty; c2 < C / 2; c2 += 8) {
        size_t i0 = base + (size_t)(2 * c2) * T;
        float yv0 = y[i0],     yv1 = y[i0 + T];
        if (TWOY) { yv0 += y2[i0]; yv1 += y2[i0 + T]; }
        if (YMASK) { yv0 *= mv; yv1 *= mv; }
        float v0 = x[i0] + yv0;
        float v1 = x[i0 + T] + yv1;
        cache[(2 * c2) * 32 + tx]     = v0;
        cache[(2 * c2 + 1) * 32 + tx] = v1;
        s += v0 + v1; sq += v0 * v0 + v1 * v1;
    }
    red0[ty * 32 + tx] = s; red1[ty * 32 + tx] = sq;
    __syncthreads();
    if (ty == 0) {
#pragma unroll
        for (int i = 1; i < 8; i++) { s += red0[i * 32 + tx]; sq += red1[i * 32 + tx]; }
        float mean = s * (1.f / C);
        float var  = sq * (1.f / C) - mean * mean;
        smv[tx]      = mean;
        smv[32 + tx] = rsqrtf(var + 1e-5f);
    }
    __syncthreads();
    float mean = smv[tx], rstd = smv[32 + tx];
    for (int c2 = ty; c2 < C / 2; c2 += 8) {
        size_t i0 = base + (size_t)(2 * c2) * T;
        float v0 = (cache[(2 * c2) * 32 + tx]     - mean) * rstd * g[2 * c2]     + be[2 * c2];
        float v1 = (cache[(2 * c2 + 1) * 32 + tx] - mean) * rstd * g[2 * c2 + 1] + be[2 * c2 + 1];
        out[i0]     = v0;
        out[i0 + T] = v1;
        float h0 = h_hi_val(v0), h1 = h_hi_val(v1);
        size_t d = ((size_t)b * (C / 2) + c2) * T + t;
        ph[d] = pack_h2(h0, h1);
        pl[d] = pack_h2(v0 - h0, v1 - h1);
    }
}

// ================= tensor-core causal flash attention (fp16, 3-term, 2 CTA/SM) =================
static constexpr int FQH = 0;
static constexpr int FQL = 2304;
static constexpr int FKH0 = 4608;
static constexpr int FVH  = 13824;
static constexpr int FSS  = 18432;
static constexpr int FPH  = 22784;
static constexpr int FPL  = 25088;
static constexpr int FCORR = 27392;
static constexpr int FMST  = 27456;
static constexpr int FLST  = 27520;
static constexpr int FLASH2_WORDS = 27584;
static constexpr int FLASH2_SMEM = FLASH2_WORDS * 4;

__global__ __launch_bounds__(256, 2) void flash_mma(
    const uint32_t* __restrict__ qh, const uint32_t* __restrict__ ql,
    const uint32_t* __restrict__ kh, const uint32_t* __restrict__ kl,
    const uint32_t* __restrict__ vh, const uint32_t* __restrict__ vl,
    uint32_t* __restrict__ oh, uint32_t* __restrict__ ol)
{
    extern __shared__ uint32_t fs[];
    float* fsf = (float*)fs;
    const uint32_t sb = smem_u32(fs);

    const int tid  = threadIdx.x;
    const int lane = tid & 31;
    const int wid  = tid >> 5;
    const int gid  = lane >> 2;
    const int tig  = lane & 3;
    const int wm   = wid & 3;
    const int wn   = wid >> 2;
    const int mbase = wm * 16;
    const int nbase = wn * 32;

    const int mb = (int)gridDim.x - 1 - (int)blockIdx.x;
    const int m0 = mb * 64;
    const int bhh = blockIdx.y;
    const int b = bhh >> 3;
    const int h = bhh & 7;

    const uint32_t* qhB = qh + ((size_t)b * (C / 2) + h * 32) * T + m0;
    const uint32_t* qlB = ql + ((size_t)b * (C / 2) + h * 32) * T + m0;
    const uint32_t* khB = kh + ((size_t)b * (C / 2) + h * 32) * T;
    const uint32_t* klB = kl + ((size_t)b * (C / 2) + h * 32) * T;
    const uint32_t* vhB = vh + ((size_t)b * C + h * 64) * (T / 2);
    const uint32_t* vlB = vl + ((size_t)b * C + h * 64) * (T / 2);

    if (tid < 64) { fsf[FMST + tid] = -1e30f; fsf[FLST + tid] = 0.f; }

    {
        int selq = tid >> 7, r = tid & 127, k2 = r >> 2, cq = (r & 3) * 4;
        const uint32_t* src = (selq ? qlB : qhB) + (size_t)k2 * T;
        uint32_t dst = sb + (uint32_t)((selq ? FQL : FQH) + k2 * 72) * 4u;
#pragma unroll
        for (int i = 0; i < 4; i++) cp16(dst + (cq + i) * 16, src + (cq + i) * 4);
    }
    auto loadK = [&](int kbk, int s) {
        const int kn0 = kbk * 64;
        int selq = tid >> 7, r = tid & 127, k2 = r >> 2, cq = (r & 3) * 4;
        const uint32_t* src = (selq ? klB : khB) + (size_t)k2 * T + kn0;
        uint32_t dst = sb + (uint32_t)(FKH0 + s * 4608 + selq * 2304 + k2 * 72) * 4u;
#pragma unroll
        for (int i = 0; i < 4; i++) cp16(dst + (cq + i) * 16, src + (cq + i) * 4);
    };
    auto loadV = [&](int kbk) {
        const int kn0 = kbk * 64;
        int selq = tid >> 7, r = tid & 127, d = r >> 1, cq = (r & 1) * 4;
        const uint32_t* src = (selq ? vlB : vhB) + (size_t)d * (T / 2) + (kn0 >> 1);
        uint32_t dst = sb + (uint32_t)(FVH + selq * 2304 + d * 36) * 4u;
#pragma unroll
        for (int i = 0; i < 4; i++) cp16(dst + (cq + i) * 16, src + (cq + i) * 4);
    };
    loadK(0, 0); cp_commit();

    float oacc[4][4];
#pragma unroll
    for (int i = 0; i < 4; i++)
#pragma unroll
        for (int j = 0; j < 4; j++) oacc[i][j] = 0.f;

    for (int kbk = 0; kbk <= mb; kbk++) {
        const int s = kbk & 1;
        const int kn0 = kbk * 64;
        cp_wait<0>();
        __syncthreads();
        loadV(kbk); cp_commit();
        if (kbk < mb) { loadK(kbk + 1, s ^ 1); cp_commit(); }

        const uint32_t* Qh_ = fs + FQH;
        const uint32_t* Ql_ = fs + FQL;
        const uint32_t* Kh_ = fs + FKH0 + s * 4608;
        const uint32_t* Kl_ = Kh_ + 2304;
        const uint32_t* Vh_ = fs + FVH;
        const uint32_t* Vl_ = Vh_ + 2304;

        float sacc[4][4];
#pragma unroll
        for (int i = 0; i < 4; i++)
#pragma unroll
            for (int j = 0; j < 4; j++) sacc[i][j] = 0.f;

#pragma unroll
        for (int kt = 0; kt < 4; kt++) {
            const int k2a = kt * 8 + tig;
            const int k2b = k2a + 4;
            const int mq = mbase + gid;
            uint32_t aqh[4] = { Qh_[k2a * 72 + mq], Qh_[k2a * 72 + mq + 8],
                                Qh_[k2b * 72 + mq], Qh_[k2b * 72 + mq + 8] };
            uint32_t aql[4] = { Ql_[k2a * 72 + mq], Ql_[k2a * 72 + mq + 8],
                                Ql_[k2b * 72 + mq], Ql_[k2b * 72 + mq + 8] };
#pragma unroll
            for (int nt = 0; nt < 4; nt++) {
                int n = nbase + nt * 8 + gid;
                uint32_t bkh[2] = { Kh_[k2a * 72 + n], Kh_[k2b * 72 + n] };
                uint32_t bkl[2] = { Kl_[k2a * 72 + n], Kl_[k2b * 72 + n] };
                mma_f16(sacc[nt], aqh, bkh);
                mma_f16(sacc[nt], aqh, bkl);
                mma_f16(sacc[nt], aql, bkh);
            }
        }
#pragma unroll
        for (int nt = 0; nt < 4; nt++) {
            int col = nbase + nt * 8 + 2 * tig;
            int r0 = mbase + gid;
            *(float2*)&fsf[FSS + r0 * 68 + col]       = make_float2(sacc[nt][0], sacc[nt][1]);
            *(float2*)&fsf[FSS + (r0 + 8) * 68 + col] = make_float2(sacc[nt][2], sacc[nt][3]);
        }
        __syncthreads();

#pragma unroll
        for (int r = 0; r < 8; r++) {
            int q = wid * 8 + r;
            int tq = m0 + q;
            float s0 = fsf[FSS + q * 68 + lane] * 0.125f;
            float s1 = fsf[FSS + q * 68 + lane + 32] * 0.125f;
            if (kn0 + lane      > tq) s0 = -1e4f;
            if (kn0 + lane + 32 > tq) s1 = -1e4f;
            float mx = fmaxf(s0, s1);
#pragma unroll
            for (int off = 16; off; off >>= 1)
                mx = fmaxf(mx, __shfl_xor_sync(0xffffffffu, mx, off));
            float mold = fsf[FMST + q];
            float mnew = fmaxf(mold, mx);
            float p0 = __expf(s0 - mnew);
            float p1 = __expf(s1 - mnew);
            float ps = p0 + p1;
#pragma unroll
            for (int off = 16; off; off >>= 1)
                ps += __shfl_xor_sync(0xffffffffu, ps, off);
            float corrv = __expf(mold - mnew);
            if (lane == 0) {
                fsf[FMST + q]  = mnew;
                fsf[FLST + q]  = fsf[FLST + q] * corrv + ps;
                fsf[FCORR + q] = corrv;
            }
            float p0p = __shfl_xor_sync(0xffffffffu, p0, 1);
            float p1p = __shfl_xor_sync(0xffffffffu, p1, 1);
            if ((lane & 1) == 0) {
                int k2 = lane >> 1;
                float h0 = h_hi_val(p0), h1 = h_hi_val(p0p);
                fs[FPH + k2 * 72 + q] = pack_h2(h0, h1);
                fs[FPL + k2 * 72 + q] = pack_h2(p0 - h0, p0p - h1);
                h0 = h_hi_val(p1); h1 = h_hi_val(p1p);
                fs[FPH + (k2 + 16) * 72 + q] = pack_h2(h0, h1);
                fs[FPL + (k2 + 16) * 72 + q] = pack_h2(p1 - h0, p1p - h1);
            }
        }
        __syncthreads();
        if (kbk < mb) cp_wait<1>(); else cp_wait<0>();
        __syncthreads();

#pragma unroll
        for (int nt = 0; nt < 4; nt++) {
            int col = nbase + nt * 8 + 2 * tig;
            float c0 = fsf[FCORR + col];
            float c1 = fsf[FCORR + col + 1];
            oacc[nt][0] *= c0; oacc[nt][1] *= c1;
            oacc[nt][2] *= c0; oacc[nt][3] *= c1;
        }
#pragma unroll
        for (int kt = 0; kt < 4; kt++) {
            const int k2a = kt * 8 + tig;
            const int k2b = k2a + 4;
            const int md = mbase + gid;
            uint32_t avh[4] = { Vh_[md * 36 + k2a], Vh_[(md + 8) * 36 + k2a],
                                Vh_[md * 36 + k2b], Vh_[(md + 8) * 36 + k2b] };
            uint32_t avl[4] = { Vl_[md * 36 + k2a], Vl_[(md + 8) * 36 + k2a],
                                Vl_[md * 36 + k2b], Vl_[(md + 8) * 36 + k2b] };
#pragma unroll
            for (int nt = 0; nt < 4; nt++) {
                int n = nbase + nt * 8 + gid;
                uint32_t bph[2] = { fs[FPH + k2a * 72 + n], fs[FPH + k2b * 72 + n] };
                uint32_t bpl[2] = { fs[FPL + k2a * 72 + n], fs[FPL + k2b * 72 + n] };
                mma_f16(oacc[nt], avh, bph);
                mma_f16(oacc[nt], avh, bpl);
                mma_f16(oacc[nt], avl, bph);
            }
        }
    }

#pragma unroll
    for (int nt = 0; nt < 4; nt++) {
        int col = nbase + nt * 8 + 2 * tig;
        float i0 = 1.f / fsf[FLST + col];
        float i1 = 1.f / fsf[FLST + col + 1];
        float v0 = oacc[nt][0] * i0;
        float v1 = oacc[nt][1] * i1;
        float v2 = oacc[nt][2] * i0;
        float v3 = oacc[nt][3] * i1;
        float q0 = __shfl_xor_sync(0xffffffffu, v0, 4);
        float q1 = __shfl_xor_sync(0xffffffffu, v1, 4);
        float q2 = __shfl_xor_sync(0xffffffffu, v2, 4);
        float q3 = __shfl_xor_sync(0xffffffffu, v3, 4);
        if ((gid & 1) == 0) {
            int d0 = h * 64 + mbase + gid;
            int c2a = d0 >> 1;
            size_t ra = ((size_t)b * (C / 2) + c2a) * T + m0 + col;
            size_t rb = ((size_t)b * (C / 2) + c2a + 4) * T + m0 + col;
            float h0 = h_hi_val(v0), hq = h_hi_val(q0);
            oh[ra]     = pack_h2(h0, hq);
            ol[ra]     = pack_h2(v0 - h0, q0 - hq);
            h0 = h_hi_val(v1); hq = h_hi_val(q1);
            oh[ra + 1] = pack_h2(h0, hq);
            ol[ra + 1] = pack_h2(v1 - h0, q1 - hq);
            h0 = h_hi_val(v2); hq = h_hi_val(q2);
            oh[rb]     = pack_h2(h0, hq);
            ol[rb]     = pack_h2(v2 - h0, q2 - hq);
            h0 = h_hi_val(v3); hq = h_hi_val(q3);
            oh[rb + 1] = pack_h2(h0, hq);
            ol[rb + 1] = pack_h2(v3 - h0, q3 - hq);
        }
    }
}

// ---------------- final 1-channel projection (4-way channel split) ----------------
__global__ void proj_out(const float* __restrict__ x, const float* __restrict__ w,
                         const float* __restrict__ pb, const float* __restrict__ mask,
                         float* __restrict__ out)
{
    __shared__ float red[256];
    const int tl   = threadIdx.x & 63;
    const int csub = threadIdx.x >> 6;
    const int t = blockIdx.x * 64 + tl;
    const int b = blockIdx.y;
    const float* xb = x + (size_t)b * C * T;
    float s = 0.f;
    for (int i = 0; i < 128; i++) {
        int c = csub * 128 + i;
        s += w[c] * xb[(size_t)c * T + t];
    }
    red[csub * 64 + tl] = s;
    __syncthreads();
    if (csub == 0) {
        float tot = red[tl] + red[64 + tl] + red[128 + tl] + red[192 + tl] + pb[0];
        out[(size_t)b * T + t] = tot * mask[(size_t)b * T + t];
    }
}

// ---------------- launch ----------------
extern "C" void kernel_launch(void* const* d_in, const int* in_sizes, int n_in,
                              void* d_out, int out_size)
{
    const float* x    = (const float*)d_in[0];
    const float* f0   = (const float*)d_in[1];
    const float* mask = (const float*)d_in[2];
    const float* spk  = (const float*)d_in[3];
    const float* prw  = (const float*)d_in[4];
    const float* prb  = (const float*)d_in[5];
    const float* f0w  = (const float*)d_in[6];
    const float* f0b  = (const float*)d_in[7];
    const float* cw   = (const float*)d_in[8];
    const float* cb   = (const float*)d_in[9];
    const float* pw   = (const float*)d_in[10];
    const float* pb   = (const float*)d_in[11];
    const float* qw   = (const float*)d_in[12];
    const float* qb   = (const float*)d_in[13];
    const float* kw   = (const float*)d_in[14];
    const float* kb   = (const float*)d_in[15];
    const float* vw   = (const float*)d_in[16];
    const float* vb   = (const float*)d_in[17];
    const float* ow   = (const float*)d_in[18];
    const float* ob   = (const float*)d_in[19];
    const float* ln0g = (const float*)d_in[20];
    const float* ln0b = (const float*)d_in[21];
    const float* ln1g = (const float*)d_in[22];
    const float* ln1b = (const float*)d_in[23];
    const float* f1w  = (const float*)d_in[24];
    const float* f1b  = (const float*)d_in[25];
    const float* f2w  = (const float*)d_in[26];
    const float* f2b  = (const float*)d_in[27];
    float* out = (float*)d_out;

    float *gx, *gy, *gy2;
    uint32_t *wh, *wl, *ah, *al, *bh2, *bl2;
    cudaGetSymbolAddress((void**)&gx,  g_x);
    cudaGetSymbolAddress((void**)&gy,  g_y);
    cudaGetSymbolAddress((void**)&gy2, g_y2);
    cudaGetSymbolAddress((void**)&wh,  g_wh);
    cudaGetSymbolAddress((void**)&wl,  g_wl);
    cudaGetSymbolAddress((void**)&ah,  g_ah);
    cudaGetSymbolAddress((void**)&al,  g_al);
    cudaGetSymbolAddress((void**)&bh2, g_bh);
    cudaGetSymbolAddress((void**)&bl2, g_bl);

    uint32_t* qh_ = bh2 + RG_Q;  uint32_t* ql_ = bl2 + RG_Q;
    uint32_t* kh_ = bh2 + RG_K;  uint32_t* kl_ = bl2 + RG_K;
    uint32_t* vh_ = bh2 + RG_V;  uint32_t* vl_ = bl2 + RG_V;
    uint32_t* th_ = bh2 + RG_A;  uint32_t* tl_ = bl2 + RG_A;

    cudaFuncSetAttribute(flash_mma, cudaFuncAttributeMaxDynamicSharedMemorySize, FLASH2_SMEM);
    cudaFuncSetAttribute(add_ln_p<true,false>, cudaFuncAttributeMaxDynamicSharedMemorySize, LN_SMEM);
    cudaFuncSetAttribute(add_ln_p<true,true >, cudaFuncAttributeMaxDynamicSharedMemorySize, LN_SMEM);
    cudaFuncSetAttribute(mma_gemm_p<1,0,false,false,true ,1,0,1,3>, cudaFuncAttributeMaxDynamicSharedMemorySize, GEMM_SMEM_T3);
    cudaFuncSetAttribute(mma_gemm_p<3,1,false,true ,false,1,0,1,3>, cudaFuncAttributeMaxDynamicSharedMemorySize, GEMM_SMEM_T3);
    cudaFuncSetAttribute(mma_gemm_p<1,0,false,false,false,3,2,1,3>, cudaFuncAttributeMaxDynamicSharedMemorySize, GEMM_SMEM_T3);
    cudaFuncSetAttribute(mma_gemm_p<1,0,false,false,false,1,0,2,3>, cudaFuncAttributeMaxDynamicSharedMemorySize, GEMM_SMEM_T3);
    cudaFuncSetAttribute(mma_gemm_p<3,2,true ,false,false,1,1,1,2>, cudaFuncAttributeMaxDynamicSharedMemorySize, GEMM_SMEM_T2);
    cudaFuncSetAttribute(mma_gemm_p<3,2,false,false,false,1,0,2,3>, cudaFuncAttributeMaxDynamicSharedMemorySize, GEMM_SMEM_T3);

    // ---- pack all weights (fp16 hi + lo) ----
    pack_w<<<dim3(65536 / 256, 1), 256>>>(cw, 0, OFF_COND, 0, S, 1, 8);
    pack_w<<<dim3(393216 / 256, 1), 256>>>(prw, 0, OFF_PRE, 0, C, 3, 48);
    pack_w<<<dim3(131072 / 256, L), 256>>>(qw, (size_t)C * C, OFF_QKV + 0,      QKV_LSTR, C, 1, 16);
    pack_w<<<dim3(131072 / 256, L), 256>>>(kw, (size_t)C * C, OFF_QKV + 131072, QKV_LSTR, C, 1, 16);
    pack_w<<<dim3(131072 / 256, L), 256>>>(vw, (size_t)C * C, OFF_QKV + 262144, QKV_LSTR, C, 1, 16);
    pack_w<<<dim3(131072 / 256, L), 256>>>(ow, (size_t)C * C, OFF_OUT, OUT_LSTR, C, 1, 16);
    pack_w<<<dim3(1572864 / 256, L), 256>>>(f1w, (size_t)FC * C * 3, OFF_F1, F1_LSTR, C,  3, 48);
    pack_w<<<dim3(1572864 / 256, L), 256>>>(f2w, (size_t)C * FC * 3, OFF_F2, F2_LSTR, FC, 3, 192);

    // ---- prep ----
    split_act<<<dim3(T / 256, S / 2, B), 256>>>(spk, ah, al, S / 2);
    mma_gemm_p<1, 0, false, false, true, 1, 0, 1, 3><<<dim3(T / 128, 4, B), 256, GEMM_SMEM_T3>>>(
        ah, al, wh + OFF_COND, wl + OFF_COND, cb, cb, cb, nullptr, x,
        gy, nullptr, nullptr, nullptr, nullptr, nullptr, nullptr, gy, gy, S, C);
    add_f0<<<dim3(T / 256, C, B), 256>>>(f0, f0w, f0b, gy);
    split_act<<<dim3(T / 256, C / 2, B), 256>>>(gy, ah, al, C / 2);
    mma_gemm_p<3, 1, false, true, false, 1, 0, 1, 3><<<dim3(T / 128, 4, B), 256, GEMM_SMEM_T3>>>(
        ah, al, wh + OFF_PRE, wl + OFF_PRE, prb, prb, prb, mask, nullptr,
        gx, nullptr, nullptr, nullptr, nullptr, nullptr, nullptr, gx, gx, C, C);
    split_act<<<dim3(T / 256, C / 2, B), 256>>>(gx, ah, al, C / 2);

    for (int l = 0; l < L; l++) {
        // fused QKV -> packed q/k (channel pairs), v (time pairs)
        mma_gemm_p<1, 0, false, false, false, 3, 2, 1, 3><<<dim3(T / 128, 12, B), 256, GEMM_SMEM_T3>>>(
            ah, al, wh + OFF_QKV + (size_t)l * QKV_LSTR, wl + OFF_QKV + (size_t)l * QKV_LSTR,
            qb + l * C, kb + l * C, vb + l * C, nullptr, nullptr,
            nullptr, qh_, ql_, kh_, kl_, vh_, vl_, nullptr, nullptr, C, C);

        flash_mma<<<dim3(T / 64, B * H), 256, FLASH2_SMEM>>>(
            qh_, ql_, kh_, kl_, vh_, vl_, th_, tl_);

        // out-proj, K split in 2 -> gy (half0 + bias) and gy2 (half1)
        mma_gemm_p<1, 0, false, false, false, 1, 0, 2, 3><<<dim3(T / 128, 8, B), 256, GEMM_SMEM_T3>>>(
            th_, tl_, wh + OFF_OUT + (size_t)l * OUT_LSTR, wl + OFF_OUT + (size_t)l * OUT_LSTR,
            ob + l * C, nullptr, nullptr, nullptr, nullptr,
            gy, nullptr, nullptr, nullptr, nullptr, nullptr, nullptr, gy2, nullptr, C, C);

        add_ln_p<true, false><<<dim3(T / 32, B), dim3(32, 8), LN_SMEM>>>(
            gx, gy, gy2, nullptr, ln0g + l * C, ln0b + l * C, gx, ah, al);

        // FFN1 -> packed B-buf (relu), 2-term fp16 (fast path)
        mma_gemm_p<3, 2, true, false, false, 1, 1, 1, 2><<<dim3(T / 128, FC / 128, B), 256, GEMM_SMEM_T2>>>(
            ah, al, wh + OFF_F1 + (size_t)l * F1_LSTR, wl + OFF_F1 + (size_t)l * F1_LSTR,
            f1b + l * FC, nullptr, nullptr, nullptr, nullptr,
            nullptr, bh2, bl2, nullptr, nullptr, nullptr, nullptr, nullptr, nullptr, C, FC);

        // FFN2, K split in 2 -> gy/gy2 raw partials; mask applied in add_ln
        mma_gemm_p<3, 2, false, false, false, 1, 0, 2, 3><<<dim3(T / 128, 8, B), 256, GEMM_SMEM_T3>>>(
            bh2, bl2, wh + OFF_F2 + (size_t)l * F2_LSTR, wl + OFF_F2 + (size_t)l * F2_LSTR,
            f2b + l * C, nullptr, nullptr, nullptr, nullptr,
            gy, nullptr, nullptr, nullptr, nullptr, nullptr, nullptr, gy2, nullptr, FC, C);

        add_ln_p<true, true><<<dim3(T / 32, B), dim3(32, 8), LN_SMEM>>>(
            gx, gy, gy2, mask, ln1g + l * C, ln1b + l * C, gx, ah, al);
    }

    proj_out<<<dim3(T / 64, B), 256>>>(gx, pw, pb, mask, out);
}